// round 10
// baseline (speedup 1.0000x reference)
#include <cuda_runtime.h>
#include <cuda_fp16.h>
#include <math.h>
#include <stdint.h>

#define SEQ   2048
#define BATCH 2
#define DIM   768
#define NH    12
#define HD    64
#define WIN   512
#define ROWS  (BATCH*SEQ)     // 4096
#define LRATE 0.1f

typedef unsigned long long ull;

// ----------------- device scratch (no cudaMalloc allowed) -----------------
__device__ float g_qkv[ROWS*3*DIM];
__device__ float g_proj[ROWS*DIM];
__device__ float g_proj2[ROWS*DIM];
__device__ float g_xlocal[ROWS*DIM];
__device__ float g_xglobal[ROWS*DIM];
__device__ float g_tq[ROWS*DIM];
__device__ float g_tk[ROWS*DIM];
__device__ float g_tv[ROWS*DIM];
__device__ float g_xc[ROWS*DIM];
__device__ float g_cms[4*(size_t)ROWS*DIM];

// hi/lo f16 planes for GEMM operands
__device__ __half g_x_h[ROWS*DIM],     g_x_l[ROWS*DIM];
__device__ __half g_wi_h[3*DIM*DIM],   g_wi_l[3*DIM*DIM];
__device__ __half g_wo_h[DIM*DIM],     g_wo_l[DIM*DIM];
__device__ __half g_wtq_h[DIM*DIM],    g_wtq_l[DIM*DIM];
__device__ __half g_wtk_h[DIM*DIM],    g_wtk_l[DIM*DIM];
__device__ __half g_wtv_h[DIM*DIM],    g_wtv_l[DIM*DIM];
__device__ __half g_wto_h[DIM*DIM],    g_wto_l[DIM*DIM];
__device__ __half g_wg_h[2*DIM*DIM],   g_wg_l[2*DIM*DIM];
__device__ __half g_wc1_h[4*4*DIM*DIM], g_wc1_l[4*4*DIM*DIM];
__device__ __half g_wc2_h[4*4*DIM*DIM], g_wc2_l[4*4*DIM*DIM];
__device__ __half g_att_h[ROWS*DIM],   g_att_l[ROWS*DIM];
__device__ __half g_to_h[ROWS*DIM],    g_to_l[ROWS*DIM];
__device__ __half g_xl_h[ROWS*DIM],    g_xl_l[ROWS*DIM];
__device__ __half g_xg_h[ROWS*DIM],    g_xg_l[ROWS*DIM];
__device__ __half g_xc_h[ROWS*DIM],    g_xc_l[ROWS*DIM];
__device__ __half g_hb_h[4*(size_t)ROWS*4*DIM], g_hb_l[4*(size_t)ROWS*4*DIM];

// ----------------- f32x2 packed helpers ------------------------------------
__device__ __forceinline__ void ffma2(ull& d, ull a, ull b) {      // d += a*b
    asm("fma.rn.f32x2 %0, %1, %2, %0;" : "+l"(d) : "l"(a), "l"(b));
}
__device__ __forceinline__ void ffma2b(ull& d, ull a, ull b) {     // d = d*a + b
    asm("fma.rn.f32x2 %0, %0, %1, %2;" : "+l"(d) : "l"(a), "l"(b));
}
__device__ __forceinline__ ull pack2f(float x, float y) {
    ull r; asm("mov.b64 %0, {%1, %2};" : "=l"(r) : "f"(x), "f"(y)); return r;
}
__device__ __forceinline__ float2 unpack2f(ull v) {
    float x, y; asm("mov.b64 {%0, %1}, %2;" : "=f"(x), "=f"(y) : "l"(v));
    return make_float2(x, y);
}

// ===================== fp16x3 GEMM with pre-split operands =================
#define TBM 128
#define TBN 128
#define TBK 32
#define STG_BYTES 32768
#define GEMM_SMEM (3*STG_BYTES)          // 98304 -> 2 blocks/SM

#define CP_ASYNC16(dst, src) \
    asm volatile("cp.async.cg.shared.global [%0], [%1], 16;" :: "r"(dst), "l"(src))
#define CP_COMMIT() asm volatile("cp.async.commit_group;")
#define CP_WAIT1()  asm volatile("cp.async.wait_group 1;" ::: "memory")
#define CP_WAIT0()  asm volatile("cp.async.wait_group 0;" ::: "memory")
#define LDSM_X4(r0,r1,r2,r3,addr) \
    asm volatile("ldmatrix.sync.aligned.m8n8.x4.shared.b16 {%0,%1,%2,%3}, [%4];" \
        : "=r"(r0),"=r"(r1),"=r"(r2),"=r"(r3) : "r"(addr))

struct B4 {
    const __half *Ah[4], *Al[4], *Wh[4], *Wl[4];
    const float* bias[4];
    float* C[4];
    __half *Ch[4], *Cl[4];
    const __half *A2h, *A2l, *W2h, *W2l;
    const float *xl, *xg;
    __half *xch, *xcl;
};

__device__ __forceinline__ uint32_t smem_u32(const void* p) {
    uint32_t a;
    asm("{ .reg .u64 t; cvta.to.shared.u64 t, %1; cvt.u32.u64 %0, t; }" : "=r"(a) : "l"(p));
    return a;
}
__device__ __forceinline__ void mma_f16(float* c, uint32_t a0, uint32_t a1,
                                        uint32_t a2, uint32_t a3,
                                        uint32_t b0, uint32_t b1) {
    asm volatile("mma.sync.aligned.m16n8k16.row.col.f32.f16.f16.f32 "
                 "{%0,%1,%2,%3}, {%4,%5,%6,%7}, {%8,%9}, {%0,%1,%2,%3};"
                 : "+f"(c[0]), "+f"(c[1]), "+f"(c[2]), "+f"(c[3])
                 : "r"(a0), "r"(a1), "r"(a2), "r"(a3), "r"(b0), "r"(b1));
}

__global__ __launch_bounds__(256, 2) void gemm_tc(
    B4 b, int lda, int ldw, int N, int K, int epi)
{
    extern __shared__ char smc[];
    const int t   = threadIdx.x;
    const int lid = t & 31;
    const int wid = t >> 5;
    const int wm  = wid & 1;
    const int wn  = wid >> 1;
    const int grp = lid >> 2;
    const int tg  = lid & 3;
    const int bm  = blockIdx.y * TBM;
    const int bn  = blockIdx.x * TBN;
    const int z   = blockIdx.z;

    float acc[4][4][4];
#pragma unroll
    for (int mi = 0; mi < 4; ++mi)
#pragma unroll
        for (int ni = 0; ni < 4; ++ni)
#pragma unroll
            for (int r = 0; r < 4; ++r) acc[mi][ni][r] = 0.f;

    const int nstage = K / TBK;
    const int npass  = b.A2h ? 2 : 1;
    const uint32_t sbase = smem_u32(smc);

    const int lr    = lid & 7;
    const int hsel  = (lid >> 3) & 1;
    const int seg2  = (lid >> 4) & 1;

    for (int pass = 0; pass < npass; ++pass) {
        const __half* pAh = pass ? b.A2h : b.Ah[z];
        const __half* pAl = pass ? b.A2l : b.Al[z];
        const __half* pWh = pass ? b.W2h : b.Wh[z];
        const __half* pWl = pass ? b.W2l : b.Wl[z];
        __syncthreads();

        auto ld_stage = [&](int buf, int k0) {
#pragma unroll
            for (int i = 0; i < 8; ++i) {
                const int tile = i >> 1;               // 0:Ahi 1:Alo 2:Whi 3:Wlo
                const int rem  = ((i & 1) << 8) + t;   // 0..511
                const int row  = rem >> 2;
                const int chn  = t & 3;
                const __half* src;
                if (tile == 0)      src = pAh + (size_t)(bm + row) * lda + k0 + chn * 8;
                else if (tile == 1) src = pAl + (size_t)(bm + row) * lda + k0 + chn * 8;
                else if (tile == 2) src = pWh + (size_t)(bn + row) * ldw + k0 + chn * 8;
                else                src = pWl + (size_t)(bn + row) * ldw + k0 + chn * 8;
                const uint32_t dst = sbase + buf * STG_BYTES + tile * 8192
                                   + row * 64 + ((chn ^ ((row >> 1) & 3)) << 4);
                CP_ASYNC16(dst, src);
            }
        };

        ld_stage(0, 0);   CP_COMMIT();
        ld_stage(1, TBK); CP_COMMIT();

        for (int s = 0; s < nstage; ++s) {
            if (s == nstage - 1) CP_WAIT0(); else CP_WAIT1();
            __syncthreads();
            if (s + 2 < nstage) { ld_stage((s + 2) % 3, (s + 2) * TBK); CP_COMMIT(); }

            const uint32_t stg = sbase + (s % 3) * STG_BYTES;
            const uint32_t a_h = stg, a_l = stg + 8192;
            const uint32_t w_h = stg + 16384, w_l = stg + 24576;

#pragma unroll
            for (int kk = 0; kk < 2; ++kk) {
                // ---- batch-load ALL fragments for this k16 chunk ----
                uint32_t Bh[4][2], Bl[4][2];
#pragma unroll
                for (int np = 0; np < 2; ++np) {
                    const int nr = wn * 32 + np * 16 + seg2 * 8 + lr;
                    const int ch = kk * 2 + hsel;
                    const uint32_t off = nr * 64 + ((ch ^ ((nr >> 1) & 3)) << 4);
                    LDSM_X4(Bh[np*2][0], Bh[np*2][1], Bh[np*2+1][0], Bh[np*2+1][1], w_h + off);
                    LDSM_X4(Bl[np*2][0], Bl[np*2][1], Bl[np*2+1][0], Bl[np*2+1][1], w_l + off);
                }
                uint32_t Ah[4][4], Al[4][4];
#pragma unroll
                for (int mi = 0; mi < 4; ++mi) {
                    const int ar = wm * 64 + mi * 16 + hsel * 8 + lr;
                    const int ch = kk * 2 + seg2;
                    const uint32_t off = ar * 64 + ((ch ^ ((ar >> 1) & 3)) << 4);
                    LDSM_X4(Ah[mi][0], Ah[mi][1], Ah[mi][2], Ah[mi][3], a_h + off);
                    LDSM_X4(Al[mi][0], Al[mi][1], Al[mi][2], Al[mi][3], a_l + off);
                }
                // ---- 48 MMAs grouped by pass: acc reuse distance = 16 ----
#pragma unroll
                for (int mi = 0; mi < 4; ++mi)
#pragma unroll
                    for (int ni = 0; ni < 4; ++ni)
                        mma_f16(acc[mi][ni], Ah[mi][0], Ah[mi][1], Ah[mi][2], Ah[mi][3],
                                Bh[ni][0], Bh[ni][1]);
#pragma unroll
                for (int mi = 0; mi < 4; ++mi)
#pragma unroll
                    for (int ni = 0; ni < 4; ++ni)
                        mma_f16(acc[mi][ni], Al[mi][0], Al[mi][1], Al[mi][2], Al[mi][3],
                                Bh[ni][0], Bh[ni][1]);
#pragma unroll
                for (int mi = 0; mi < 4; ++mi)
#pragma unroll
                    for (int ni = 0; ni < 4; ++ni)
                        mma_f16(acc[mi][ni], Ah[mi][0], Ah[mi][1], Ah[mi][2], Ah[mi][3],
                                Bl[ni][0], Bl[ni][1]);
            }
        }
    }

    // ---------------- epilogue ----------------
#pragma unroll
    for (int mi = 0; mi < 4; ++mi) {
#pragma unroll
        for (int ni = 0; ni < 4; ++ni) {
            const int col = bn + wn * 32 + ni * 8 + 2 * tg;
            float bx = 0.f, by = 0.f;
            if (b.bias[z]) { bx = b.bias[z][col]; by = b.bias[z][col + 1]; }
#pragma unroll
            for (int hf = 0; hf < 2; ++hf) {
                const int row = bm + wm * 64 + mi * 16 + grp + hf * 8;
                float v0 = acc[mi][ni][hf * 2 + 0] + bx;
                float v1 = acc[mi][ni][hf * 2 + 1] + by;
                const size_t idx = (size_t)row * N + col;
                if (epi == 0) {
                    *(float2*)(b.C[z] + idx) = make_float2(v0, v1);
                } else if (epi == 1) {
                    float u3;
                    u3 = v0 * v0 * v0;
                    v0 = 0.5f * v0 * (1.f + tanhf(0.7978845608028654f * (v0 + 0.044715f * u3)));
                    u3 = v1 * v1 * v1;
                    v1 = 0.5f * v1 * (1.f + tanhf(0.7978845608028654f * (v1 + 0.044715f * u3)));
                    __half2 hh = __floats2half2_rn(v0, v1);
                    float2 hv = __half22float2(hh);
                    __half2 ll = __floats2half2_rn(v0 - hv.x, v1 - hv.y);
                    *(__half2*)(b.Ch[z] + idx) = hh;
                    *(__half2*)(b.Cl[z] + idx) = ll;
                } else { // epi == 3
                    float s0 = 1.f / (1.f + __expf(-v0));
                    float s1 = 1.f / (1.f + __expf(-v1));
                    float2 xl2 = *(const float2*)(b.xl + idx);
                    float2 xg2 = *(const float2*)(b.xg + idx);
                    v0 = s0 * xl2.x + (1.f - s0) * xg2.x;
                    v1 = s1 * xl2.y + (1.f - s1) * xg2.y;
                    *(float2*)(b.C[z] + idx) = make_float2(v0, v1);
                    __half2 hh = __floats2half2_rn(v0, v1);
                    float2 hv = __half22float2(hh);
                    __half2 ll = __floats2half2_rn(v0 - hv.x, v1 - hv.y);
                    *(__half2*)(b.xch + idx) = hh;
                    *(__half2*)(b.xcl + idx) = ll;
                }
            }
        }
    }
}

// ----------------- fused splitter: f32 -> f16 hi/lo, all tensors ----------
struct SplitSeg { const float4* src; uint2* hi; uint2* lo; unsigned n4; };
struct SplitTab { SplitSeg seg[10]; };

__global__ void split_all_kernel(SplitTab tab)
{
    unsigned idx = blockIdx.x * blockDim.x + threadIdx.x;
#pragma unroll
    for (int s = 0; s < 10; ++s) {
        if (idx < tab.seg[s].n4) {
            float4 v = tab.seg[s].src[idx];
            __half2 h0 = __floats2half2_rn(v.x, v.y);
            __half2 h1 = __floats2half2_rn(v.z, v.w);
            float2 f0 = __half22float2(h0), f1 = __half22float2(h1);
            __half2 l0 = __floats2half2_rn(v.x - f0.x, v.y - f0.y);
            __half2 l1 = __floats2half2_rn(v.z - f1.x, v.w - f1.y);
            tab.seg[s].hi[idx] = make_uint2(*(uint32_t*)&h0, *(uint32_t*)&h1);
            tab.seg[s].lo[idx] = make_uint2(*(uint32_t*)&l0, *(uint32_t*)&l1);
            return;
        }
        idx -= tab.seg[s].n4;
    }
}

// ----------------- sliding-window causal attention (f32x2) ----------------
__global__ __launch_bounds__(64) void attn_kernel(const float* __restrict__ qkv,
                                                  __half* __restrict__ oh,
                                                  __half* __restrict__ ol)
{
    const int qt = blockIdx.x;
    const int b  = blockIdx.y;
    const int h  = blockIdx.z;
    const int t  = threadIdx.x;
    const int qi = qt * 64 + t;

    __shared__ __align__(16) float ks[64][64];
    __shared__ __align__(16) float vs[64][64];

    ull q2[32], o2[32];
    {
        const float4* qb = (const float4*)(qkv + ((size_t)(b * SEQ + qi)) * (3 * DIM) + h * HD);
#pragma unroll
        for (int d4 = 0; d4 < 16; ++d4) {
            float4 v = qb[d4];
            q2[2*d4]   = pack2f(v.x * 0.125f, v.y * 0.125f);
            q2[2*d4+1] = pack2f(v.z * 0.125f, v.w * 0.125f);
        }
    }
#pragma unroll
    for (int i = 0; i < 32; ++i) o2[i] = 0ull;
    float m = -1e30f, l = 0.f;

    const int kt0 = (qt >= 8) ? (qt - 8) : 0;
    for (int kt = kt0; kt <= qt; ++kt) {
        const float* kbase = qkv + ((size_t)(b * SEQ + kt * 64)) * (3 * DIM) + DIM + h * HD + t;
        const float* vbase = kbase + DIM;
        for (int r = 0; r < 64; ++r) {
            ks[r][t] = kbase[(size_t)r * (3 * DIM)];
            vs[r][t] = vbase[(size_t)r * (3 * DIM)];
        }
        __syncthreads();

        int jlo = qi - WIN + 1 - kt * 64; if (jlo < 0)  jlo = 0;
        int jhi = qi - kt * 64;           if (jhi > 63) jhi = 63;
        for (int j = jlo; j <= jhi; ++j) {
            const ull* kr2 = (const ull*)ks[j];
            ull a0 = 0ull, a1 = 0ull, a2 = 0ull, a3 = 0ull;
#pragma unroll
            for (int i = 0; i < 32; i += 4) {
                ffma2(a0, q2[i],   kr2[i]);
                ffma2(a1, q2[i+1], kr2[i+1]);
                ffma2(a2, q2[i+2], kr2[i+2]);
                ffma2(a3, q2[i+3], kr2[i+3]);
            }
            float2 f0 = unpack2f(a0), f1 = unpack2f(a1);
            float2 f2 = unpack2f(a2), f3 = unpack2f(a3);
            float s = ((f0.x + f0.y) + (f1.x + f1.y)) + ((f2.x + f2.y) + (f3.x + f3.y));
            const ull* vr2 = (const ull*)vs[j];
            if (s <= m) {
                float p = __expf(s - m);
                l += p;
                ull p2 = pack2f(p, p);
#pragma unroll
                for (int i = 0; i < 32; ++i) ffma2(o2[i], p2, vr2[i]);
            } else {
                float al = __expf(m - s);
                m = s; l = l * al + 1.f;
                ull al2 = pack2f(al, al);
#pragma unroll
                for (int i = 0; i < 32; ++i) ffma2b(o2[i], al2, vr2[i]);
            }
        }
        __syncthreads();
    }

    const float inv = 1.f / l;
    const size_t ob = ((size_t)(b * SEQ + qi)) * DIM + h * HD;
#pragma unroll
    for (int i = 0; i < 32; i += 2) {
        float2 p0 = unpack2f(o2[i]), p1 = unpack2f(o2[i+1]);
        float v0 = p0.x * inv, v1 = p0.y * inv, v2 = p1.x * inv, v3 = p1.y * inv;
        __half2 h0 = __floats2half2_rn(v0, v1);
        __half2 h1 = __floats2half2_rn(v2, v3);
        float2 f0 = __half22float2(h0), f1 = __half22float2(h1);
        __half2 l0 = __floats2half2_rn(v0 - f0.x, v1 - f0.y);
        __half2 l1 = __floats2half2_rn(v2 - f1.x, v3 - f1.y);
        *(uint2*)(oh + ob + 2*i) = make_uint2(*(uint32_t*)&h0, *(uint32_t*)&h1);
        *(uint2*)(ol + ob + 2*i) = make_uint2(*(uint32_t*)&l0, *(uint32_t*)&l1);
    }
}

// ----------------- fused residual-add + LayerNorm (+split out) ------------
__global__ __launch_bounds__(256) void add_ln_kernel(const float* __restrict__ x,
    const float* __restrict__ r, const float* __restrict__ gg,
    const float* __restrict__ bb, float* __restrict__ y,
    __half* __restrict__ yh, __half* __restrict__ yl)
{
    const int row = blockIdx.x;
    const int t = threadIdx.x;
    __shared__ float red[8];
    __shared__ float bc0, bc1;

    const float* xr = x + (size_t)row * DIM;
    const float* rr = r + (size_t)row * DIM;
    float v[3]; float s = 0.f;
#pragma unroll
    for (int i = 0; i < 3; ++i) { int c = t + i * 256; v[i] = xr[c] + rr[c]; s += v[i]; }
#pragma unroll
    for (int off = 16; off; off >>= 1) s += __shfl_xor_sync(0xffffffffu, s, off);
    if ((t & 31) == 0) red[t >> 5] = s;
    __syncthreads();
    if (t == 0) { float tot = 0.f;
#pragma unroll
        for (int w = 0; w < 8; ++w) tot += red[w];
        bc0 = tot * (1.f / DIM);
    }
    __syncthreads();
    const float mean = bc0;
    float sq = 0.f;
#pragma unroll
    for (int i = 0; i < 3; ++i) { float d = v[i] - mean; sq += d * d; }
#pragma unroll
    for (int off = 16; off; off >>= 1) sq += __shfl_xor_sync(0xffffffffu, sq, off);
    if ((t & 31) == 0) red[t >> 5] = sq;
    __syncthreads();
    if (t == 0) { float tot = 0.f;
#pragma unroll
        for (int w = 0; w < 8; ++w) tot += red[w];
        bc1 = rsqrtf(tot * (1.f / DIM) + 1e-5f);
    }
    __syncthreads();
    const float rstd = bc1;
#pragma unroll
    for (int i = 0; i < 3; ++i) {
        int c = t + i * 256;
        float val = (v[i] - mean) * rstd * gg[c] + bb[c];
        y[(size_t)row * DIM + c] = val;
        __half hh = __float2half_rn(val);
        __half ll = __float2half_rn(val - __half2float(hh));
        yh[(size_t)row * DIM + c] = hh;
        yl[(size_t)row * DIM + c] = ll;
    }
}

// ----------------- final LN with 4-way CMS mean ----------------------------
__global__ __launch_bounds__(256) void ln_final_kernel(const float* __restrict__ xc,
    const float* __restrict__ c0, const float* __restrict__ c1,
    const float* __restrict__ c2, const float* __restrict__ c3,
    const float* __restrict__ gg, const float* __restrict__ bb,
    float* __restrict__ y)
{
    const int row = blockIdx.x;
    const int t = threadIdx.x;
    __shared__ float red[8];
    __shared__ float bc0, bc1;

    const size_t rb = (size_t)row * DIM;
    float v[3]; float s = 0.f;
#pragma unroll
    for (int i = 0; i < 3; ++i) {
        int c = t + i * 256;
        v[i] = xc[rb + c] + 0.25f * (c0[rb + c] + c1[rb + c] + c2[rb + c] + c3[rb + c]);
        s += v[i];
    }
#pragma unroll
    for (int off = 16; off; off >>= 1) s += __shfl_xor_sync(0xffffffffu, s, off);
    if ((t & 31) == 0) red[t >> 5] = s;
    __syncthreads();
    if (t == 0) { float tot = 0.f;
#pragma unroll
        for (int w = 0; w < 8; ++w) tot += red[w];
        bc0 = tot * (1.f / DIM);
    }
    __syncthreads();
    const float mean = bc0;
    float sq = 0.f;
#pragma unroll
    for (int i = 0; i < 3; ++i) { float d = v[i] - mean; sq += d * d; }
#pragma unroll
    for (int off = 16; off; off >>= 1) sq += __shfl_xor_sync(0xffffffffu, sq, off);
    if ((t & 31) == 0) red[t >> 5] = sq;
    __syncthreads();
    if (t == 0) { float tot = 0.f;
#pragma unroll
        for (int w = 0; w < 8; ++w) tot += red[w];
        bc1 = rsqrtf(tot * (1.f / DIM) + 1e-5f);
    }
    __syncthreads();
    const float rstd = bc1;
#pragma unroll
    for (int i = 0; i < 3; ++i) {
        int c = t + i * 256;
        y[rb + c] = (v[i] - mean) * rstd * gg[c] + bb[c];
    }
}

// ----------------- delta-rule scan: f32x2 + 2 barriers/step ---------------
__global__ __launch_bounds__(256) void delta_scan_kernel(const float* __restrict__ tq,
    const float* __restrict__ tk, const float* __restrict__ tv,
    __half* __restrict__ toh, __half* __restrict__ tol, float* __restrict__ Mout)
{
    const int bh = blockIdx.x;
    const int b = bh / NH, h = bh % NH;
    const int t = threadIdx.x;
    const int e = t & 63;
    const int g = t >> 6;

    __shared__ __align__(8) float ks[2][64], vs[2][64], qs[2][64];
    __shared__ float part[2][4][64];
    __shared__ float opart[2][4][64];

    ull M2[8];
#pragma unroll
    for (int i = 0; i < 8; ++i) M2[i] = 0ull;

    const size_t base = ((size_t)b * SEQ) * DIM + h * HD + e;
    float nxt = 0.f;
    if (g == 0) nxt = tk[base];
    else if (g == 1) nxt = tv[base];
    else if (g == 2) nxt = tq[base];

    for (int s = 0; s < SEQ; ++s) {
        const int p = s & 1;
        if (g == 0) ks[p][e] = nxt;
        else if (g == 1) vs[p][e] = nxt;
        else if (g == 2) qs[p][e] = nxt;
        __syncthreads();   // B1
        if (s + 1 < SEQ) {
            size_t nb = base + (size_t)(s + 1) * DIM;
            if (g == 0) nxt = tk[nb];
            else if (g == 1) nxt = tv[nb];
            else if (g == 2) nxt = tq[nb];
        }
        if (g == 0 && s > 0) {
            const int pp = p ^ 1;
            float ov = (opart[pp][0][e] + opart[pp][1][e])
                     + (opart[pp][2][e] + opart[pp][3][e]);
            __half hh = __float2half_rn(ov);
            __half ll = __float2half_rn(ov - __half2float(hh));
            toh[base + (size_t)(s - 1) * DIM] = hh;
            tol[base + (size_t)(s - 1) * DIM] = ll;
        }
        ull k2[8];
        ull pa = 0ull, pb = 0ull;
        const ull* kp = (const ull*)&ks[p][g * 16];
#pragma unroll
        for (int i = 0; i < 8; i += 2) {
            k2[i] = kp[i]; k2[i+1] = kp[i+1];
            ffma2(pa, M2[i], k2[i]);
            ffma2(pb, M2[i+1], k2[i+1]);
        }
        float2 pf = unpack2f(pa), pg = unpack2f(pb);
        part[p][g][e] = (pf.x + pf.y) + (pg.x + pg.y);
        __syncthreads();   // B2
        const float pred  = (part[p][0][e] + part[p][1][e]) + (part[p][2][e] + part[p][3][e]);
        const float delta = LRATE * (vs[p][e] - pred);
        const ull d2 = pack2f(delta, delta);
        const ull* qp = (const ull*)&qs[p][g * 16];
        ull oa = 0ull, obb = 0ull;
#pragma unroll
        for (int i = 0; i < 8; i += 2) {
            ffma2(M2[i], k2[i], d2);     ffma2(oa, M2[i], qp[i]);
            ffma2(M2[i+1], k2[i+1], d2); ffma2(obb, M2[i+1], qp[i+1]);
        }
        float2 of = unpack2f(oa), og = unpack2f(obb);
        opart[p][g][e] = (of.x + of.y) + (og.x + og.y);
    }
    __syncthreads();
    if (g == 0) {
        const int pp = (SEQ - 1) & 1;
        float ov = (opart[pp][0][e] + opart[pp][1][e]) + (opart[pp][2][e] + opart[pp][3][e]);
        __half hh = __float2half_rn(ov);
        __half ll = __float2half_rn(ov - __half2float(hh));
        toh[base + (size_t)(SEQ - 1) * DIM] = hh;
        tol[base + (size_t)(SEQ - 1) * DIM] = ll;
    }
    if (Mout) {
#pragma unroll
        for (int i = 0; i < 8; ++i) {
            float2 mv = unpack2f(M2[i]);
            Mout[(((size_t)b * NH + h) * HD + (g * 16 + 2*i))     * HD + e] = mv.x;
            Mout[(((size_t)b * NH + h) * HD + (g * 16 + 2*i + 1)) * HD + e] = mv.y;
        }
    }
}

// ----------------- launch ---------------------------------------------------
static void* symp(const void* s) {
    void* p = nullptr;
    cudaGetSymbolAddress(&p, s);
    return p;
}

extern "C" void kernel_launch(void* const* d_in, const int* in_sizes, int n_in,
                              void* d_out, int out_size)
{
    const float* x          = (const float*)d_in[0];
    const float* in_proj_w  = (const float*)d_in[1];
    const float* in_proj_b  = (const float*)d_in[2];
    const float* out_proj_w = (const float*)d_in[3];
    const float* out_proj_b = (const float*)d_in[4];
    const float* ln_local_g = (const float*)d_in[5];
    const float* ln_local_b = (const float*)d_in[6];
    const float* t_wq       = (const float*)d_in[7];
    const float* t_wk       = (const float*)d_in[8];
    const float* t_wv       = (const float*)d_in[9];
    const float* t_wo       = (const float*)d_in[10];
    const float* ln_tit_g   = (const float*)d_in[11];
    const float* ln_tit_b   = (const float*)d_in[12];
    const float* gate_w     = (const float*)d_in[13];
    const float* gate_b     = (const float*)d_in[14];
    const float* cms_w1     = (const float*)d_in[15];
    const float* cms_b1     = (const float*)d_in[16];
    const float* cms_w2     = (const float*)d_in[17];
    const float* cms_b2     = (const float*)d_in[18];
    const float* ln_cms_g   = (const float*)d_in[19];
    const float* ln_cms_b   = (const float*)d_in[20];

    float* qkv    = (float*)symp(g_qkv);
    float* proj   = (float*)symp(g_proj);
    float* proj2  = (float*)symp(g_proj2);
    float* xlocal = (float*)symp(g_xlocal);
    float* xglob  = (float*)symp(g_xglobal);
    float* tq     = (float*)symp(g_tq);
    float* tk     = (float*)symp(g_tk);
    float* tv     = (float*)symp(g_tv);
    float* xc     = (float*)symp(g_xc);
    float* cmsb   = (float*)symp(g_cms);

    __half* x_h   = (__half*)symp(g_x_h);   __half* x_l   = (__half*)symp(g_x_l);
    __half* wi_h  = (__half*)symp(g_wi_h);  __half* wi_l  = (__half*)symp(g_wi_l);
    __half* wo_h  = (__half*)symp(g_wo_h);  __half* wo_l  = (__half*)symp(g_wo_l);
    __half* wtq_h = (__half*)symp(g_wtq_h); __half* wtq_l = (__half*)symp(g_wtq_l);
    __half* wtk_h = (__half*)symp(g_wtk_h); __half* wtk_l = (__half*)symp(g_wtk_l);
    __half* wtv_h = (__half*)symp(g_wtv_h); __half* wtv_l = (__half*)symp(g_wtv_l);
    __half* wto_h = (__half*)symp(g_wto_h); __half* wto_l = (__half*)symp(g_wto_l);
    __half* wg_h  = (__half*)symp(g_wg_h);  __half* wg_l  = (__half*)symp(g_wg_l);
    __half* wc1_h = (__half*)symp(g_wc1_h); __half* wc1_l = (__half*)symp(g_wc1_l);
    __half* wc2_h = (__half*)symp(g_wc2_h); __half* wc2_l = (__half*)symp(g_wc2_l);
    __half* att_h = (__half*)symp(g_att_h); __half* att_l = (__half*)symp(g_att_l);
    __half* to_h  = (__half*)symp(g_to_h);  __half* to_l  = (__half*)symp(g_to_l);
    __half* xl_h  = (__half*)symp(g_xl_h);  __half* xl_l  = (__half*)symp(g_xl_l);
    __half* xg_h  = (__half*)symp(g_xg_h);  __half* xg_l  = (__half*)symp(g_xg_l);
    __half* xc_h  = (__half*)symp(g_xc_h);  __half* xc_l  = (__half*)symp(g_xc_l);
    __half* hb_h  = (__half*)symp(g_hb_h);  __half* hb_l  = (__half*)symp(g_hb_l);

    float* out = (float*)d_out;
    float* mout = (out_size >= ROWS * DIM + BATCH * NH * HD * HD)
                      ? out + (size_t)ROWS * DIM : nullptr;

    static cudaStream_t s2 = nullptr;
    static cudaEvent_t ev_fork = nullptr, ev_join = nullptr;
    if (!s2) {
        cudaFuncSetAttribute(gemm_tc, cudaFuncAttributeMaxDynamicSharedMemorySize, GEMM_SMEM);
        cudaStreamCreateWithFlags(&s2, cudaStreamNonBlocking);
        cudaEventCreateWithFlags(&ev_fork, cudaEventDisableTiming);
        cudaEventCreateWithFlags(&ev_join, cudaEventDisableTiming);
    }

    // [0] single fused split of all f32 operands -> f16 hi/lo planes
    {
        SplitTab tab{};
        unsigned tot4 = 0;
        auto add = [&](int i, const float* s, __half* h, __half* l, size_t n) {
            tab.seg[i] = SplitSeg{ (const float4*)s, (uint2*)h, (uint2*)l, (unsigned)(n / 4) };
            tot4 += (unsigned)(n / 4);
        };
        add(0, x, x_h, x_l, (size_t)ROWS * DIM);
        add(1, t_wq, wtq_h, wtq_l, (size_t)DIM * DIM);
        add(2, t_wk, wtk_h, wtk_l, (size_t)DIM * DIM);
        add(3, t_wv, wtv_h, wtv_l, (size_t)DIM * DIM);
        add(4, t_wo, wto_h, wto_l, (size_t)DIM * DIM);
        add(5, in_proj_w, wi_h, wi_l, (size_t)3 * DIM * DIM);
        add(6, out_proj_w, wo_h, wo_l, (size_t)DIM * DIM);
        add(7, gate_w, wg_h, wg_l, (size_t)2 * DIM * DIM);
        add(8, cms_w1, wc1_h, wc1_l, (size_t)16 * DIM * DIM);
        add(9, cms_w2, wc2_h, wc2_l, (size_t)16 * DIM * DIM);
        split_all_kernel<<<(tot4 + 255) / 256, 256>>>(tab);
    }

    cudaEventRecord(ev_fork, 0);
    cudaStreamWaitEvent(s2, ev_fork, 0);

    B4 b{};

    // [s2] Titans projections (z-batched x3)
    b = B4{};
    b.Ah[0] = x_h; b.Al[0] = x_l; b.Wh[0] = wtq_h; b.Wl[0] = wtq_l; b.C[0] = tq;
    b.Ah[1] = x_h; b.Al[1] = x_l; b.Wh[1] = wtk_h; b.Wl[1] = wtk_l; b.C[1] = tk;
    b.Ah[2] = x_h; b.Al[2] = x_l; b.Wh[2] = wtv_h; b.Wl[2] = wtv_l; b.C[2] = tv;
    gemm_tc<<<dim3(DIM / TBN, ROWS / TBM, 3), 256, GEMM_SMEM, s2>>>(b, DIM, DIM, DIM, DIM, 0);

    // [s2] delta-rule scan
    delta_scan_kernel<<<BATCH * NH, 256, 0, s2>>>(tq, tk, tv, to_h, to_l, mout);

    // [s2] titans out proj + residual LN -> x_global (+split)
    b = B4{};
    b.Ah[0] = to_h; b.Al[0] = to_l; b.Wh[0] = wto_h; b.Wl[0] = wto_l; b.C[0] = proj2;
    gemm_tc<<<dim3(DIM / TBN, ROWS / TBM, 1), 256, GEMM_SMEM, s2>>>(b, DIM, DIM, DIM, DIM, 0);
    add_ln_kernel<<<ROWS, 256, 0, s2>>>(x, proj2, ln_tit_g, ln_tit_b, xglob, xg_h, xg_l);
    cudaEventRecord(ev_join, s2);

    // [0] packed QKV projection
    b = B4{};
    b.Ah[0] = x_h; b.Al[0] = x_l; b.Wh[0] = wi_h; b.Wl[0] = wi_l;
    b.bias[0] = in_proj_b; b.C[0] = qkv;
    gemm_tc<<<dim3(3 * DIM / TBN, ROWS / TBM, 1), 256, GEMM_SMEM>>>(b, DIM, DIM, 3 * DIM, DIM, 0);

    // [0] sliding-window attention -> split att
    attn_kernel<<<dim3(SEQ / 64, BATCH, NH), 64>>>(qkv, att_h, att_l);

    // [0] out_proj + residual LN -> x_local (+split)
    b = B4{};
    b.Ah[0] = att_h; b.Al[0] = att_l; b.Wh[0] = wo_h; b.Wl[0] = wo_l;
    b.bias[0] = out_proj_b; b.C[0] = proj;
    gemm_tc<<<dim3(DIM / TBN, ROWS / TBM, 1), 256, GEMM_SMEM>>>(b, DIM, DIM, DIM, DIM, 0);
    add_ln_kernel<<<ROWS, 256>>>(x, proj, ln_local_g, ln_local_b, xlocal, xl_h, xl_l);

    // ---- join ----
    cudaStreamWaitEvent(0, ev_join, 0);

    // [0] gate: two K-passes with fused sigmoid-combine
    b = B4{};
    b.Ah[0] = xl_h; b.Al[0] = xl_l; b.Wh[0] = wg_h; b.Wl[0] = wg_l;
    b.bias[0] = gate_b; b.C[0] = xc;
    b.A2h = xg_h; b.A2l = xg_l; b.W2h = wg_h + DIM; b.W2l = wg_l + DIM;
    b.xl = xlocal; b.xg = xglob; b.xch = xc_h; b.xcl = xc_l;
    gemm_tc<<<dim3(DIM / TBN, ROWS / TBM, 1), 256, GEMM_SMEM>>>(b, DIM, 2 * DIM, DIM, DIM, 3);

    // [0] CMS: w1 x4 (gelu, split-only output), z-batched
    b = B4{};
    for (int l = 0; l < 4; ++l) {
        b.Ah[l] = xc_h; b.Al[l] = xc_l;
        b.Wh[l] = wc1_h + (size_t)l * 4 * DIM * DIM;
        b.Wl[l] = wc1_l + (size_t)l * 4 * DIM * DIM;
        b.bias[l] = cms_b1 + (size_t)l * 4 * DIM;
        b.Ch[l] = hb_h + (size_t)l * ROWS * 4 * DIM;
        b.Cl[l] = hb_l + (size_t)l * ROWS * 4 * DIM;
    }
    gemm_tc<<<dim3(4 * DIM / TBN, ROWS / TBM, 4), 256, GEMM_SMEM>>>(b, DIM, DIM, 4 * DIM, DIM, 1);

    // [0] CMS: w2 x4, z-batched, per-level f32 outputs
    b = B4{};
    for (int l = 0; l < 4; ++l) {
        b.Ah[l] = hb_h + (size_t)l * ROWS * 4 * DIM;
        b.Al[l] = hb_l + (size_t)l * ROWS * 4 * DIM;
        b.Wh[l] = wc2_h + (size_t)l * 4 * DIM * DIM;
        b.Wl[l] = wc2_l + (size_t)l * 4 * DIM * DIM;
        b.bias[l] = cms_b2 + (size_t)l * DIM;
        b.C[l] = cmsb + (size_t)l * ROWS * DIM;
    }
    gemm_tc<<<dim3(DIM / TBN, ROWS / TBM, 4), 256, GEMM_SMEM>>>(b, 4 * DIM, 4 * DIM, DIM, 4 * DIM, 0);

    // [0] final LN
    ln_final_kernel<<<ROWS, 256>>>(xc, cmsb, cmsb + (size_t)ROWS * DIM,
                                   cmsb + 2 * (size_t)ROWS * DIM, cmsb + 3 * (size_t)ROWS * DIM,
                                   ln_cms_g, ln_cms_b, out);
}

// round 11
// speedup vs baseline: 1.1046x; 1.1046x over previous
#include <cuda_runtime.h>
#include <cuda_fp16.h>
#include <math.h>
#include <stdint.h>

#define SEQ   2048
#define BATCH 2
#define DIM   768
#define NH    12
#define HD    64
#define WIN   512
#define ROWS  (BATCH*SEQ)     // 4096
#define LRATE 0.1f

typedef unsigned long long ull;

// ----------------- device scratch (no cudaMalloc allowed) -----------------
__device__ float g_qkv[ROWS*3*DIM];
__device__ float g_proj[ROWS*DIM];
__device__ float g_proj2[ROWS*DIM];
__device__ float g_xlocal[ROWS*DIM];
__device__ float g_xglobal[ROWS*DIM];
__device__ float g_tq[ROWS*DIM];
__device__ float g_tk[ROWS*DIM];
__device__ float g_tv[ROWS*DIM];
__device__ float g_xc[ROWS*DIM];
__device__ float g_cms[4*(size_t)ROWS*DIM];

// hi/lo f16 planes for GEMM operands
__device__ __half g_x_h[ROWS*DIM],     g_x_l[ROWS*DIM];
__device__ __half g_wi_h[3*DIM*DIM],   g_wi_l[3*DIM*DIM];
__device__ __half g_wo_h[DIM*DIM],     g_wo_l[DIM*DIM];
__device__ __half g_wtq_h[DIM*DIM],    g_wtq_l[DIM*DIM];
__device__ __half g_wtk_h[DIM*DIM],    g_wtk_l[DIM*DIM];
__device__ __half g_wtv_h[DIM*DIM],    g_wtv_l[DIM*DIM];
__device__ __half g_wto_h[DIM*DIM],    g_wto_l[DIM*DIM];
__device__ __half g_wg_h[2*DIM*DIM],   g_wg_l[2*DIM*DIM];
__device__ __half g_wc1_h[4*4*DIM*DIM], g_wc1_l[4*4*DIM*DIM];
__device__ __half g_wc2_h[4*4*DIM*DIM], g_wc2_l[4*4*DIM*DIM];
__device__ __half g_att_h[ROWS*DIM],   g_att_l[ROWS*DIM];
__device__ __half g_to_h[ROWS*DIM],    g_to_l[ROWS*DIM];
__device__ __half g_xl_h[ROWS*DIM],    g_xl_l[ROWS*DIM];
__device__ __half g_xg_h[ROWS*DIM],    g_xg_l[ROWS*DIM];
__device__ __half g_xc_h[ROWS*DIM],    g_xc_l[ROWS*DIM];
__device__ __half g_hb_h[4*(size_t)ROWS*4*DIM], g_hb_l[4*(size_t)ROWS*4*DIM];

// ----------------- f32x2 packed helpers ------------------------------------
__device__ __forceinline__ void ffma2(ull& d, ull a, ull b) {      // d += a*b
    asm("fma.rn.f32x2 %0, %1, %2, %0;" : "+l"(d) : "l"(a), "l"(b));
}
__device__ __forceinline__ void ffma2b(ull& d, ull a, ull b) {     // d = d*a + b
    asm("fma.rn.f32x2 %0, %0, %1, %2;" : "+l"(d) : "l"(a), "l"(b));
}
__device__ __forceinline__ ull pack2f(float x, float y) {
    ull r; asm("mov.b64 %0, {%1, %2};" : "=l"(r) : "f"(x), "f"(y)); return r;
}
__device__ __forceinline__ float2 unpack2f(ull v) {
    float x, y; asm("mov.b64 {%0, %1}, %2;" : "=f"(x), "=f"(y) : "l"(v));
    return make_float2(x, y);
}

// ===================== fp16 multi-pass GEMM with pre-split operands ========
// passes==3: hh + lh + hl (full fp32 emulation, ~2^-23)
// passes==2: hh + lh       (drops a_hi*b_lo, ~2^-12 noise; post-scan ops only)
#define TBM 128
#define TBN 128
#define TBK 32
#define STG_BYTES 32768
#define GEMM_SMEM (3*STG_BYTES)          // 98304 -> 2 blocks/SM

#define CP_ASYNC16(dst, src) \
    asm volatile("cp.async.cg.shared.global [%0], [%1], 16;" :: "r"(dst), "l"(src))
#define CP_COMMIT() asm volatile("cp.async.commit_group;")
#define CP_WAIT1()  asm volatile("cp.async.wait_group 1;" ::: "memory")
#define CP_WAIT0()  asm volatile("cp.async.wait_group 0;" ::: "memory")
#define LDSM_X4(r0,r1,r2,r3,addr) \
    asm volatile("ldmatrix.sync.aligned.m8n8.x4.shared.b16 {%0,%1,%2,%3}, [%4];" \
        : "=r"(r0),"=r"(r1),"=r"(r2),"=r"(r3) : "r"(addr))

struct B4 {
    const __half *Ah[4], *Al[4], *Wh[4], *Wl[4];
    const float* bias[4];
    float* C[4];
    __half *Ch[4], *Cl[4];
    const __half *A2h, *A2l, *W2h, *W2l;
    const float *xl, *xg;
    __half *xch, *xcl;
};

__device__ __forceinline__ uint32_t smem_u32(const void* p) {
    uint32_t a;
    asm("{ .reg .u64 t; cvta.to.shared.u64 t, %1; cvt.u32.u64 %0, t; }" : "=r"(a) : "l"(p));
    return a;
}
__device__ __forceinline__ void mma_f16(float* c, uint32_t a0, uint32_t a1,
                                        uint32_t a2, uint32_t a3,
                                        uint32_t b0, uint32_t b1) {
    asm volatile("mma.sync.aligned.m16n8k16.row.col.f32.f16.f16.f32 "
                 "{%0,%1,%2,%3}, {%4,%5,%6,%7}, {%8,%9}, {%0,%1,%2,%3};"
                 : "+f"(c[0]), "+f"(c[1]), "+f"(c[2]), "+f"(c[3])
                 : "r"(a0), "r"(a1), "r"(a2), "r"(a3), "r"(b0), "r"(b1));
}

__global__ __launch_bounds__(256, 2) void gemm_tc(
    B4 b, int lda, int ldw, int N, int K, int epi, int passes3)
{
    extern __shared__ char smc[];
    const int t   = threadIdx.x;
    const int lid = t & 31;
    const int wid = t >> 5;
    const int wm  = wid & 1;
    const int wn  = wid >> 1;
    const int grp = lid >> 2;
    const int tg  = lid & 3;
    const int bm  = blockIdx.y * TBM;
    const int bn  = blockIdx.x * TBN;
    const int z   = blockIdx.z;

    float acc[4][4][4];
#pragma unroll
    for (int mi = 0; mi < 4; ++mi)
#pragma unroll
        for (int ni = 0; ni < 4; ++ni)
#pragma unroll
            for (int r = 0; r < 4; ++r) acc[mi][ni][r] = 0.f;

    const int nstage = K / TBK;
    const int npass  = b.A2h ? 2 : 1;
    const uint32_t sbase = smem_u32(smc);

    const int lr    = lid & 7;
    const int hsel  = (lid >> 3) & 1;
    const int seg2  = (lid >> 4) & 1;

    for (int pass = 0; pass < npass; ++pass) {
        const __half* pAh = pass ? b.A2h : b.Ah[z];
        const __half* pAl = pass ? b.A2l : b.Al[z];
        const __half* pWh = pass ? b.W2h : b.Wh[z];
        const __half* pWl = pass ? b.W2l : b.Wl[z];
        __syncthreads();

        auto ld_stage = [&](int buf, int k0) {
#pragma unroll
            for (int i = 0; i < 8; ++i) {
                const int tile = i >> 1;               // 0:Ahi 1:Alo 2:Whi 3:Wlo
                const int rem  = ((i & 1) << 8) + t;   // 0..511
                const int row  = rem >> 2;
                const int chn  = t & 3;
                const __half* src;
                if (tile == 0)      src = pAh + (size_t)(bm + row) * lda + k0 + chn * 8;
                else if (tile == 1) src = pAl + (size_t)(bm + row) * lda + k0 + chn * 8;
                else if (tile == 2) src = pWh + (size_t)(bn + row) * ldw + k0 + chn * 8;
                else                src = pWl + (size_t)(bn + row) * ldw + k0 + chn * 8;
                const uint32_t dst = sbase + buf * STG_BYTES + tile * 8192
                                   + row * 64 + ((chn ^ ((row >> 1) & 3)) << 4);
                CP_ASYNC16(dst, src);
            }
        };

        ld_stage(0, 0);   CP_COMMIT();
        ld_stage(1, TBK); CP_COMMIT();

        for (int s = 0; s < nstage; ++s) {
            if (s == nstage - 1) CP_WAIT0(); else CP_WAIT1();
            __syncthreads();
            if (s + 2 < nstage) { ld_stage((s + 2) % 3, (s + 2) * TBK); CP_COMMIT(); }

            const uint32_t stg = sbase + (s % 3) * STG_BYTES;
            const uint32_t a_h = stg, a_l = stg + 8192;
            const uint32_t w_h = stg + 16384, w_l = stg + 24576;

#pragma unroll
            for (int kk = 0; kk < 2; ++kk) {
                uint32_t Bh[4][2], Bl[4][2];
#pragma unroll
                for (int np = 0; np < 2; ++np) {
                    const int nr = wn * 32 + np * 16 + seg2 * 8 + lr;
                    const int ch = kk * 2 + hsel;
                    const uint32_t off = nr * 64 + ((ch ^ ((nr >> 1) & 3)) << 4);
                    LDSM_X4(Bh[np*2][0], Bh[np*2][1], Bh[np*2+1][0], Bh[np*2+1][1], w_h + off);
                    LDSM_X4(Bl[np*2][0], Bl[np*2][1], Bl[np*2+1][0], Bl[np*2+1][1], w_l + off);
                }
                uint32_t Ah[4][4], Al[4][4];
#pragma unroll
                for (int mi = 0; mi < 4; ++mi) {
                    const int ar = wm * 64 + mi * 16 + hsel * 8 + lr;
                    const int ch = kk * 2 + seg2;
                    const uint32_t off = ar * 64 + ((ch ^ ((ar >> 1) & 3)) << 4);
                    LDSM_X4(Ah[mi][0], Ah[mi][1], Ah[mi][2], Ah[mi][3], a_h + off);
                    LDSM_X4(Al[mi][0], Al[mi][1], Al[mi][2], Al[mi][3], a_l + off);
                }
#pragma unroll
                for (int mi = 0; mi < 4; ++mi)
#pragma unroll
                    for (int ni = 0; ni < 4; ++ni)
                        mma_f16(acc[mi][ni], Ah[mi][0], Ah[mi][1], Ah[mi][2], Ah[mi][3],
                                Bh[ni][0], Bh[ni][1]);
#pragma unroll
                for (int mi = 0; mi < 4; ++mi)
#pragma unroll
                    for (int ni = 0; ni < 4; ++ni)
                        mma_f16(acc[mi][ni], Al[mi][0], Al[mi][1], Al[mi][2], Al[mi][3],
                                Bh[ni][0], Bh[ni][1]);
                if (passes3) {
#pragma unroll
                    for (int mi = 0; mi < 4; ++mi)
#pragma unroll
                        for (int ni = 0; ni < 4; ++ni)
                            mma_f16(acc[mi][ni], Ah[mi][0], Ah[mi][1], Ah[mi][2], Ah[mi][3],
                                    Bl[ni][0], Bl[ni][1]);
                }
            }
        }
    }

    // ---------------- epilogue ----------------
#pragma unroll
    for (int mi = 0; mi < 4; ++mi) {
#pragma unroll
        for (int ni = 0; ni < 4; ++ni) {
            const int col = bn + wn * 32 + ni * 8 + 2 * tg;
            float bx = 0.f, by = 0.f;
            if (b.bias[z]) { bx = b.bias[z][col]; by = b.bias[z][col + 1]; }
#pragma unroll
            for (int hf = 0; hf < 2; ++hf) {
                const int row = bm + wm * 64 + mi * 16 + grp + hf * 8;
                float v0 = acc[mi][ni][hf * 2 + 0] + bx;
                float v1 = acc[mi][ni][hf * 2 + 1] + by;
                const size_t idx = (size_t)row * N + col;
                if (epi == 0) {
                    *(float2*)(b.C[z] + idx) = make_float2(v0, v1);
                } else if (epi == 1) {
                    float u3;
                    u3 = v0 * v0 * v0;
                    v0 = 0.5f * v0 * (1.f + tanhf(0.7978845608028654f * (v0 + 0.044715f * u3)));
                    u3 = v1 * v1 * v1;
                    v1 = 0.5f * v1 * (1.f + tanhf(0.7978845608028654f * (v1 + 0.044715f * u3)));
                    __half2 hh = __floats2half2_rn(v0, v1);
                    float2 hv = __half22float2(hh);
                    __half2 ll = __floats2half2_rn(v0 - hv.x, v1 - hv.y);
                    *(__half2*)(b.Ch[z] + idx) = hh;
                    *(__half2*)(b.Cl[z] + idx) = ll;
                } else { // epi == 3
                    float s0 = 1.f / (1.f + __expf(-v0));
                    float s1 = 1.f / (1.f + __expf(-v1));
                    float2 xl2 = *(const float2*)(b.xl + idx);
                    float2 xg2 = *(const float2*)(b.xg + idx);
                    v0 = s0 * xl2.x + (1.f - s0) * xg2.x;
                    v1 = s1 * xl2.y + (1.f - s1) * xg2.y;
                    *(float2*)(b.C[z] + idx) = make_float2(v0, v1);
                    __half2 hh = __floats2half2_rn(v0, v1);
                    float2 hv = __half22float2(hh);
                    __half2 ll = __floats2half2_rn(v0 - hv.x, v1 - hv.y);
                    *(__half2*)(b.xch + idx) = hh;
                    *(__half2*)(b.xcl + idx) = ll;
                }
            }
        }
    }
}

// ----------------- fused splitter: f32 -> f16 hi/lo, all tensors ----------
struct SplitSeg { const float4* src; uint2* hi; uint2* lo; unsigned n4; };
struct SplitTab { SplitSeg seg[10]; };

__global__ void split_all_kernel(SplitTab tab)
{
    unsigned idx = blockIdx.x * blockDim.x + threadIdx.x;
#pragma unroll
    for (int s = 0; s < 10; ++s) {
        if (idx < tab.seg[s].n4) {
            float4 v = tab.seg[s].src[idx];
            __half2 h0 = __floats2half2_rn(v.x, v.y);
            __half2 h1 = __floats2half2_rn(v.z, v.w);
            float2 f0 = __half22float2(h0), f1 = __half22float2(h1);
            __half2 l0 = __floats2half2_rn(v.x - f0.x, v.y - f0.y);
            __half2 l1 = __floats2half2_rn(v.z - f1.x, v.w - f1.y);
            tab.seg[s].hi[idx] = make_uint2(*(uint32_t*)&h0, *(uint32_t*)&h1);
            tab.seg[s].lo[idx] = make_uint2(*(uint32_t*)&l0, *(uint32_t*)&l1);
            return;
        }
        idx -= tab.seg[s].n4;
    }
}

// ----------------- sliding-window causal attention (f32x2) ----------------
__global__ __launch_bounds__(64) void attn_kernel(const float* __restrict__ qkv,
                                                  __half* __restrict__ oh,
                                                  __half* __restrict__ ol)
{
    const int qt = blockIdx.x;
    const int b  = blockIdx.y;
    const int h  = blockIdx.z;
    const int t  = threadIdx.x;
    const int qi = qt * 64 + t;

    __shared__ __align__(16) float ks[64][64];
    __shared__ __align__(16) float vs[64][64];

    ull q2[32], o2[32];
    {
        const float4* qb = (const float4*)(qkv + ((size_t)(b * SEQ + qi)) * (3 * DIM) + h * HD);
#pragma unroll
        for (int d4 = 0; d4 < 16; ++d4) {
            float4 v = qb[d4];
            q2[2*d4]   = pack2f(v.x * 0.125f, v.y * 0.125f);
            q2[2*d4+1] = pack2f(v.z * 0.125f, v.w * 0.125f);
        }
    }
#pragma unroll
    for (int i = 0; i < 32; ++i) o2[i] = 0ull;
    float m = -1e30f, l = 0.f;

    const int kt0 = (qt >= 8) ? (qt - 8) : 0;
    for (int kt = kt0; kt <= qt; ++kt) {
        const float* kbase = qkv + ((size_t)(b * SEQ + kt * 64)) * (3 * DIM) + DIM + h * HD + t;
        const float* vbase = kbase + DIM;
        for (int r = 0; r < 64; ++r) {
            ks[r][t] = kbase[(size_t)r * (3 * DIM)];
            vs[r][t] = vbase[(size_t)r * (3 * DIM)];
        }
        __syncthreads();

        int jlo = qi - WIN + 1 - kt * 64; if (jlo < 0)  jlo = 0;
        int jhi = qi - kt * 64;           if (jhi > 63) jhi = 63;
        for (int j = jlo; j <= jhi; ++j) {
            const ull* kr2 = (const ull*)ks[j];
            ull a0 = 0ull, a1 = 0ull, a2 = 0ull, a3 = 0ull;
#pragma unroll
            for (int i = 0; i < 32; i += 4) {
                ffma2(a0, q2[i],   kr2[i]);
                ffma2(a1, q2[i+1], kr2[i+1]);
                ffma2(a2, q2[i+2], kr2[i+2]);
                ffma2(a3, q2[i+3], kr2[i+3]);
            }
            float2 f0 = unpack2f(a0), f1 = unpack2f(a1);
            float2 f2 = unpack2f(a2), f3 = unpack2f(a3);
            float s = ((f0.x + f0.y) + (f1.x + f1.y)) + ((f2.x + f2.y) + (f3.x + f3.y));
            const ull* vr2 = (const ull*)vs[j];
            if (s <= m) {
                float p = __expf(s - m);
                l += p;
                ull p2 = pack2f(p, p);
#pragma unroll
                for (int i = 0; i < 32; ++i) ffma2(o2[i], p2, vr2[i]);
            } else {
                float al = __expf(m - s);
                m = s; l = l * al + 1.f;
                ull al2 = pack2f(al, al);
#pragma unroll
                for (int i = 0; i < 32; ++i) ffma2b(o2[i], al2, vr2[i]);
            }
        }
        __syncthreads();
    }

    const float inv = 1.f / l;
    const size_t ob = ((size_t)(b * SEQ + qi)) * DIM + h * HD;
#pragma unroll
    for (int i = 0; i < 32; i += 2) {
        float2 p0 = unpack2f(o2[i]), p1 = unpack2f(o2[i+1]);
        float v0 = p0.x * inv, v1 = p0.y * inv, v2 = p1.x * inv, v3 = p1.y * inv;
        __half2 h0 = __floats2half2_rn(v0, v1);
        __half2 h1 = __floats2half2_rn(v2, v3);
        float2 f0 = __half22float2(h0), f1 = __half22float2(h1);
        __half2 l0 = __floats2half2_rn(v0 - f0.x, v1 - f0.y);
        __half2 l1 = __floats2half2_rn(v2 - f1.x, v3 - f1.y);
        *(uint2*)(oh + ob + 2*i) = make_uint2(*(uint32_t*)&h0, *(uint32_t*)&h1);
        *(uint2*)(ol + ob + 2*i) = make_uint2(*(uint32_t*)&l0, *(uint32_t*)&l1);
    }
}

// ----------------- fused residual-add + LayerNorm (+split out) ------------
__global__ __launch_bounds__(256) void add_ln_kernel(const float* __restrict__ x,
    const float* __restrict__ r, const float* __restrict__ gg,
    const float* __restrict__ bb, float* __restrict__ y,
    __half* __restrict__ yh, __half* __restrict__ yl)
{
    const int row = blockIdx.x;
    const int t = threadIdx.x;
    __shared__ float red[8];
    __shared__ float bc0, bc1;

    const float* xr = x + (size_t)row * DIM;
    const float* rr = r + (size_t)row * DIM;
    float v[3]; float s = 0.f;
#pragma unroll
    for (int i = 0; i < 3; ++i) { int c = t + i * 256; v[i] = xr[c] + rr[c]; s += v[i]; }
#pragma unroll
    for (int off = 16; off; off >>= 1) s += __shfl_xor_sync(0xffffffffu, s, off);
    if ((t & 31) == 0) red[t >> 5] = s;
    __syncthreads();
    if (t == 0) { float tot = 0.f;
#pragma unroll
        for (int w = 0; w < 8; ++w) tot += red[w];
        bc0 = tot * (1.f / DIM);
    }
    __syncthreads();
    const float mean = bc0;
    float sq = 0.f;
#pragma unroll
    for (int i = 0; i < 3; ++i) { float d = v[i] - mean; sq += d * d; }
#pragma unroll
    for (int off = 16; off; off >>= 1) sq += __shfl_xor_sync(0xffffffffu, sq, off);
    if ((t & 31) == 0) red[t >> 5] = sq;
    __syncthreads();
    if (t == 0) { float tot = 0.f;
#pragma unroll
        for (int w = 0; w < 8; ++w) tot += red[w];
        bc1 = rsqrtf(tot * (1.f / DIM) + 1e-5f);
    }
    __syncthreads();
    const float rstd = bc1;
#pragma unroll
    for (int i = 0; i < 3; ++i) {
        int c = t + i * 256;
        float val = (v[i] - mean) * rstd * gg[c] + bb[c];
        y[(size_t)row * DIM + c] = val;
        __half hh = __float2half_rn(val);
        __half ll = __float2half_rn(val - __half2float(hh));
        yh[(size_t)row * DIM + c] = hh;
        yl[(size_t)row * DIM + c] = ll;
    }
}

// ----------------- final LN with 4-way CMS mean ----------------------------
__global__ __launch_bounds__(256) void ln_final_kernel(const float* __restrict__ xc,
    const float* __restrict__ c0, const float* __restrict__ c1,
    const float* __restrict__ c2, const float* __restrict__ c3,
    const float* __restrict__ gg, const float* __restrict__ bb,
    float* __restrict__ y)
{
    const int row = blockIdx.x;
    const int t = threadIdx.x;
    __shared__ float red[8];
    __shared__ float bc0, bc1;

    const size_t rb = (size_t)row * DIM;
    float v[3]; float s = 0.f;
#pragma unroll
    for (int i = 0; i < 3; ++i) {
        int c = t + i * 256;
        v[i] = xc[rb + c] + 0.25f * (c0[rb + c] + c1[rb + c] + c2[rb + c] + c3[rb + c]);
        s += v[i];
    }
#pragma unroll
    for (int off = 16; off; off >>= 1) s += __shfl_xor_sync(0xffffffffu, s, off);
    if ((t & 31) == 0) red[t >> 5] = s;
    __syncthreads();
    if (t == 0) { float tot = 0.f;
#pragma unroll
        for (int w = 0; w < 8; ++w) tot += red[w];
        bc0 = tot * (1.f / DIM);
    }
    __syncthreads();
    const float mean = bc0;
    float sq = 0.f;
#pragma unroll
    for (int i = 0; i < 3; ++i) { float d = v[i] - mean; sq += d * d; }
#pragma unroll
    for (int off = 16; off; off >>= 1) sq += __shfl_xor_sync(0xffffffffu, sq, off);
    if ((t & 31) == 0) red[t >> 5] = sq;
    __syncthreads();
    if (t == 0) { float tot = 0.f;
#pragma unroll
        for (int w = 0; w < 8; ++w) tot += red[w];
        bc1 = rsqrtf(tot * (1.f / DIM) + 1e-5f);
    }
    __syncthreads();
    const float rstd = bc1;
#pragma unroll
    for (int i = 0; i < 3; ++i) {
        int c = t + i * 256;
        y[rb + c] = (v[i] - mean) * rstd * gg[c] + bb[c];
    }
}

// ----------------- delta-rule scan: f32x2 + 2 barriers/step ---------------
__global__ __launch_bounds__(256) void delta_scan_kernel(const float* __restrict__ tq,
    const float* __restrict__ tk, const float* __restrict__ tv,
    __half* __restrict__ toh, __half* __restrict__ tol, float* __restrict__ Mout)
{
    const int bh = blockIdx.x;
    const int b = bh / NH, h = bh % NH;
    const int t = threadIdx.x;
    const int e = t & 63;
    const int g = t >> 6;

    __shared__ __align__(8) float ks[2][64], vs[2][64], qs[2][64];
    __shared__ float part[2][4][64];
    __shared__ float opart[2][4][64];

    ull M2[8];
#pragma unroll
    for (int i = 0; i < 8; ++i) M2[i] = 0ull;

    const size_t base = ((size_t)b * SEQ) * DIM + h * HD + e;
    float nxt = 0.f;
    if (g == 0) nxt = tk[base];
    else if (g == 1) nxt = tv[base];
    else if (g == 2) nxt = tq[base];

    for (int s = 0; s < SEQ; ++s) {
        const int p = s & 1;
        if (g == 0) ks[p][e] = nxt;
        else if (g == 1) vs[p][e] = nxt;
        else if (g == 2) qs[p][e] = nxt;
        __syncthreads();   // B1
        if (s + 1 < SEQ) {
            size_t nb = base + (size_t)(s + 1) * DIM;
            if (g == 0) nxt = tk[nb];
            else if (g == 1) nxt = tv[nb];
            else if (g == 2) nxt = tq[nb];
        }
        if (g == 0 && s > 0) {
            const int pp = p ^ 1;
            float ov = (opart[pp][0][e] + opart[pp][1][e])
                     + (opart[pp][2][e] + opart[pp][3][e]);
            __half hh = __float2half_rn(ov);
            __half ll = __float2half_rn(ov - __half2float(hh));
            toh[base + (size_t)(s - 1) * DIM] = hh;
            tol[base + (size_t)(s - 1) * DIM] = ll;
        }
        ull k2[8];
        ull pa = 0ull, pb = 0ull;
        const ull* kp = (const ull*)&ks[p][g * 16];
#pragma unroll
        for (int i = 0; i < 8; i += 2) {
            k2[i] = kp[i]; k2[i+1] = kp[i+1];
            ffma2(pa, M2[i], k2[i]);
            ffma2(pb, M2[i+1], k2[i+1]);
        }
        float2 pf = unpack2f(pa), pg = unpack2f(pb);
        part[p][g][e] = (pf.x + pf.y) + (pg.x + pg.y);
        __syncthreads();   // B2
        const float pred  = (part[p][0][e] + part[p][1][e]) + (part[p][2][e] + part[p][3][e]);
        const float delta = LRATE * (vs[p][e] - pred);
        const ull d2 = pack2f(delta, delta);
        const ull* qp = (const ull*)&qs[p][g * 16];
        ull oa = 0ull, obb = 0ull;
#pragma unroll
        for (int i = 0; i < 8; i += 2) {
            ffma2(M2[i], k2[i], d2);     ffma2(oa, M2[i], qp[i]);
            ffma2(M2[i+1], k2[i+1], d2); ffma2(obb, M2[i+1], qp[i+1]);
        }
        float2 of = unpack2f(oa), og = unpack2f(obb);
        opart[p][g][e] = (of.x + of.y) + (og.x + og.y);
    }
    __syncthreads();
    if (g == 0) {
        const int pp = (SEQ - 1) & 1;
        float ov = (opart[pp][0][e] + opart[pp][1][e]) + (opart[pp][2][e] + opart[pp][3][e]);
        __half hh = __float2half_rn(ov);
        __half ll = __float2half_rn(ov - __half2float(hh));
        toh[base + (size_t)(SEQ - 1) * DIM] = hh;
        tol[base + (size_t)(SEQ - 1) * DIM] = ll;
    }
    if (Mout) {
#pragma unroll
        for (int i = 0; i < 8; ++i) {
            float2 mv = unpack2f(M2[i]);
            Mout[(((size_t)b * NH + h) * HD + (g * 16 + 2*i))     * HD + e] = mv.x;
            Mout[(((size_t)b * NH + h) * HD + (g * 16 + 2*i + 1)) * HD + e] = mv.y;
        }
    }
}

// ----------------- launch ---------------------------------------------------
static void* symp(const void* s) {
    void* p = nullptr;
    cudaGetSymbolAddress(&p, s);
    return p;
}

extern "C" void kernel_launch(void* const* d_in, const int* in_sizes, int n_in,
                              void* d_out, int out_size)
{
    const float* x          = (const float*)d_in[0];
    const float* in_proj_w  = (const float*)d_in[1];
    const float* in_proj_b  = (const float*)d_in[2];
    const float* out_proj_w = (const float*)d_in[3];
    const float* out_proj_b = (const float*)d_in[4];
    const float* ln_local_g = (const float*)d_in[5];
    const float* ln_local_b = (const float*)d_in[6];
    const float* t_wq       = (const float*)d_in[7];
    const float* t_wk       = (const float*)d_in[8];
    const float* t_wv       = (const float*)d_in[9];
    const float* t_wo       = (const float*)d_in[10];
    const float* ln_tit_g   = (const float*)d_in[11];
    const float* ln_tit_b   = (const float*)d_in[12];
    const float* gate_w     = (const float*)d_in[13];
    const float* gate_b     = (const float*)d_in[14];
    const float* cms_w1     = (const float*)d_in[15];
    const float* cms_b1     = (const float*)d_in[16];
    const float* cms_w2     = (const float*)d_in[17];
    const float* cms_b2     = (const float*)d_in[18];
    const float* ln_cms_g   = (const float*)d_in[19];
    const float* ln_cms_b   = (const float*)d_in[20];

    float* qkv    = (float*)symp(g_qkv);
    float* proj   = (float*)symp(g_proj);
    float* proj2  = (float*)symp(g_proj2);
    float* xlocal = (float*)symp(g_xlocal);
    float* xglob  = (float*)symp(g_xglobal);
    float* tq     = (float*)symp(g_tq);
    float* tk     = (float*)symp(g_tk);
    float* tv     = (float*)symp(g_tv);
    float* xc     = (float*)symp(g_xc);
    float* cmsb   = (float*)symp(g_cms);

    __half* x_h   = (__half*)symp(g_x_h);   __half* x_l   = (__half*)symp(g_x_l);
    __half* wi_h  = (__half*)symp(g_wi_h);  __half* wi_l  = (__half*)symp(g_wi_l);
    __half* wo_h  = (__half*)symp(g_wo_h);  __half* wo_l  = (__half*)symp(g_wo_l);
    __half* wtq_h = (__half*)symp(g_wtq_h); __half* wtq_l = (__half*)symp(g_wtq_l);
    __half* wtk_h = (__half*)symp(g_wtk_h); __half* wtk_l = (__half*)symp(g_wtk_l);
    __half* wtv_h = (__half*)symp(g_wtv_h); __half* wtv_l = (__half*)symp(g_wtv_l);
    __half* wto_h = (__half*)symp(g_wto_h); __half* wto_l = (__half*)symp(g_wto_l);
    __half* wg_h  = (__half*)symp(g_wg_h);  __half* wg_l  = (__half*)symp(g_wg_l);
    __half* wc1_h = (__half*)symp(g_wc1_h); __half* wc1_l = (__half*)symp(g_wc1_l);
    __half* wc2_h = (__half*)symp(g_wc2_h); __half* wc2_l = (__half*)symp(g_wc2_l);
    __half* att_h = (__half*)symp(g_att_h); __half* att_l = (__half*)symp(g_att_l);
    __half* to_h  = (__half*)symp(g_to_h);  __half* to_l  = (__half*)symp(g_to_l);
    __half* xl_h  = (__half*)symp(g_xl_h);  __half* xl_l  = (__half*)symp(g_xl_l);
    __half* xg_h  = (__half*)symp(g_xg_h);  __half* xg_l  = (__half*)symp(g_xg_l);
    __half* xc_h  = (__half*)symp(g_xc_h);  __half* xc_l  = (__half*)symp(g_xc_l);
    __half* hb_h  = (__half*)symp(g_hb_h);  __half* hb_l  = (__half*)symp(g_hb_l);

    float* out = (float*)d_out;
    float* mout = (out_size >= ROWS * DIM + BATCH * NH * HD * HD)
                      ? out + (size_t)ROWS * DIM : nullptr;

    static cudaStream_t s2 = nullptr;
    static cudaEvent_t ev_fork = nullptr, ev_join = nullptr;
    if (!s2) {
        cudaFuncSetAttribute(gemm_tc, cudaFuncAttributeMaxDynamicSharedMemorySize, GEMM_SMEM);
        cudaStreamCreateWithFlags(&s2, cudaStreamNonBlocking);
        cudaEventCreateWithFlags(&ev_fork, cudaEventDisableTiming);
        cudaEventCreateWithFlags(&ev_join, cudaEventDisableTiming);
    }

    // [0] single fused split of all f32 operands -> f16 hi/lo planes
    {
        SplitTab tab{};
        unsigned tot4 = 0;
        auto add = [&](int i, const float* s, __half* h, __half* l, size_t n) {
            tab.seg[i] = SplitSeg{ (const float4*)s, (uint2*)h, (uint2*)l, (unsigned)(n / 4) };
            tot4 += (unsigned)(n / 4);
        };
        add(0, x, x_h, x_l, (size_t)ROWS * DIM);
        add(1, t_wq, wtq_h, wtq_l, (size_t)DIM * DIM);
        add(2, t_wk, wtk_h, wtk_l, (size_t)DIM * DIM);
        add(3, t_wv, wtv_h, wtv_l, (size_t)DIM * DIM);
        add(4, t_wo, wto_h, wto_l, (size_t)DIM * DIM);
        add(5, in_proj_w, wi_h, wi_l, (size_t)3 * DIM * DIM);
        add(6, out_proj_w, wo_h, wo_l, (size_t)DIM * DIM);
        add(7, gate_w, wg_h, wg_l, (size_t)2 * DIM * DIM);
        add(8, cms_w1, wc1_h, wc1_l, (size_t)16 * DIM * DIM);
        add(9, cms_w2, wc2_h, wc2_l, (size_t)16 * DIM * DIM);
        split_all_kernel<<<(tot4 + 255) / 256, 256>>>(tab);
    }

    cudaEventRecord(ev_fork, 0);
    cudaStreamWaitEvent(s2, ev_fork, 0);

    B4 b{};

    // [s2] Titans projections (z-batched x3) — FULL 3-pass (feeds the scan)
    b = B4{};
    b.Ah[0] = x_h; b.Al[0] = x_l; b.Wh[0] = wtq_h; b.Wl[0] = wtq_l; b.C[0] = tq;
    b.Ah[1] = x_h; b.Al[1] = x_l; b.Wh[1] = wtk_h; b.Wl[1] = wtk_l; b.C[1] = tk;
    b.Ah[2] = x_h; b.Al[2] = x_l; b.Wh[2] = wtv_h; b.Wl[2] = wtv_l; b.C[2] = tv;
    gemm_tc<<<dim3(DIM / TBN, ROWS / TBM, 3), 256, GEMM_SMEM, s2>>>(b, DIM, DIM, DIM, DIM, 0, 1);

    // [s2] delta-rule scan
    delta_scan_kernel<<<BATCH * NH, 256, 0, s2>>>(tq, tk, tv, to_h, to_l, mout);

    // [s2] titans out proj (2-pass) + residual LN -> x_global (+split)
    b = B4{};
    b.Ah[0] = to_h; b.Al[0] = to_l; b.Wh[0] = wto_h; b.Wl[0] = wto_l; b.C[0] = proj2;
    gemm_tc<<<dim3(DIM / TBN, ROWS / TBM, 1), 256, GEMM_SMEM, s2>>>(b, DIM, DIM, DIM, DIM, 0, 0);
    add_ln_kernel<<<ROWS, 256, 0, s2>>>(x, proj2, ln_tit_g, ln_tit_b, xglob, xg_h, xg_l);
    cudaEventRecord(ev_join, s2);

    // [0] packed QKV projection (2-pass)
    b = B4{};
    b.Ah[0] = x_h; b.Al[0] = x_l; b.Wh[0] = wi_h; b.Wl[0] = wi_l;
    b.bias[0] = in_proj_b; b.C[0] = qkv;
    gemm_tc<<<dim3(3 * DIM / TBN, ROWS / TBM, 1), 256, GEMM_SMEM>>>(b, DIM, DIM, 3 * DIM, DIM, 0, 0);

    // [0] sliding-window attention -> split att
    attn_kernel<<<dim3(SEQ / 64, BATCH, NH), 64>>>(qkv, att_h, att_l);

    // [0] out_proj (2-pass) + residual LN -> x_local (+split)
    b = B4{};
    b.Ah[0] = att_h; b.Al[0] = att_l; b.Wh[0] = wo_h; b.Wl[0] = wo_l;
    b.bias[0] = out_proj_b; b.C[0] = proj;
    gemm_tc<<<dim3(DIM / TBN, ROWS / TBM, 1), 256, GEMM_SMEM>>>(b, DIM, DIM, DIM, DIM, 0, 0);
    add_ln_kernel<<<ROWS, 256>>>(x, proj, ln_local_g, ln_local_b, xlocal, xl_h, xl_l);

    // ---- join ----
    cudaStreamWaitEvent(0, ev_join, 0);

    // [0] gate (2-pass x 2 K-chunks) with fused sigmoid-combine
    b = B4{};
    b.Ah[0] = xl_h; b.Al[0] = xl_l; b.Wh[0] = wg_h; b.Wl[0] = wg_l;
    b.bias[0] = gate_b; b.C[0] = xc;
    b.A2h = xg_h; b.A2l = xg_l; b.W2h = wg_h + DIM; b.W2l = wg_l + DIM;
    b.xl = xlocal; b.xg = xglob; b.xch = xc_h; b.xcl = xc_l;
    gemm_tc<<<dim3(DIM / TBN, ROWS / TBM, 1), 256, GEMM_SMEM>>>(b, DIM, 2 * DIM, DIM, DIM, 3, 0);

    // [0] CMS: w1 x4 (gelu, split-only output, 2-pass), z-batched
    b = B4{};
    for (int l = 0; l < 4; ++l) {
        b.Ah[l] = xc_h; b.Al[l] = xc_l;
        b.Wh[l] = wc1_h + (size_t)l * 4 * DIM * DIM;
        b.Wl[l] = wc1_l + (size_t)l * 4 * DIM * DIM;
        b.bias[l] = cms_b1 + (size_t)l * 4 * DIM;
        b.Ch[l] = hb_h + (size_t)l * ROWS * 4 * DIM;
        b.Cl[l] = hb_l + (size_t)l * ROWS * 4 * DIM;
    }
    gemm_tc<<<dim3(4 * DIM / TBN, ROWS / TBM, 4), 256, GEMM_SMEM>>>(b, DIM, DIM, 4 * DIM, DIM, 1, 0);

    // [0] CMS: w2 x4 (2-pass), z-batched, per-level f32 outputs
    b = B4{};
    for (int l = 0; l < 4; ++l) {
        b.Ah[l] = hb_h + (size_t)l * ROWS * 4 * DIM;
        b.Al[l] = hb_l + (size_t)l * ROWS * 4 * DIM;
        b.Wh[l] = wc2_h + (size_t)l * 4 * DIM * DIM;
        b.Wl[l] = wc2_l + (size_t)l * 4 * DIM * DIM;
        b.bias[l] = cms_b2 + (size_t)l * DIM;
        b.C[l] = cmsb + (size_t)l * ROWS * DIM;
    }
    gemm_tc<<<dim3(DIM / TBN, ROWS / TBM, 4), 256, GEMM_SMEM>>>(b, 4 * DIM, 4 * DIM, DIM, 4 * DIM, 0, 0);

    // [0] final LN
    ln_final_kernel<<<ROWS, 256>>>(xc, cmsb, cmsb + (size_t)ROWS * DIM,
                                   cmsb + 2 * (size_t)ROWS * DIM, cmsb + 3 * (size_t)ROWS * DIM,
                                   ln_cms_g, ln_cms_b, out);
}

// round 12
// speedup vs baseline: 1.3055x; 1.1819x over previous
#include <cuda_runtime.h>
#include <cuda_fp16.h>
#include <math.h>
#include <stdint.h>

#define SEQ   2048
#define BATCH 2
#define DIM   768
#define NH    12
#define HD    64
#define WIN   512
#define ROWS  (BATCH*SEQ)     // 4096
#define LRATE 0.1f

typedef unsigned long long ull;

// ----------------- device scratch (no cudaMalloc allowed) -----------------
__device__ float g_qkv[ROWS*3*DIM];
__device__ float g_proj[ROWS*DIM];
__device__ float g_proj2[ROWS*DIM];
__device__ float g_xlocal[ROWS*DIM];
__device__ float g_xglobal[ROWS*DIM];
__device__ float g_tq[ROWS*DIM];
__device__ float g_tk[ROWS*DIM];
__device__ float g_tv[ROWS*DIM];
__device__ float g_xc[ROWS*DIM];
__device__ float g_cms[4*(size_t)ROWS*DIM];

// hi/lo f16 planes for GEMM operands
__device__ __half g_x_h[ROWS*DIM],     g_x_l[ROWS*DIM];
__device__ __half g_wi_h[3*DIM*DIM],   g_wi_l[3*DIM*DIM];
__device__ __half g_wo_h[DIM*DIM],     g_wo_l[DIM*DIM];
__device__ __half g_wtq_h[DIM*DIM],    g_wtq_l[DIM*DIM];
__device__ __half g_wtk_h[DIM*DIM],    g_wtk_l[DIM*DIM];
__device__ __half g_wtv_h[DIM*DIM],    g_wtv_l[DIM*DIM];
__device__ __half g_wto_h[DIM*DIM],    g_wto_l[DIM*DIM];
__device__ __half g_wg_h[2*DIM*DIM],   g_wg_l[2*DIM*DIM];
__device__ __half g_wc1_h[4*4*DIM*DIM], g_wc1_l[4*4*DIM*DIM];
__device__ __half g_wc2_h[4*4*DIM*DIM], g_wc2_l[4*4*DIM*DIM];
__device__ __half g_att_h[ROWS*DIM],   g_att_l[ROWS*DIM];
__device__ __half g_to_h[ROWS*DIM],    g_to_l[ROWS*DIM];
__device__ __half g_xl_h[ROWS*DIM],    g_xl_l[ROWS*DIM];
__device__ __half g_xg_h[ROWS*DIM],    g_xg_l[ROWS*DIM];
__device__ __half g_xc_h[ROWS*DIM],    g_xc_l[ROWS*DIM];
__device__ __half g_hb_h[4*(size_t)ROWS*4*DIM], g_hb_l[4*(size_t)ROWS*4*DIM];

// ----------------- f32x2 packed helpers ------------------------------------
__device__ __forceinline__ void ffma2(ull& d, ull a, ull b) {      // d += a*b
    asm("fma.rn.f32x2 %0, %1, %2, %0;" : "+l"(d) : "l"(a), "l"(b));
}
__device__ __forceinline__ void ffma2b(ull& d, ull a, ull b) {     // d = d*a + b
    asm("fma.rn.f32x2 %0, %0, %1, %2;" : "+l"(d) : "l"(a), "l"(b));
}
__device__ __forceinline__ ull pack2f(float x, float y) {
    ull r; asm("mov.b64 %0, {%1, %2};" : "=l"(r) : "f"(x), "f"(y)); return r;
}
__device__ __forceinline__ float2 unpack2f(ull v) {
    float x, y; asm("mov.b64 {%0, %1}, %2;" : "=f"(x), "=f"(y) : "l"(v));
    return make_float2(x, y);
}

// ===================== fp16 multi-pass GEMM with pre-split operands ========
// passes==3: hh + lh + hl (full fp32 emulation, ~2^-23)  [scan inputs]
// passes==2: hh + lh      (exact a * b_hi, ~2^-12 in b)  [out-path matmuls]
// passes==1: hh           (pure fp16, ~2^-11)            [CMS: small values]
#define TBM 128
#define TBN 128
#define TBK 32
#define STG_BYTES 32768
#define GEMM_SMEM (3*STG_BYTES)          // 98304 -> 2 blocks/SM

#define CP_ASYNC16(dst, src) \
    asm volatile("cp.async.cg.shared.global [%0], [%1], 16;" :: "r"(dst), "l"(src))
#define CP_COMMIT() asm volatile("cp.async.commit_group;")
#define CP_WAIT1()  asm volatile("cp.async.wait_group 1;" ::: "memory")
#define CP_WAIT0()  asm volatile("cp.async.wait_group 0;" ::: "memory")
#define LDSM_X4(r0,r1,r2,r3,addr) \
    asm volatile("ldmatrix.sync.aligned.m8n8.x4.shared.b16 {%0,%1,%2,%3}, [%4];" \
        : "=r"(r0),"=r"(r1),"=r"(r2),"=r"(r3) : "r"(addr))

struct B4 {
    const __half *Ah[4], *Al[4], *Wh[4], *Wl[4];
    const float* bias[4];
    float* C[4];
    __half *Ch[4], *Cl[4];
    const __half *A2h, *A2l, *W2h, *W2l;
    const float *xl, *xg;
    __half *xch, *xcl;
};

__device__ __forceinline__ uint32_t smem_u32(const void* p) {
    uint32_t a;
    asm("{ .reg .u64 t; cvta.to.shared.u64 t, %1; cvt.u32.u64 %0, t; }" : "=r"(a) : "l"(p));
    return a;
}
__device__ __forceinline__ void mma_f16(float* c, uint32_t a0, uint32_t a1,
                                        uint32_t a2, uint32_t a3,
                                        uint32_t b0, uint32_t b1) {
    asm volatile("mma.sync.aligned.m16n8k16.row.col.f32.f16.f16.f32 "
                 "{%0,%1,%2,%3}, {%4,%5,%6,%7}, {%8,%9}, {%0,%1,%2,%3};"
                 : "+f"(c[0]), "+f"(c[1]), "+f"(c[2]), "+f"(c[3])
                 : "r"(a0), "r"(a1), "r"(a2), "r"(a3), "r"(b0), "r"(b1));
}

__global__ __launch_bounds__(256, 2) void gemm_tc(
    B4 b, int lda, int ldw, int N, int K, int epi, int passes)
{
    extern __shared__ char smc[];
    const int t   = threadIdx.x;
    const int lid = t & 31;
    const int wid = t >> 5;
    const int wm  = wid & 1;
    const int wn  = wid >> 1;
    const int grp = lid >> 2;
    const int tg  = lid & 3;
    const int bm  = blockIdx.y * TBM;
    const int bn  = blockIdx.x * TBN;
    const int z   = blockIdx.z;

    float acc[4][4][4];
#pragma unroll
    for (int mi = 0; mi < 4; ++mi)
#pragma unroll
        for (int ni = 0; ni < 4; ++ni)
#pragma unroll
            for (int r = 0; r < 4; ++r) acc[mi][ni][r] = 0.f;

    const int nstage = K / TBK;
    const int npass  = b.A2h ? 2 : 1;
    const uint32_t sbase = smem_u32(smc);

    const int lr    = lid & 7;
    const int hsel  = (lid >> 3) & 1;
    const int seg2  = (lid >> 4) & 1;

    for (int pass = 0; pass < npass; ++pass) {
        const __half* pAh = pass ? b.A2h : b.Ah[z];
        const __half* pAl = pass ? b.A2l : b.Al[z];
        const __half* pWh = pass ? b.W2h : b.Wh[z];
        const __half* pWl = pass ? b.W2l : b.Wl[z];
        __syncthreads();

        auto ld_stage = [&](int buf, int k0) {
#pragma unroll
            for (int i = 0; i < 8; ++i) {
                const int tile = i >> 1;               // 0:Ahi 1:Alo 2:Whi 3:Wlo
                if (tile == 1 && passes < 2) continue; // skip Alo for 1-pass
                if (tile == 3 && passes < 3) continue; // skip Wlo for <3-pass
                const int rem  = ((i & 1) << 8) + t;   // 0..511
                const int row  = rem >> 2;
                const int chn  = t & 3;
                const __half* src;
                if (tile == 0)      src = pAh + (size_t)(bm + row) * lda + k0 + chn * 8;
                else if (tile == 1) src = pAl + (size_t)(bm + row) * lda + k0 + chn * 8;
                else if (tile == 2) src = pWh + (size_t)(bn + row) * ldw + k0 + chn * 8;
                else                src = pWl + (size_t)(bn + row) * ldw + k0 + chn * 8;
                const uint32_t dst = sbase + buf * STG_BYTES + tile * 8192
                                   + row * 64 + ((chn ^ ((row >> 1) & 3)) << 4);
                CP_ASYNC16(dst, src);
            }
        };

        ld_stage(0, 0);   CP_COMMIT();
        ld_stage(1, TBK); CP_COMMIT();

        for (int s = 0; s < nstage; ++s) {
            if (s == nstage - 1) CP_WAIT0(); else CP_WAIT1();
            __syncthreads();
            if (s + 2 < nstage) { ld_stage((s + 2) % 3, (s + 2) * TBK); CP_COMMIT(); }

            const uint32_t stg = sbase + (s % 3) * STG_BYTES;
            const uint32_t a_h = stg, a_l = stg + 8192;
            const uint32_t w_h = stg + 16384, w_l = stg + 24576;

#pragma unroll
            for (int kk = 0; kk < 2; ++kk) {
                uint32_t Bh[4][2], Bl[4][2];
#pragma unroll
                for (int np = 0; np < 2; ++np) {
                    const int nr = wn * 32 + np * 16 + seg2 * 8 + lr;
                    const int ch = kk * 2 + hsel;
                    const uint32_t off = nr * 64 + ((ch ^ ((nr >> 1) & 3)) << 4);
                    LDSM_X4(Bh[np*2][0], Bh[np*2][1], Bh[np*2+1][0], Bh[np*2+1][1], w_h + off);
                    if (passes == 3)
                        LDSM_X4(Bl[np*2][0], Bl[np*2][1], Bl[np*2+1][0], Bl[np*2+1][1], w_l + off);
                }
                uint32_t Ah[4][4], Al[4][4];
#pragma unroll
                for (int mi = 0; mi < 4; ++mi) {
                    const int ar = wm * 64 + mi * 16 + hsel * 8 + lr;
                    const int ch = kk * 2 + seg2;
                    const uint32_t off = ar * 64 + ((ch ^ ((ar >> 1) & 3)) << 4);
                    LDSM_X4(Ah[mi][0], Ah[mi][1], Ah[mi][2], Ah[mi][3], a_h + off);
                    if (passes >= 2)
                        LDSM_X4(Al[mi][0], Al[mi][1], Al[mi][2], Al[mi][3], a_l + off);
                }
#pragma unroll
                for (int mi = 0; mi < 4; ++mi)
#pragma unroll
                    for (int ni = 0; ni < 4; ++ni)
                        mma_f16(acc[mi][ni], Ah[mi][0], Ah[mi][1], Ah[mi][2], Ah[mi][3],
                                Bh[ni][0], Bh[ni][1]);
                if (passes >= 2) {
#pragma unroll
                    for (int mi = 0; mi < 4; ++mi)
#pragma unroll
                        for (int ni = 0; ni < 4; ++ni)
                            mma_f16(acc[mi][ni], Al[mi][0], Al[mi][1], Al[mi][2], Al[mi][3],
                                    Bh[ni][0], Bh[ni][1]);
                }
                if (passes == 3) {
#pragma unroll
                    for (int mi = 0; mi < 4; ++mi)
#pragma unroll
                        for (int ni = 0; ni < 4; ++ni)
                            mma_f16(acc[mi][ni], Ah[mi][0], Ah[mi][1], Ah[mi][2], Ah[mi][3],
                                    Bl[ni][0], Bl[ni][1]);
                }
            }
        }
    }

    // ---------------- epilogue ----------------
#pragma unroll
    for (int mi = 0; mi < 4; ++mi) {
#pragma unroll
        for (int ni = 0; ni < 4; ++ni) {
            const int col = bn + wn * 32 + ni * 8 + 2 * tg;
            float bx = 0.f, by = 0.f;
            if (b.bias[z]) { bx = b.bias[z][col]; by = b.bias[z][col + 1]; }
#pragma unroll
            for (int hf = 0; hf < 2; ++hf) {
                const int row = bm + wm * 64 + mi * 16 + grp + hf * 8;
                float v0 = acc[mi][ni][hf * 2 + 0] + bx;
                float v1 = acc[mi][ni][hf * 2 + 1] + by;
                const size_t idx = (size_t)row * N + col;
                if (epi == 0) {
                    *(float2*)(b.C[z] + idx) = make_float2(v0, v1);
                } else if (epi == 1) {
                    float u3;
                    u3 = v0 * v0 * v0;
                    v0 = 0.5f * v0 * (1.f + tanhf(0.7978845608028654f * (v0 + 0.044715f * u3)));
                    u3 = v1 * v1 * v1;
                    v1 = 0.5f * v1 * (1.f + tanhf(0.7978845608028654f * (v1 + 0.044715f * u3)));
                    __half2 hh = __floats2half2_rn(v0, v1);
                    *(__half2*)(b.Ch[z] + idx) = hh;
                    if (b.Cl[z]) {
                        float2 hv = __half22float2(hh);
                        __half2 ll = __floats2half2_rn(v0 - hv.x, v1 - hv.y);
                        *(__half2*)(b.Cl[z] + idx) = ll;
                    }
                } else { // epi == 3
                    float s0 = 1.f / (1.f + __expf(-v0));
                    float s1 = 1.f / (1.f + __expf(-v1));
                    float2 xl2 = *(const float2*)(b.xl + idx);
                    float2 xg2 = *(const float2*)(b.xg + idx);
                    v0 = s0 * xl2.x + (1.f - s0) * xg2.x;
                    v1 = s1 * xl2.y + (1.f - s1) * xg2.y;
                    *(float2*)(b.C[z] + idx) = make_float2(v0, v1);
                    __half2 hh = __floats2half2_rn(v0, v1);
                    *(__half2*)(b.xch + idx) = hh;
                    if (b.xcl) {
                        float2 hv = __half22float2(hh);
                        __half2 ll = __floats2half2_rn(v0 - hv.x, v1 - hv.y);
                        *(__half2*)(b.xcl + idx) = ll;
                    }
                }
            }
        }
    }
}

// ----------------- fused splitter: f32 -> f16 hi/lo, all tensors ----------
struct SplitSeg { const float4* src; uint2* hi; uint2* lo; unsigned n4; };
struct SplitTab { SplitSeg seg[10]; };

__global__ void split_all_kernel(SplitTab tab)
{
    unsigned idx = blockIdx.x * blockDim.x + threadIdx.x;
#pragma unroll
    for (int s = 0; s < 10; ++s) {
        if (idx < tab.seg[s].n4) {
            float4 v = tab.seg[s].src[idx];
            __half2 h0 = __floats2half2_rn(v.x, v.y);
            __half2 h1 = __floats2half2_rn(v.z, v.w);
            tab.seg[s].hi[idx] = make_uint2(*(uint32_t*)&h0, *(uint32_t*)&h1);
            if (tab.seg[s].lo) {
                float2 f0 = __half22float2(h0), f1 = __half22float2(h1);
                __half2 l0 = __floats2half2_rn(v.x - f0.x, v.y - f0.y);
                __half2 l1 = __floats2half2_rn(v.z - f1.x, v.w - f1.y);
                tab.seg[s].lo[idx] = make_uint2(*(uint32_t*)&l0, *(uint32_t*)&l1);
            }
            return;
        }
        idx -= tab.seg[s].n4;
    }
}

// ----------------- sliding-window causal attention (f32x2) ----------------
__global__ __launch_bounds__(64) void attn_kernel(const float* __restrict__ qkv,
                                                  __half* __restrict__ oh,
                                                  __half* __restrict__ ol)
{
    const int qt = blockIdx.x;
    const int b  = blockIdx.y;
    const int h  = blockIdx.z;
    const int t  = threadIdx.x;
    const int qi = qt * 64 + t;

    __shared__ __align__(16) float ks[64][64];
    __shared__ __align__(16) float vs[64][64];

    ull q2[32], o2[32];
    {
        const float4* qb = (const float4*)(qkv + ((size_t)(b * SEQ + qi)) * (3 * DIM) + h * HD);
#pragma unroll
        for (int d4 = 0; d4 < 16; ++d4) {
            float4 v = qb[d4];
            q2[2*d4]   = pack2f(v.x * 0.125f, v.y * 0.125f);
            q2[2*d4+1] = pack2f(v.z * 0.125f, v.w * 0.125f);
        }
    }
#pragma unroll
    for (int i = 0; i < 32; ++i) o2[i] = 0ull;
    float m = -1e30f, l = 0.f;

    const int kt0 = (qt >= 8) ? (qt - 8) : 0;
    for (int kt = kt0; kt <= qt; ++kt) {
        const float* kbase = qkv + ((size_t)(b * SEQ + kt * 64)) * (3 * DIM) + DIM + h * HD + t;
        const float* vbase = kbase + DIM;
        for (int r = 0; r < 64; ++r) {
            ks[r][t] = kbase[(size_t)r * (3 * DIM)];
            vs[r][t] = vbase[(size_t)r * (3 * DIM)];
        }
        __syncthreads();

        int jlo = qi - WIN + 1 - kt * 64; if (jlo < 0)  jlo = 0;
        int jhi = qi - kt * 64;           if (jhi > 63) jhi = 63;
        for (int j = jlo; j <= jhi; ++j) {
            const ull* kr2 = (const ull*)ks[j];
            ull a0 = 0ull, a1 = 0ull, a2 = 0ull, a3 = 0ull;
#pragma unroll
            for (int i = 0; i < 32; i += 4) {
                ffma2(a0, q2[i],   kr2[i]);
                ffma2(a1, q2[i+1], kr2[i+1]);
                ffma2(a2, q2[i+2], kr2[i+2]);
                ffma2(a3, q2[i+3], kr2[i+3]);
            }
            float2 f0 = unpack2f(a0), f1 = unpack2f(a1);
            float2 f2 = unpack2f(a2), f3 = unpack2f(a3);
            float s = ((f0.x + f0.y) + (f1.x + f1.y)) + ((f2.x + f2.y) + (f3.x + f3.y));
            const ull* vr2 = (const ull*)vs[j];
            if (s <= m) {
                float p = __expf(s - m);
                l += p;
                ull p2 = pack2f(p, p);
#pragma unroll
                for (int i = 0; i < 32; ++i) ffma2(o2[i], p2, vr2[i]);
            } else {
                float al = __expf(m - s);
                m = s; l = l * al + 1.f;
                ull al2 = pack2f(al, al);
#pragma unroll
                for (int i = 0; i < 32; ++i) ffma2b(o2[i], al2, vr2[i]);
            }
        }
        __syncthreads();
    }

    const float inv = 1.f / l;
    const size_t ob = ((size_t)(b * SEQ + qi)) * DIM + h * HD;
#pragma unroll
    for (int i = 0; i < 32; i += 2) {
        float2 p0 = unpack2f(o2[i]), p1 = unpack2f(o2[i+1]);
        float v0 = p0.x * inv, v1 = p0.y * inv, v2 = p1.x * inv, v3 = p1.y * inv;
        __half2 h0 = __floats2half2_rn(v0, v1);
        __half2 h1 = __floats2half2_rn(v2, v3);
        float2 f0 = __half22float2(h0), f1 = __half22float2(h1);
        __half2 l0 = __floats2half2_rn(v0 - f0.x, v1 - f0.y);
        __half2 l1 = __floats2half2_rn(v2 - f1.x, v3 - f1.y);
        *(uint2*)(oh + ob + 2*i) = make_uint2(*(uint32_t*)&h0, *(uint32_t*)&h1);
        *(uint2*)(ol + ob + 2*i) = make_uint2(*(uint32_t*)&l0, *(uint32_t*)&l1);
    }
}

// ----------------- fused residual-add + LayerNorm (+split out) ------------
__global__ __launch_bounds__(256) void add_ln_kernel(const float* __restrict__ x,
    const float* __restrict__ r, const float* __restrict__ gg,
    const float* __restrict__ bb, float* __restrict__ y,
    __half* __restrict__ yh, __half* __restrict__ yl)
{
    const int row = blockIdx.x;
    const int t = threadIdx.x;
    __shared__ float red[8];
    __shared__ float bc0, bc1;

    const float* xr = x + (size_t)row * DIM;
    const float* rr = r + (size_t)row * DIM;
    float v[3]; float s = 0.f;
#pragma unroll
    for (int i = 0; i < 3; ++i) { int c = t + i * 256; v[i] = xr[c] + rr[c]; s += v[i]; }
#pragma unroll
    for (int off = 16; off; off >>= 1) s += __shfl_xor_sync(0xffffffffu, s, off);
    if ((t & 31) == 0) red[t >> 5] = s;
    __syncthreads();
    if (t == 0) { float tot = 0.f;
#pragma unroll
        for (int w = 0; w < 8; ++w) tot += red[w];
        bc0 = tot * (1.f / DIM);
    }
    __syncthreads();
    const float mean = bc0;
    float sq = 0.f;
#pragma unroll
    for (int i = 0; i < 3; ++i) { float d = v[i] - mean; sq += d * d; }
#pragma unroll
    for (int off = 16; off; off >>= 1) sq += __shfl_xor_sync(0xffffffffu, sq, off);
    if ((t & 31) == 0) red[t >> 5] = sq;
    __syncthreads();
    if (t == 0) { float tot = 0.f;
#pragma unroll
        for (int w = 0; w < 8; ++w) tot += red[w];
        bc1 = rsqrtf(tot * (1.f / DIM) + 1e-5f);
    }
    __syncthreads();
    const float rstd = bc1;
#pragma unroll
    for (int i = 0; i < 3; ++i) {
        int c = t + i * 256;
        float val = (v[i] - mean) * rstd * gg[c] + bb[c];
        y[(size_t)row * DIM + c] = val;
        __half hh = __float2half_rn(val);
        __half ll = __float2half_rn(val - __half2float(hh));
        yh[(size_t)row * DIM + c] = hh;
        yl[(size_t)row * DIM + c] = ll;
    }
}

// ----------------- final LN with 4-way CMS mean ----------------------------
__global__ __launch_bounds__(256) void ln_final_kernel(const float* __restrict__ xc,
    const float* __restrict__ c0, const float* __restrict__ c1,
    const float* __restrict__ c2, const float* __restrict__ c3,
    const float* __restrict__ gg, const float* __restrict__ bb,
    float* __restrict__ y)
{
    const int row = blockIdx.x;
    const int t = threadIdx.x;
    __shared__ float red[8];
    __shared__ float bc0, bc1;

    const size_t rb = (size_t)row * DIM;
    float v[3]; float s = 0.f;
#pragma unroll
    for (int i = 0; i < 3; ++i) {
        int c = t + i * 256;
        v[i] = xc[rb + c] + 0.25f * (c0[rb + c] + c1[rb + c] + c2[rb + c] + c3[rb + c]);
        s += v[i];
    }
#pragma unroll
    for (int off = 16; off; off >>= 1) s += __shfl_xor_sync(0xffffffffu, s, off);
    if ((t & 31) == 0) red[t >> 5] = s;
    __syncthreads();
    if (t == 0) { float tot = 0.f;
#pragma unroll
        for (int w = 0; w < 8; ++w) tot += red[w];
        bc0 = tot * (1.f / DIM);
    }
    __syncthreads();
    const float mean = bc0;
    float sq = 0.f;
#pragma unroll
    for (int i = 0; i < 3; ++i) { float d = v[i] - mean; sq += d * d; }
#pragma unroll
    for (int off = 16; off; off >>= 1) sq += __shfl_xor_sync(0xffffffffu, sq, off);
    if ((t & 31) == 0) red[t >> 5] = sq;
    __syncthreads();
    if (t == 0) { float tot = 0.f;
#pragma unroll
        for (int w = 0; w < 8; ++w) tot += red[w];
        bc1 = rsqrtf(tot * (1.f / DIM) + 1e-5f);
    }
    __syncthreads();
    const float rstd = bc1;
#pragma unroll
    for (int i = 0; i < 3; ++i) {
        int c = t + i * 256;
        y[rb + c] = (v[i] - mean) * rstd * gg[c] + bb[c];
    }
}

// ----------------- delta-rule scan: f32x2 + 2 barriers/step ---------------
__global__ __launch_bounds__(256) void delta_scan_kernel(const float* __restrict__ tq,
    const float* __restrict__ tk, const float* __restrict__ tv,
    __half* __restrict__ toh, __half* __restrict__ tol, float* __restrict__ Mout)
{
    const int bh = blockIdx.x;
    const int b = bh / NH, h = bh % NH;
    const int t = threadIdx.x;
    const int e = t & 63;
    const int g = t >> 6;

    __shared__ __align__(8) float ks[2][64], vs[2][64], qs[2][64];
    __shared__ float part[2][4][64];
    __shared__ float opart[2][4][64];

    ull M2[8];
#pragma unroll
    for (int i = 0; i < 8; ++i) M2[i] = 0ull;

    const size_t base = ((size_t)b * SEQ) * DIM + h * HD + e;
    float nxt = 0.f;
    if (g == 0) nxt = tk[base];
    else if (g == 1) nxt = tv[base];
    else if (g == 2) nxt = tq[base];

    for (int s = 0; s < SEQ; ++s) {
        const int p = s & 1;
        if (g == 0) ks[p][e] = nxt;
        else if (g == 1) vs[p][e] = nxt;
        else if (g == 2) qs[p][e] = nxt;
        __syncthreads();   // B1
        if (s + 1 < SEQ) {
            size_t nb = base + (size_t)(s + 1) * DIM;
            if (g == 0) nxt = tk[nb];
            else if (g == 1) nxt = tv[nb];
            else if (g == 2) nxt = tq[nb];
        }
        if (g == 0 && s > 0) {
            const int pp = p ^ 1;
            float ov = (opart[pp][0][e] + opart[pp][1][e])
                     + (opart[pp][2][e] + opart[pp][3][e]);
            __half hh = __float2half_rn(ov);
            __half ll = __float2half_rn(ov - __half2float(hh));
            toh[base + (size_t)(s - 1) * DIM] = hh;
            tol[base + (size_t)(s - 1) * DIM] = ll;
        }
        ull k2[8];
        ull pa = 0ull, pb = 0ull;
        const ull* kp = (const ull*)&ks[p][g * 16];
#pragma unroll
        for (int i = 0; i < 8; i += 2) {
            k2[i] = kp[i]; k2[i+1] = kp[i+1];
            ffma2(pa, M2[i], k2[i]);
            ffma2(pb, M2[i+1], k2[i+1]);
        }
        float2 pf = unpack2f(pa), pg = unpack2f(pb);
        part[p][g][e] = (pf.x + pf.y) + (pg.x + pg.y);
        __syncthreads();   // B2
        const float pred  = (part[p][0][e] + part[p][1][e]) + (part[p][2][e] + part[p][3][e]);
        const float delta = LRATE * (vs[p][e] - pred);
        const ull d2 = pack2f(delta, delta);
        const ull* qp = (const ull*)&qs[p][g * 16];
        ull oa = 0ull, obb = 0ull;
#pragma unroll
        for (int i = 0; i < 8; i += 2) {
            ffma2(M2[i], k2[i], d2);     ffma2(oa, M2[i], qp[i]);
            ffma2(M2[i+1], k2[i+1], d2); ffma2(obb, M2[i+1], qp[i+1]);
        }
        float2 of = unpack2f(oa), og = unpack2f(obb);
        opart[p][g][e] = (of.x + of.y) + (og.x + og.y);
    }
    __syncthreads();
    if (g == 0) {
        const int pp = (SEQ - 1) & 1;
        float ov = (opart[pp][0][e] + opart[pp][1][e]) + (opart[pp][2][e] + opart[pp][3][e]);
        __half hh = __float2half_rn(ov);
        __half ll = __float2half_rn(ov - __half2float(hh));
        toh[base + (size_t)(SEQ - 1) * DIM] = hh;
        tol[base + (size_t)(SEQ - 1) * DIM] = ll;
    }
    if (Mout) {
#pragma unroll
        for (int i = 0; i < 8; ++i) {
            float2 mv = unpack2f(M2[i]);
            Mout[(((size_t)b * NH + h) * HD + (g * 16 + 2*i))     * HD + e] = mv.x;
            Mout[(((size_t)b * NH + h) * HD + (g * 16 + 2*i + 1)) * HD + e] = mv.y;
        }
    }
}

// ----------------- launch ---------------------------------------------------
static void* symp(const void* s) {
    void* p = nullptr;
    cudaGetSymbolAddress(&p, s);
    return p;
}

extern "C" void kernel_launch(void* const* d_in, const int* in_sizes, int n_in,
                              void* d_out, int out_size)
{
    const float* x          = (const float*)d_in[0];
    const float* in_proj_w  = (const float*)d_in[1];
    const float* in_proj_b  = (const float*)d_in[2];
    const float* out_proj_w = (const float*)d_in[3];
    const float* out_proj_b = (const float*)d_in[4];
    const float* ln_local_g = (const float*)d_in[5];
    const float* ln_local_b = (const float*)d_in[6];
    const float* t_wq       = (const float*)d_in[7];
    const float* t_wk       = (const float*)d_in[8];
    const float* t_wv       = (const float*)d_in[9];
    const float* t_wo       = (const float*)d_in[10];
    const float* ln_tit_g   = (const float*)d_in[11];
    const float* ln_tit_b   = (const float*)d_in[12];
    const float* gate_w     = (const float*)d_in[13];
    const float* gate_b     = (const float*)d_in[14];
    const float* cms_w1     = (const float*)d_in[15];
    const float* cms_b1     = (const float*)d_in[16];
    const float* cms_w2     = (const float*)d_in[17];
    const float* cms_b2     = (const float*)d_in[18];
    const float* ln_cms_g   = (const float*)d_in[19];
    const float* ln_cms_b   = (const float*)d_in[20];

    float* qkv    = (float*)symp(g_qkv);
    float* proj   = (float*)symp(g_proj);
    float* proj2  = (float*)symp(g_proj2);
    float* xlocal = (float*)symp(g_xlocal);
    float* xglob  = (float*)symp(g_xglobal);
    float* tq     = (float*)symp(g_tq);
    float* tk     = (float*)symp(g_tk);
    float* tv     = (float*)symp(g_tv);
    float* xc     = (float*)symp(g_xc);
    float* cmsb   = (float*)symp(g_cms);

    __half* x_h   = (__half*)symp(g_x_h);   __half* x_l   = (__half*)symp(g_x_l);
    __half* wi_h  = (__half*)symp(g_wi_h);  __half* wi_l  = (__half*)symp(g_wi_l);
    __half* wo_h  = (__half*)symp(g_wo_h);  __half* wo_l  = (__half*)symp(g_wo_l);
    __half* wtq_h = (__half*)symp(g_wtq_h); __half* wtq_l = (__half*)symp(g_wtq_l);
    __half* wtk_h = (__half*)symp(g_wtk_h); __half* wtk_l = (__half*)symp(g_wtk_l);
    __half* wtv_h = (__half*)symp(g_wtv_h); __half* wtv_l = (__half*)symp(g_wtv_l);
    __half* wto_h = (__half*)symp(g_wto_h); __half* wto_l = (__half*)symp(g_wto_l);
    __half* wg_h  = (__half*)symp(g_wg_h);  __half* wg_l  = (__half*)symp(g_wg_l);
    __half* wc1_h = (__half*)symp(g_wc1_h);
    __half* wc2_h = (__half*)symp(g_wc2_h);
    __half* att_h = (__half*)symp(g_att_h); __half* att_l = (__half*)symp(g_att_l);
    __half* to_h  = (__half*)symp(g_to_h);  __half* to_l  = (__half*)symp(g_to_l);
    __half* xl_h  = (__half*)symp(g_xl_h);  __half* xl_l  = (__half*)symp(g_xl_l);
    __half* xg_h  = (__half*)symp(g_xg_h);  __half* xg_l  = (__half*)symp(g_xg_l);
    __half* xc_h  = (__half*)symp(g_xc_h);
    __half* hb_h  = (__half*)symp(g_hb_h);

    float* out = (float*)d_out;
    float* mout = (out_size >= ROWS * DIM + BATCH * NH * HD * HD)
                      ? out + (size_t)ROWS * DIM : nullptr;

    static cudaStream_t s2 = nullptr;
    static cudaEvent_t ev_fork = nullptr, ev_join = nullptr;
    if (!s2) {
        cudaFuncSetAttribute(gemm_tc, cudaFuncAttributeMaxDynamicSharedMemorySize, GEMM_SMEM);
        cudaStreamCreateWithFlags(&s2, cudaStreamNonBlocking);
        cudaEventCreateWithFlags(&ev_fork, cudaEventDisableTiming);
        cudaEventCreateWithFlags(&ev_join, cudaEventDisableTiming);
    }

    // [0] single fused split of all f32 operands -> f16 hi(/lo) planes
    {
        SplitTab tab{};
        unsigned tot4 = 0;
        auto add = [&](int i, const float* s, __half* h, __half* l, size_t n) {
            tab.seg[i] = SplitSeg{ (const float4*)s, (uint2*)h, (uint2*)l, (unsigned)(n / 4) };
            tot4 += (unsigned)(n / 4);
        };
        add(0, x, x_h, x_l, (size_t)ROWS * DIM);
        add(1, t_wq, wtq_h, wtq_l, (size_t)DIM * DIM);
        add(2, t_wk, wtk_h, wtk_l, (size_t)DIM * DIM);
        add(3, t_wv, wtv_h, wtv_l, (size_t)DIM * DIM);
        add(4, t_wo, wto_h, wto_l, (size_t)DIM * DIM);
        add(5, in_proj_w, wi_h, wi_l, (size_t)3 * DIM * DIM);
        add(6, out_proj_w, wo_h, wo_l, (size_t)DIM * DIM);
        add(7, gate_w, wg_h, wg_l, (size_t)2 * DIM * DIM);
        add(8, cms_w1, wc1_h, nullptr, (size_t)16 * DIM * DIM);   // hi-only (1-pass)
        add(9, cms_w2, wc2_h, nullptr, (size_t)16 * DIM * DIM);   // hi-only (1-pass)
        split_all_kernel<<<(tot4 + 255) / 256, 256>>>(tab);
    }

    cudaEventRecord(ev_fork, 0);
    cudaStreamWaitEvent(s2, ev_fork, 0);

    B4 b{};

    // [s2] Titans projections (z-batched x3) — FULL 3-pass (feeds the scan)
    b = B4{};
    b.Ah[0] = x_h; b.Al[0] = x_l; b.Wh[0] = wtq_h; b.Wl[0] = wtq_l; b.C[0] = tq;
    b.Ah[1] = x_h; b.Al[1] = x_l; b.Wh[1] = wtk_h; b.Wl[1] = wtk_l; b.C[1] = tk;
    b.Ah[2] = x_h; b.Al[2] = x_l; b.Wh[2] = wtv_h; b.Wl[2] = wtv_l; b.C[2] = tv;
    gemm_tc<<<dim3(DIM / TBN, ROWS / TBM, 3), 256, GEMM_SMEM, s2>>>(b, DIM, DIM, DIM, DIM, 0, 3);

    // [s2] delta-rule scan
    delta_scan_kernel<<<BATCH * NH, 256, 0, s2>>>(tq, tk, tv, to_h, to_l, mout);

    // [s2] titans out proj (2-pass) + residual LN -> x_global (+split)
    b = B4{};
    b.Ah[0] = to_h; b.Al[0] = to_l; b.Wh[0] = wto_h; b.Wl[0] = wto_l; b.C[0] = proj2;
    gemm_tc<<<dim3(DIM / TBN, ROWS / TBM, 1), 256, GEMM_SMEM, s2>>>(b, DIM, DIM, DIM, DIM, 0, 2);
    add_ln_kernel<<<ROWS, 256, 0, s2>>>(x, proj2, ln_tit_g, ln_tit_b, xglob, xg_h, xg_l);
    cudaEventRecord(ev_join, s2);

    // [0] packed QKV projection (2-pass)
    b = B4{};
    b.Ah[0] = x_h; b.Al[0] = x_l; b.Wh[0] = wi_h; b.Wl[0] = wi_l;
    b.bias[0] = in_proj_b; b.C[0] = qkv;
    gemm_tc<<<dim3(3 * DIM / TBN, ROWS / TBM, 1), 256, GEMM_SMEM>>>(b, DIM, DIM, 3 * DIM, DIM, 0, 2);

    // [0] sliding-window attention -> split att
    attn_kernel<<<dim3(SEQ / 64, BATCH, NH), 64>>>(qkv, att_h, att_l);

    // [0] out_proj (2-pass) + residual LN -> x_local (+split)
    b = B4{};
    b.Ah[0] = att_h; b.Al[0] = att_l; b.Wh[0] = wo_h; b.Wl[0] = wo_l;
    b.bias[0] = out_proj_b; b.C[0] = proj;
    gemm_tc<<<dim3(DIM / TBN, ROWS / TBM, 1), 256, GEMM_SMEM>>>(b, DIM, DIM, DIM, DIM, 0, 2);
    add_ln_kernel<<<ROWS, 256>>>(x, proj, ln_local_g, ln_local_b, xlocal, xl_h, xl_l);

    // ---- join ----
    cudaStreamWaitEvent(0, ev_join, 0);

    // [0] gate (2-pass x 2 K-chunks) with fused sigmoid-combine; xc hi-only
    b = B4{};
    b.Ah[0] = xl_h; b.Al[0] = xl_l; b.Wh[0] = wg_h; b.Wl[0] = wg_l;
    b.bias[0] = gate_b; b.C[0] = xc;
    b.A2h = xg_h; b.A2l = xg_l; b.W2h = wg_h + DIM; b.W2l = wg_l + DIM;
    b.xl = xlocal; b.xg = xglob; b.xch = xc_h; b.xcl = nullptr;
    gemm_tc<<<dim3(DIM / TBN, ROWS / TBM, 1), 256, GEMM_SMEM>>>(b, DIM, 2 * DIM, DIM, DIM, 3, 2);

    // [0] CMS: w1 x4 (gelu, hi-only output, 1-pass), z-batched
    b = B4{};
    for (int l = 0; l < 4; ++l) {
        b.Ah[l] = xc_h;
        b.Wh[l] = wc1_h + (size_t)l * 4 * DIM * DIM;
        b.bias[l] = cms_b1 + (size_t)l * 4 * DIM;
        b.Ch[l] = hb_h + (size_t)l * ROWS * 4 * DIM;
        b.Cl[l] = nullptr;
    }
    gemm_tc<<<dim3(4 * DIM / TBN, ROWS / TBM, 4), 256, GEMM_SMEM>>>(b, DIM, DIM, 4 * DIM, DIM, 1, 1);

    // [0] CMS: w2 x4 (1-pass), z-batched, per-level f32 outputs
    b = B4{};
    for (int l = 0; l < 4; ++l) {
        b.Ah[l] = hb_h + (size_t)l * ROWS * 4 * DIM;
        b.Wh[l] = wc2_h + (size_t)l * 4 * DIM * DIM;
        b.bias[l] = cms_b2 + (size_t)l * DIM;
        b.C[l] = cmsb + (size_t)l * ROWS * DIM;
    }
    gemm_tc<<<dim3(DIM / TBN, ROWS / TBM, 4), 256, GEMM_SMEM>>>(b, 4 * DIM, 4 * DIM, DIM, 4 * DIM, 0, 1);

    // [0] final LN
    ln_final_kernel<<<ROWS, 256>>>(xc, cmsb, cmsb + (size_t)ROWS * DIM,
                                   cmsb + 2 * (size_t)ROWS * DIM, cmsb + 3 * (size_t)ROWS * DIM,
                                   ln_cms_g, ln_cms_b, out);
}

// round 13
// speedup vs baseline: 1.3983x; 1.0711x over previous
#include <cuda_runtime.h>
#include <cuda_fp16.h>
#include <math.h>
#include <stdint.h>

#define SEQ   2048
#define BATCH 2
#define DIM   768
#define NH    12
#define HD    64
#define WIN   512
#define ROWS  (BATCH*SEQ)     // 4096
#define LRATE 0.1f

typedef unsigned long long ull;

// ----------------- device scratch (no cudaMalloc allowed) -----------------
__device__ float g_qkv[ROWS*3*DIM];
__device__ float g_proj[ROWS*DIM];      // out_proj result, then gate_pre result
__device__ float g_proj2[ROWS*DIM];
__device__ float g_xlocal[ROWS*DIM];
__device__ float g_xglobal[ROWS*DIM];
__device__ float g_tq[ROWS*DIM];
__device__ float g_tk[ROWS*DIM];
__device__ float g_tv[ROWS*DIM];
__device__ float g_gpre[ROWS*DIM];
__device__ float g_xc[ROWS*DIM];
__device__ float g_cms[4*(size_t)ROWS*DIM];

// f16 planes for GEMM operands (lo planes only where needed)
__device__ __half g_x_h[ROWS*DIM],     g_x_l[ROWS*DIM];
__device__ __half g_wi_h[3*DIM*DIM],   g_wi_l[3*DIM*DIM];
__device__ __half g_wo_h[DIM*DIM];
__device__ __half g_wtq_h[DIM*DIM],    g_wtq_l[DIM*DIM];
__device__ __half g_wtk_h[DIM*DIM],    g_wtk_l[DIM*DIM];
__device__ __half g_wtv_h[DIM*DIM],    g_wtv_l[DIM*DIM];
__device__ __half g_wto_h[DIM*DIM];
__device__ __half g_wg_h[2*DIM*DIM];
__device__ __half g_wc1_h[4*4*DIM*DIM];
__device__ __half g_wc2_h[4*4*DIM*DIM];
__device__ __half g_att_h[ROWS*DIM];
__device__ __half g_to_h[ROWS*DIM];
__device__ __half g_xl_h[ROWS*DIM];
__device__ __half g_xg_h[ROWS*DIM];
__device__ __half g_xc_h[ROWS*DIM];
__device__ __half g_hb_h[4*(size_t)ROWS*4*DIM];

// ----------------- f32x2 packed helpers ------------------------------------
__device__ __forceinline__ void ffma2(ull& d, ull a, ull b) {      // d += a*b
    asm("fma.rn.f32x2 %0, %1, %2, %0;" : "+l"(d) : "l"(a), "l"(b));
}
__device__ __forceinline__ void ffma2b(ull& d, ull a, ull b) {     // d = d*a + b
    asm("fma.rn.f32x2 %0, %0, %1, %2;" : "+l"(d) : "l"(a), "l"(b));
}
__device__ __forceinline__ ull pack2f(float x, float y) {
    ull r; asm("mov.b64 %0, {%1, %2};" : "=l"(r) : "f"(x), "f"(y)); return r;
}
__device__ __forceinline__ float2 unpack2f(ull v) {
    float x, y; asm("mov.b64 {%0, %1}, %2;" : "=f"(x), "=f"(y) : "l"(v));
    return make_float2(x, y);
}

// ===================== fp16 multi-pass GEMM with pre-split operands ========
// passes==3: hh + lh + hl (full fp32 emulation)  [scan inputs]
// passes==2: hh + lh                              [QKV]
// passes==1: hh                                   [out-path + CMS]
#define TBM 128
#define TBN 128
#define TBK 32
#define STG_BYTES 32768
#define GEMM_SMEM (3*STG_BYTES)          // 98304 -> 2 blocks/SM

#define CP_ASYNC16(dst, src) \
    asm volatile("cp.async.cg.shared.global [%0], [%1], 16;" :: "r"(dst), "l"(src))
#define CP_COMMIT() asm volatile("cp.async.commit_group;")
#define CP_WAIT1()  asm volatile("cp.async.wait_group 1;" ::: "memory")
#define CP_WAIT0()  asm volatile("cp.async.wait_group 0;" ::: "memory")
#define LDSM_X4(r0,r1,r2,r3,addr) \
    asm volatile("ldmatrix.sync.aligned.m8n8.x4.shared.b16 {%0,%1,%2,%3}, [%4];" \
        : "=r"(r0),"=r"(r1),"=r"(r2),"=r"(r3) : "r"(addr))

struct B4 {
    const __half *Ah[4], *Al[4], *Wh[4], *Wl[4];
    const float* bias[4];
    float* C[4];
    __half *Ch[4], *Cl[4];
    const float *xl, *xg, *gpre;    // epi==4 operands
    __half *xch;                    // epi==4 split output (hi only)
};

__device__ __forceinline__ uint32_t smem_u32(const void* p) {
    uint32_t a;
    asm("{ .reg .u64 t; cvta.to.shared.u64 t, %1; cvt.u32.u64 %0, t; }" : "=r"(a) : "l"(p));
    return a;
}
__device__ __forceinline__ void mma_f16(float* c, uint32_t a0, uint32_t a1,
                                        uint32_t a2, uint32_t a3,
                                        uint32_t b0, uint32_t b1) {
    asm volatile("mma.sync.aligned.m16n8k16.row.col.f32.f16.f16.f32 "
                 "{%0,%1,%2,%3}, {%4,%5,%6,%7}, {%8,%9}, {%0,%1,%2,%3};"
                 : "+f"(c[0]), "+f"(c[1]), "+f"(c[2]), "+f"(c[3])
                 : "r"(a0), "r"(a1), "r"(a2), "r"(a3), "r"(b0), "r"(b1));
}

__global__ __launch_bounds__(256, 2) void gemm_tc(
    B4 b, int lda, int ldw, int N, int K, int epi, int passes)
{
    extern __shared__ char smc[];
    const int t   = threadIdx.x;
    const int lid = t & 31;
    const int wid = t >> 5;
    const int wm  = wid & 1;
    const int wn  = wid >> 1;
    const int grp = lid >> 2;
    const int tg  = lid & 3;
    const int bm  = blockIdx.y * TBM;
    const int bn  = blockIdx.x * TBN;
    const int z   = blockIdx.z;

    float acc[4][4][4];
#pragma unroll
    for (int mi = 0; mi < 4; ++mi)
#pragma unroll
        for (int ni = 0; ni < 4; ++ni)
#pragma unroll
            for (int r = 0; r < 4; ++r) acc[mi][ni][r] = 0.f;

    const int nstage = K / TBK;
    const uint32_t sbase = smem_u32(smc);

    const int lr    = lid & 7;
    const int hsel  = (lid >> 3) & 1;
    const int seg2  = (lid >> 4) & 1;

    {
        const __half* pAh = b.Ah[z];
        const __half* pAl = b.Al[z];
        const __half* pWh = b.Wh[z];
        const __half* pWl = b.Wl[z];

        auto ld_stage = [&](int buf, int k0) {
#pragma unroll
            for (int i = 0; i < 8; ++i) {
                const int tile = i >> 1;               // 0:Ahi 1:Alo 2:Whi 3:Wlo
                if (tile == 1 && passes < 2) continue;
                if (tile == 3 && passes < 3) continue;
                const int rem  = ((i & 1) << 8) + t;   // 0..511
                const int row  = rem >> 2;
                const int chn  = t & 3;
                const __half* src;
                if (tile == 0)      src = pAh + (size_t)(bm + row) * lda + k0 + chn * 8;
                else if (tile == 1) src = pAl + (size_t)(bm + row) * lda + k0 + chn * 8;
                else if (tile == 2) src = pWh + (size_t)(bn + row) * ldw + k0 + chn * 8;
                else                src = pWl + (size_t)(bn + row) * ldw + k0 + chn * 8;
                const uint32_t dst = sbase + buf * STG_BYTES + tile * 8192
                                   + row * 64 + ((chn ^ ((row >> 1) & 3)) << 4);
                CP_ASYNC16(dst, src);
            }
        };

        ld_stage(0, 0);   CP_COMMIT();
        ld_stage(1, TBK); CP_COMMIT();

        for (int s = 0; s < nstage; ++s) {
            if (s == nstage - 1) CP_WAIT0(); else CP_WAIT1();
            __syncthreads();
            if (s + 2 < nstage) { ld_stage((s + 2) % 3, (s + 2) * TBK); CP_COMMIT(); }

            const uint32_t stg = sbase + (s % 3) * STG_BYTES;
            const uint32_t a_h = stg, a_l = stg + 8192;
            const uint32_t w_h = stg + 16384, w_l = stg + 24576;

#pragma unroll
            for (int kk = 0; kk < 2; ++kk) {
                uint32_t Bh[4][2], Bl[4][2];
#pragma unroll
                for (int np = 0; np < 2; ++np) {
                    const int nr = wn * 32 + np * 16 + seg2 * 8 + lr;
                    const int ch = kk * 2 + hsel;
                    const uint32_t off = nr * 64 + ((ch ^ ((nr >> 1) & 3)) << 4);
                    LDSM_X4(Bh[np*2][0], Bh[np*2][1], Bh[np*2+1][0], Bh[np*2+1][1], w_h + off);
                    if (passes == 3)
                        LDSM_X4(Bl[np*2][0], Bl[np*2][1], Bl[np*2+1][0], Bl[np*2+1][1], w_l + off);
                }
                uint32_t Ah[4][4], Al[4][4];
#pragma unroll
                for (int mi = 0; mi < 4; ++mi) {
                    const int ar = wm * 64 + mi * 16 + hsel * 8 + lr;
                    const int ch = kk * 2 + seg2;
                    const uint32_t off = ar * 64 + ((ch ^ ((ar >> 1) & 3)) << 4);
                    LDSM_X4(Ah[mi][0], Ah[mi][1], Ah[mi][2], Ah[mi][3], a_h + off);
                    if (passes >= 2)
                        LDSM_X4(Al[mi][0], Al[mi][1], Al[mi][2], Al[mi][3], a_l + off);
                }
#pragma unroll
                for (int mi = 0; mi < 4; ++mi)
#pragma unroll
                    for (int ni = 0; ni < 4; ++ni)
                        mma_f16(acc[mi][ni], Ah[mi][0], Ah[mi][1], Ah[mi][2], Ah[mi][3],
                                Bh[ni][0], Bh[ni][1]);
                if (passes >= 2) {
#pragma unroll
                    for (int mi = 0; mi < 4; ++mi)
#pragma unroll
                        for (int ni = 0; ni < 4; ++ni)
                            mma_f16(acc[mi][ni], Al[mi][0], Al[mi][1], Al[mi][2], Al[mi][3],
                                    Bh[ni][0], Bh[ni][1]);
                }
                if (passes == 3) {
#pragma unroll
                    for (int mi = 0; mi < 4; ++mi)
#pragma unroll
                        for (int ni = 0; ni < 4; ++ni)
                            mma_f16(acc[mi][ni], Ah[mi][0], Ah[mi][1], Ah[mi][2], Ah[mi][3],
                                    Bl[ni][0], Bl[ni][1]);
                }
            }
        }
    }

    // ---------------- epilogue ----------------
#pragma unroll
    for (int mi = 0; mi < 4; ++mi) {
#pragma unroll
        for (int ni = 0; ni < 4; ++ni) {
            const int col = bn + wn * 32 + ni * 8 + 2 * tg;
            float bx = 0.f, by = 0.f;
            if (b.bias[z]) { bx = b.bias[z][col]; by = b.bias[z][col + 1]; }
#pragma unroll
            for (int hf = 0; hf < 2; ++hf) {
                const int row = bm + wm * 64 + mi * 16 + grp + hf * 8;
                float v0 = acc[mi][ni][hf * 2 + 0] + bx;
                float v1 = acc[mi][ni][hf * 2 + 1] + by;
                const size_t idx = (size_t)row * N + col;
                if (epi == 0) {
                    *(float2*)(b.C[z] + idx) = make_float2(v0, v1);
                } else if (epi == 1) {
                    float u3;
                    u3 = v0 * v0 * v0;
                    v0 = 0.5f * v0 * (1.f + tanhf(0.7978845608028654f * (v0 + 0.044715f * u3)));
                    u3 = v1 * v1 * v1;
                    v1 = 0.5f * v1 * (1.f + tanhf(0.7978845608028654f * (v1 + 0.044715f * u3)));
                    __half2 hh = __floats2half2_rn(v0, v1);
                    *(__half2*)(b.Ch[z] + idx) = hh;
                } else { // epi == 4: gate finish (add gpre, sigmoid, combine)
                    float2 gp = *(const float2*)(b.gpre + idx);
                    v0 += gp.x; v1 += gp.y;
                    float s0 = 1.f / (1.f + __expf(-v0));
                    float s1 = 1.f / (1.f + __expf(-v1));
                    float2 xl2 = *(const float2*)(b.xl + idx);
                    float2 xg2 = *(const float2*)(b.xg + idx);
                    v0 = s0 * xl2.x + (1.f - s0) * xg2.x;
                    v1 = s1 * xl2.y + (1.f - s1) * xg2.y;
                    *(float2*)(b.C[z] + idx) = make_float2(v0, v1);
                    __half2 hh = __floats2half2_rn(v0, v1);
                    *(__half2*)(b.xch + idx) = hh;
                }
            }
        }
    }
}

// ----------------- fused splitter: f32 -> f16 hi(/lo) ----------------------
struct SplitSeg { const float4* src; uint2* hi; uint2* lo; unsigned n4; };
struct SplitTab { SplitSeg seg[10]; };

__global__ void split_all_kernel(SplitTab tab)
{
    unsigned idx = blockIdx.x * blockDim.x + threadIdx.x;
#pragma unroll
    for (int s = 0; s < 10; ++s) {
        if (idx < tab.seg[s].n4) {
            float4 v = tab.seg[s].src[idx];
            __half2 h0 = __floats2half2_rn(v.x, v.y);
            __half2 h1 = __floats2half2_rn(v.z, v.w);
            tab.seg[s].hi[idx] = make_uint2(*(uint32_t*)&h0, *(uint32_t*)&h1);
            if (tab.seg[s].lo) {
                float2 f0 = __half22float2(h0), f1 = __half22float2(h1);
                __half2 l0 = __floats2half2_rn(v.x - f0.x, v.y - f0.y);
                __half2 l1 = __floats2half2_rn(v.z - f1.x, v.w - f1.y);
                tab.seg[s].lo[idx] = make_uint2(*(uint32_t*)&l0, *(uint32_t*)&l1);
            }
            return;
        }
        idx -= tab.seg[s].n4;
    }
}

// ----------------- sliding-window causal attention (f32x2, hi-only out) ---
__global__ __launch_bounds__(64) void attn_kernel(const float* __restrict__ qkv,
                                                  __half* __restrict__ oh)
{
    const int qt = blockIdx.x;
    const int b  = blockIdx.y;
    const int h  = blockIdx.z;
    const int t  = threadIdx.x;
    const int qi = qt * 64 + t;

    __shared__ __align__(16) float ks[64][64];
    __shared__ __align__(16) float vs[64][64];

    ull q2[32], o2[32];
    {
        const float4* qb = (const float4*)(qkv + ((size_t)(b * SEQ + qi)) * (3 * DIM) + h * HD);
#pragma unroll
        for (int d4 = 0; d4 < 16; ++d4) {
            float4 v = qb[d4];
            q2[2*d4]   = pack2f(v.x * 0.125f, v.y * 0.125f);
            q2[2*d4+1] = pack2f(v.z * 0.125f, v.w * 0.125f);
        }
    }
#pragma unroll
    for (int i = 0; i < 32; ++i) o2[i] = 0ull;
    float m = -1e30f, l = 0.f;

    const int kt0 = (qt >= 8) ? (qt - 8) : 0;
    for (int kt = kt0; kt <= qt; ++kt) {
        const float* kbase = qkv + ((size_t)(b * SEQ + kt * 64)) * (3 * DIM) + DIM + h * HD + t;
        const float* vbase = kbase + DIM;
        for (int r = 0; r < 64; ++r) {
            ks[r][t] = kbase[(size_t)r * (3 * DIM)];
            vs[r][t] = vbase[(size_t)r * (3 * DIM)];
        }
        __syncthreads();

        int jlo = qi - WIN + 1 - kt * 64; if (jlo < 0)  jlo = 0;
        int jhi = qi - kt * 64;           if (jhi > 63) jhi = 63;
        for (int j = jlo; j <= jhi; ++j) {
            const ull* kr2 = (const ull*)ks[j];
            ull a0 = 0ull, a1 = 0ull, a2 = 0ull, a3 = 0ull;
#pragma unroll
            for (int i = 0; i < 32; i += 4) {
                ffma2(a0, q2[i],   kr2[i]);
                ffma2(a1, q2[i+1], kr2[i+1]);
                ffma2(a2, q2[i+2], kr2[i+2]);
                ffma2(a3, q2[i+3], kr2[i+3]);
            }
            float2 f0 = unpack2f(a0), f1 = unpack2f(a1);
            float2 f2 = unpack2f(a2), f3 = unpack2f(a3);
            float s = ((f0.x + f0.y) + (f1.x + f1.y)) + ((f2.x + f2.y) + (f3.x + f3.y));
            const ull* vr2 = (const ull*)vs[j];
            if (s <= m) {
                float p = __expf(s - m);
                l += p;
                ull p2 = pack2f(p, p);
#pragma unroll
                for (int i = 0; i < 32; ++i) ffma2(o2[i], p2, vr2[i]);
            } else {
                float al = __expf(m - s);
                m = s; l = l * al + 1.f;
                ull al2 = pack2f(al, al);
#pragma unroll
                for (int i = 0; i < 32; ++i) ffma2b(o2[i], al2, vr2[i]);
            }
        }
        __syncthreads();
    }

    const float inv = 1.f / l;
    const size_t ob = ((size_t)(b * SEQ + qi)) * DIM + h * HD;
#pragma unroll
    for (int i = 0; i < 32; i += 2) {
        float2 p0 = unpack2f(o2[i]), p1 = unpack2f(o2[i+1]);
        __half2 h0 = __floats2half2_rn(p0.x * inv, p0.y * inv);
        __half2 h1 = __floats2half2_rn(p1.x * inv, p1.y * inv);
        *(uint2*)(oh + ob + 2*i) = make_uint2(*(uint32_t*)&h0, *(uint32_t*)&h1);
    }
}

// ----------------- fused residual-add + LayerNorm (+hi split out) ---------
__global__ __launch_bounds__(256) void add_ln_kernel(const float* __restrict__ x,
    const float* __restrict__ r, const float* __restrict__ gg,
    const float* __restrict__ bb, float* __restrict__ y,
    __half* __restrict__ yh)
{
    const int row = blockIdx.x;
    const int t = threadIdx.x;
    __shared__ float red[8];
    __shared__ float bc0, bc1;

    const float* xr = x + (size_t)row * DIM;
    const float* rr = r + (size_t)row * DIM;
    float v[3]; float s = 0.f;
#pragma unroll
    for (int i = 0; i < 3; ++i) { int c = t + i * 256; v[i] = xr[c] + rr[c]; s += v[i]; }
#pragma unroll
    for (int off = 16; off; off >>= 1) s += __shfl_xor_sync(0xffffffffu, s, off);
    if ((t & 31) == 0) red[t >> 5] = s;
    __syncthreads();
    if (t == 0) { float tot = 0.f;
#pragma unroll
        for (int w = 0; w < 8; ++w) tot += red[w];
        bc0 = tot * (1.f / DIM);
    }
    __syncthreads();
    const float mean = bc0;
    float sq = 0.f;
#pragma unroll
    for (int i = 0; i < 3; ++i) { float d = v[i] - mean; sq += d * d; }
#pragma unroll
    for (int off = 16; off; off >>= 1) sq += __shfl_xor_sync(0xffffffffu, sq, off);
    if ((t & 31) == 0) red[t >> 5] = sq;
    __syncthreads();
    if (t == 0) { float tot = 0.f;
#pragma unroll
        for (int w = 0; w < 8; ++w) tot += red[w];
        bc1 = rsqrtf(tot * (1.f / DIM) + 1e-5f);
    }
    __syncthreads();
    const float rstd = bc1;
#pragma unroll
    for (int i = 0; i < 3; ++i) {
        int c = t + i * 256;
        float val = (v[i] - mean) * rstd * gg[c] + bb[c];
        y[(size_t)row * DIM + c] = val;
        yh[(size_t)row * DIM + c] = __float2half_rn(val);
    }
}

// ----------------- final LN with 4-way CMS mean ----------------------------
__global__ __launch_bounds__(256) void ln_final_kernel(const float* __restrict__ xc,
    const float* __restrict__ c0, const float* __restrict__ c1,
    const float* __restrict__ c2, const float* __restrict__ c3,
    const float* __restrict__ gg, const float* __restrict__ bb,
    float* __restrict__ y)
{
    const int row = blockIdx.x;
    const int t = threadIdx.x;
    __shared__ float red[8];
    __shared__ float bc0, bc1;

    const size_t rb = (size_t)row * DIM;
    float v[3]; float s = 0.f;
#pragma unroll
    for (int i = 0; i < 3; ++i) {
        int c = t + i * 256;
        v[i] = xc[rb + c] + 0.25f * (c0[rb + c] + c1[rb + c] + c2[rb + c] + c3[rb + c]);
        s += v[i];
    }
#pragma unroll
    for (int off = 16; off; off >>= 1) s += __shfl_xor_sync(0xffffffffu, s, off);
    if ((t & 31) == 0) red[t >> 5] = s;
    __syncthreads();
    if (t == 0) { float tot = 0.f;
#pragma unroll
        for (int w = 0; w < 8; ++w) tot += red[w];
        bc0 = tot * (1.f / DIM);
    }
    __syncthreads();
    const float mean = bc0;
    float sq = 0.f;
#pragma unroll
    for (int i = 0; i < 3; ++i) { float d = v[i] - mean; sq += d * d; }
#pragma unroll
    for (int off = 16; off; off >>= 1) sq += __shfl_xor_sync(0xffffffffu, sq, off);
    if ((t & 31) == 0) red[t >> 5] = sq;
    __syncthreads();
    if (t == 0) { float tot = 0.f;
#pragma unroll
        for (int w = 0; w < 8; ++w) tot += red[w];
        bc1 = rsqrtf(tot * (1.f / DIM) + 1e-5f);
    }
    __syncthreads();
    const float rstd = bc1;
#pragma unroll
    for (int i = 0; i < 3; ++i) {
        int c = t + i * 256;
        y[rb + c] = (v[i] - mean) * rstd * gg[c] + bb[c];
    }
}

// ----------------- delta-rule scan: 1 barrier/step + warp shuffles --------
// warp w owns e in [8w, 8w+8); lane bits 3..4 select d-group g (16 d's each).
__global__ __launch_bounds__(256) void delta_scan_kernel(const float* __restrict__ tq,
    const float* __restrict__ tk, const float* __restrict__ tv,
    __half* __restrict__ toh, float* __restrict__ Mout)
{
    const int bh = blockIdx.x;
    const int b = bh / NH, h = bh % NH;
    const int t = threadIdx.x;
    const int lane = t & 31;
    const int w = t >> 5;
    const int e = w * 8 + (lane & 7);
    const int g = lane >> 3;

    __shared__ __align__(8) float kb[2][64], vb[2][64], qb[2][64];

    ull M2[8];
#pragma unroll
    for (int i = 0; i < 8; ++i) M2[i] = 0ull;

    // staging role: threads 0..191, three groups of 64
    const int grp3 = t >> 6;
    const size_t sbase = ((size_t)b * SEQ) * DIM + h * HD + (t & 63);
    float nxt = 0.f;
    if (grp3 == 0) nxt = tk[sbase];
    else if (grp3 == 1) nxt = tv[sbase];
    else if (grp3 == 2) nxt = tq[sbase];

    const size_t obase = ((size_t)b * SEQ) * DIM + h * HD + e;

    for (int s = 0; s < SEQ; ++s) {
        const int p = s & 1;
        if (grp3 == 0) kb[p][t & 63] = nxt;
        else if (grp3 == 1) vb[p][t & 63] = nxt;
        else if (grp3 == 2) qb[p][t & 63] = nxt;
        __syncthreads();
        if (s + 1 < SEQ) {
            const size_t nb = sbase + (size_t)(s + 1) * DIM;
            if (grp3 == 0) nxt = tk[nb];
            else if (grp3 == 1) nxt = tv[nb];
            else if (grp3 == 2) nxt = tq[nb];
        }
        // pred partial over this thread's 16 d's
        ull k2[8];
        ull pa = 0ull, pb = 0ull;
        const ull* kp = (const ull*)&kb[p][g * 16];
#pragma unroll
        for (int i = 0; i < 8; i += 2) {
            k2[i] = kp[i]; k2[i+1] = kp[i+1];
            ffma2(pa, M2[i], k2[i]);
            ffma2(pb, M2[i+1], k2[i+1]);
        }
        float2 pf = unpack2f(pa), pg2 = unpack2f(pb);
        float pp = (pf.x + pf.y) + (pg2.x + pg2.y);
        float r1 = pp + __shfl_xor_sync(0xffffffffu, pp, 8);
        const float pred = r1 + __shfl_xor_sync(0xffffffffu, r1, 16);
        const float delta = LRATE * (vb[p][e] - pred);
        const ull d2 = pack2f(delta, delta);
        const ull* qp = (const ull*)&qb[p][g * 16];
        ull oa = 0ull, ob2 = 0ull;
#pragma unroll
        for (int i = 0; i < 8; i += 2) {
            ffma2(M2[i], k2[i], d2);     ffma2(oa, M2[i], qp[i]);
            ffma2(M2[i+1], k2[i+1], d2); ffma2(ob2, M2[i+1], qp[i+1]);
        }
        float2 of = unpack2f(oa), og = unpack2f(ob2);
        float oo = (of.x + of.y) + (og.x + og.y);
        float r2 = oo + __shfl_xor_sync(0xffffffffu, oo, 8);
        float ov = r2 + __shfl_xor_sync(0xffffffffu, r2, 16);
        if (g == 0)
            toh[obase + (size_t)s * DIM] = __float2half_rn(ov);
    }
    if (Mout) {
#pragma unroll
        for (int i = 0; i < 8; ++i) {
            float2 mv = unpack2f(M2[i]);
            Mout[(((size_t)b * NH + h) * HD + (g * 16 + 2*i))     * HD + e] = mv.x;
            Mout[(((size_t)b * NH + h) * HD + (g * 16 + 2*i + 1)) * HD + e] = mv.y;
        }
    }
}

// ----------------- launch ---------------------------------------------------
static void* symp(const void* s) {
    void* p = nullptr;
    cudaGetSymbolAddress(&p, s);
    return p;
}

extern "C" void kernel_launch(void* const* d_in, const int* in_sizes, int n_in,
                              void* d_out, int out_size)
{
    const float* x          = (const float*)d_in[0];
    const float* in_proj_w  = (const float*)d_in[1];
    const float* in_proj_b  = (const float*)d_in[2];
    const float* out_proj_w = (const float*)d_in[3];
    const float* out_proj_b = (const float*)d_in[4];
    const float* ln_local_g = (const float*)d_in[5];
    const float* ln_local_b = (const float*)d_in[6];
    const float* t_wq       = (const float*)d_in[7];
    const float* t_wk       = (const float*)d_in[8];
    const float* t_wv       = (const float*)d_in[9];
    const float* t_wo       = (const float*)d_in[10];
    const float* ln_tit_g   = (const float*)d_in[11];
    const float* ln_tit_b   = (const float*)d_in[12];
    const float* gate_w     = (const float*)d_in[13];
    const float* gate_b     = (const float*)d_in[14];
    const float* cms_w1     = (const float*)d_in[15];
    const float* cms_b1     = (const float*)d_in[16];
    const float* cms_w2     = (const float*)d_in[17];
    const float* cms_b2     = (const float*)d_in[18];
    const float* ln_cms_g   = (const float*)d_in[19];
    const float* ln_cms_b   = (const float*)d_in[20];

    float* qkv    = (float*)symp(g_qkv);
    float* proj   = (float*)symp(g_proj);
    float* proj2  = (float*)symp(g_proj2);
    float* xlocal = (float*)symp(g_xlocal);
    float* xglob  = (float*)symp(g_xglobal);
    float* tq     = (float*)symp(g_tq);
    float* tk     = (float*)symp(g_tk);
    float* tv     = (float*)symp(g_tv);
    float* gpre   = (float*)symp(g_gpre);
    float* xc     = (float*)symp(g_xc);
    float* cmsb   = (float*)symp(g_cms);

    __half* x_h   = (__half*)symp(g_x_h);   __half* x_l   = (__half*)symp(g_x_l);
    __half* wi_h  = (__half*)symp(g_wi_h);  __half* wi_l  = (__half*)symp(g_wi_l);
    __half* wo_h  = (__half*)symp(g_wo_h);
    __half* wtq_h = (__half*)symp(g_wtq_h); __half* wtq_l = (__half*)symp(g_wtq_l);
    __half* wtk_h = (__half*)symp(g_wtk_h); __half* wtk_l = (__half*)symp(g_wtk_l);
    __half* wtv_h = (__half*)symp(g_wtv_h); __half* wtv_l = (__half*)symp(g_wtv_l);
    __half* wto_h = (__half*)symp(g_wto_h);
    __half* wg_h  = (__half*)symp(g_wg_h);
    __half* wc1_h = (__half*)symp(g_wc1_h);
    __half* wc2_h = (__half*)symp(g_wc2_h);
    __half* att_h = (__half*)symp(g_att_h);
    __half* to_h  = (__half*)symp(g_to_h);
    __half* xl_h  = (__half*)symp(g_xl_h);
    __half* xg_h  = (__half*)symp(g_xg_h);
    __half* xc_h  = (__half*)symp(g_xc_h);
    __half* hb_h  = (__half*)symp(g_hb_h);

    float* out = (float*)d_out;
    float* mout = (out_size >= ROWS * DIM + BATCH * NH * HD * HD)
                      ? out + (size_t)ROWS * DIM : nullptr;

    static cudaStream_t s2 = nullptr;
    static cudaEvent_t ev_fork = nullptr, ev_join = nullptr;
    if (!s2) {
        cudaFuncSetAttribute(gemm_tc, cudaFuncAttributeMaxDynamicSharedMemorySize, GEMM_SMEM);
        cudaStreamCreateWithFlags(&s2, cudaStreamNonBlocking);
        cudaEventCreateWithFlags(&ev_fork, cudaEventDisableTiming);
        cudaEventCreateWithFlags(&ev_join, cudaEventDisableTiming);
    }

    // [0] single fused split of all f32 operands
    {
        SplitTab tab{};
        unsigned tot4 = 0;
        auto add = [&](int i, const float* s, __half* h, __half* l, size_t n) {
            tab.seg[i] = SplitSeg{ (const float4*)s, (uint2*)h, (uint2*)l, (unsigned)(n / 4) };
            tot4 += (unsigned)(n / 4);
        };
        add(0, x, x_h, x_l, (size_t)ROWS * DIM);
        add(1, t_wq, wtq_h, wtq_l, (size_t)DIM * DIM);
        add(2, t_wk, wtk_h, wtk_l, (size_t)DIM * DIM);
        add(3, t_wv, wtv_h, wtv_l, (size_t)DIM * DIM);
        add(4, t_wo, wto_h, nullptr, (size_t)DIM * DIM);
        add(5, in_proj_w, wi_h, wi_l, (size_t)3 * DIM * DIM);
        add(6, out_proj_w, wo_h, nullptr, (size_t)DIM * DIM);
        add(7, gate_w, wg_h, nullptr, (size_t)2 * DIM * DIM);
        add(8, cms_w1, wc1_h, nullptr, (size_t)16 * DIM * DIM);
        add(9, cms_w2, wc2_h, nullptr, (size_t)16 * DIM * DIM);
        split_all_kernel<<<(tot4 + 255) / 256, 256>>>(tab);
    }

    cudaEventRecord(ev_fork, 0);
    cudaStreamWaitEvent(s2, ev_fork, 0);

    B4 b{};

    // [s2] Titans projections (z-batched x3) — FULL 3-pass (feeds the scan)
    b = B4{};
    b.Ah[0] = x_h; b.Al[0] = x_l; b.Wh[0] = wtq_h; b.Wl[0] = wtq_l; b.C[0] = tq;
    b.Ah[1] = x_h; b.Al[1] = x_l; b.Wh[1] = wtk_h; b.Wl[1] = wtk_l; b.C[1] = tk;
    b.Ah[2] = x_h; b.Al[2] = x_l; b.Wh[2] = wtv_h; b.Wl[2] = wtv_l; b.C[2] = tv;
    gemm_tc<<<dim3(DIM / TBN, ROWS / TBM, 3), 256, GEMM_SMEM, s2>>>(b, DIM, DIM, DIM, DIM, 0, 3);

    // [s2] delta-rule scan (hi-only output + memory_state)
    delta_scan_kernel<<<BATCH * NH, 256, 0, s2>>>(tq, tk, tv, to_h, mout);

    // [s2] titans out proj (1-pass) + residual LN -> x_global (+hi split)
    b = B4{};
    b.Ah[0] = to_h; b.Wh[0] = wto_h; b.C[0] = proj2;
    gemm_tc<<<dim3(DIM / TBN, ROWS / TBM, 1), 256, GEMM_SMEM, s2>>>(b, DIM, DIM, DIM, DIM, 0, 1);
    add_ln_kernel<<<ROWS, 256, 0, s2>>>(x, proj2, ln_tit_g, ln_tit_b, xglob, xg_h);
    cudaEventRecord(ev_join, s2);

    // [0] packed QKV projection (2-pass)
    b = B4{};
    b.Ah[0] = x_h; b.Al[0] = x_l; b.Wh[0] = wi_h;
    b.bias[0] = in_proj_b; b.C[0] = qkv;
    gemm_tc<<<dim3(3 * DIM / TBN, ROWS / TBM, 1), 256, GEMM_SMEM>>>(b, DIM, DIM, 3 * DIM, DIM, 0, 2);

    // [0] sliding-window attention -> att (hi only)
    attn_kernel<<<dim3(SEQ / 64, BATCH, NH), 64>>>(qkv, att_h);

    // [0] out_proj (1-pass) + residual LN -> x_local (+hi split)
    b = B4{};
    b.Ah[0] = att_h; b.Wh[0] = wo_h;
    b.bias[0] = out_proj_b; b.C[0] = proj;
    gemm_tc<<<dim3(DIM / TBN, ROWS / TBM, 1), 256, GEMM_SMEM>>>(b, DIM, DIM, DIM, DIM, 0, 1);
    add_ln_kernel<<<ROWS, 256>>>(x, proj, ln_local_g, ln_local_b, xlocal, xl_h);

    // [0] gate pre-pass (1-pass): gpre = xlocal @ Wg1^T + gate_b (overlaps s2 scan)
    b = B4{};
    b.Ah[0] = xl_h; b.Wh[0] = wg_h;
    b.bias[0] = gate_b; b.C[0] = gpre;
    gemm_tc<<<dim3(DIM / TBN, ROWS / TBM, 1), 256, GEMM_SMEM>>>(b, DIM, 2 * DIM, DIM, DIM, 0, 1);

    // ---- join ----
    cudaStreamWaitEvent(0, ev_join, 0);

    // [0] gate finish (1-pass): logits = gpre + xglob @ Wg2^T -> sigmoid-combine
    b = B4{};
    b.Ah[0] = xg_h; b.Wh[0] = wg_h + DIM;
    b.C[0] = xc;
    b.xl = xlocal; b.xg = xglob; b.gpre = gpre; b.xch = xc_h;
    gemm_tc<<<dim3(DIM / TBN, ROWS / TBM, 1), 256, GEMM_SMEM>>>(b, DIM, 2 * DIM, DIM, DIM, 4, 1);

    // [0] CMS: w1 x4 (gelu, hi-only output, 1-pass), z-batched
    b = B4{};
    for (int l = 0; l < 4; ++l) {
        b.Ah[l] = xc_h;
        b.Wh[l] = wc1_h + (size_t)l * 4 * DIM * DIM;
        b.bias[l] = cms_b1 + (size_t)l * 4 * DIM;
        b.Ch[l] = hb_h + (size_t)l * ROWS * 4 * DIM;
    }
    gemm_tc<<<dim3(4 * DIM / TBN, ROWS / TBM, 4), 256, GEMM_SMEM>>>(b, DIM, DIM, 4 * DIM, DIM, 1, 1);

    // [0] CMS: w2 x4 (1-pass), z-batched, per-level f32 outputs
    b = B4{};
    for (int l = 0; l < 4; ++l) {
        b.Ah[l] = hb_h + (size_t)l * ROWS * 4 * DIM;
        b.Wh[l] = wc2_h + (size_t)l * 4 * DIM * DIM;
        b.bias[l] = cms_b2 + (size_t)l * DIM;
        b.C[l] = cmsb + (size_t)l * ROWS * DIM;
    }
    gemm_tc<<<dim3(DIM / TBN, ROWS / TBM, 4), 256, GEMM_SMEM>>>(b, 4 * DIM, 4 * DIM, DIM, 4 * DIM, 0, 1);

    // [0] final LN
    ln_final_kernel<<<ROWS, 256>>>(xc, cmsb, cmsb + (size_t)ROWS * DIM,
                                   cmsb + 2 * (size_t)ROWS * DIM, cmsb + 3 * (size_t)ROWS * DIM,
                                   ln_cms_g, ln_cms_b, out);
}

// round 14
// speedup vs baseline: 1.4838x; 1.0611x over previous
#include <cuda_runtime.h>
#include <cuda_fp16.h>
#include <math.h>
#include <stdint.h>

#define SEQ   2048
#define BATCH 2
#define DIM   768
#define NH    12
#define HD    64
#define WIN   512
#define ROWS  (BATCH*SEQ)     // 4096
#define LRATE 0.1f

typedef unsigned long long ull;

// ----------------- device scratch (no cudaMalloc allowed) -----------------
__device__ float g_qkv[ROWS*3*DIM];
__device__ float g_proj[ROWS*DIM];
__device__ float g_proj2[ROWS*DIM];
__device__ float g_xlocal[ROWS*DIM];
__device__ float g_xglobal[ROWS*DIM];
__device__ float g_tq[ROWS*DIM];
__device__ float g_tk[ROWS*DIM];
__device__ float g_tv[ROWS*DIM];
__device__ float g_gpre[ROWS*DIM];
__device__ float g_xc[ROWS*DIM];
__device__ float g_cms[4*(size_t)ROWS*DIM];

// f16 planes for GEMM operands (lo planes only where needed)
__device__ __half g_x_h[ROWS*DIM],     g_x_l[ROWS*DIM];
__device__ __half g_wi_h[3*DIM*DIM],   g_wi_l[3*DIM*DIM];
__device__ __half g_wo_h[DIM*DIM];
__device__ __half g_wtq_h[DIM*DIM],    g_wtq_l[DIM*DIM];
__device__ __half g_wtk_h[DIM*DIM],    g_wtk_l[DIM*DIM];
__device__ __half g_wtv_h[DIM*DIM],    g_wtv_l[DIM*DIM];
__device__ __half g_wto_h[DIM*DIM];
__device__ __half g_wg_h[2*DIM*DIM];
__device__ __half g_wc1_h[4*4*DIM*DIM];
__device__ __half g_wc2_h[4*4*DIM*DIM];
__device__ __half g_att_h[ROWS*DIM];
__device__ __half g_to_h[ROWS*DIM];
__device__ __half g_xl_h[ROWS*DIM];
__device__ __half g_xg_h[ROWS*DIM];
__device__ __half g_xc_h[ROWS*DIM];
__device__ __half g_hb_h[4*(size_t)ROWS*4*DIM];

// ----------------- f32x2 packed helpers ------------------------------------
__device__ __forceinline__ void ffma2(ull& d, ull a, ull b) {      // d += a*b
    asm("fma.rn.f32x2 %0, %1, %2, %0;" : "+l"(d) : "l"(a), "l"(b));
}
__device__ __forceinline__ void ffma2b(ull& d, ull a, ull b) {     // d = d*a + b
    asm("fma.rn.f32x2 %0, %0, %1, %2;" : "+l"(d) : "l"(a), "l"(b));
}
__device__ __forceinline__ ull pack2f(float x, float y) {
    ull r; asm("mov.b64 %0, {%1, %2};" : "=l"(r) : "f"(x), "f"(y)); return r;
}
__device__ __forceinline__ float2 unpack2f(ull v) {
    float x, y; asm("mov.b64 {%0, %1}, %2;" : "=f"(x), "=f"(y) : "l"(v));
    return make_float2(x, y);
}

// ===================== shared GEMM infrastructure ==========================
#define TBM 128
#define TBN 128
#define TBK 32
#define STG_BYTES 32768
#define GEMM_SMEM (3*STG_BYTES)          // 98304 -> 2 blocks/SM

#define CP_ASYNC16(dst, src) \
    asm volatile("cp.async.cg.shared.global [%0], [%1], 16;" :: "r"(dst), "l"(src))
#define CP_COMMIT() asm volatile("cp.async.commit_group;")
#define CP_WAIT1()  asm volatile("cp.async.wait_group 1;" ::: "memory")
#define CP_WAIT0()  asm volatile("cp.async.wait_group 0;" ::: "memory")
#define LDSM_X4(r0,r1,r2,r3,addr) \
    asm volatile("ldmatrix.sync.aligned.m8n8.x4.shared.b16 {%0,%1,%2,%3}, [%4];" \
        : "=r"(r0),"=r"(r1),"=r"(r2),"=r"(r3) : "r"(addr))

struct B4 {
    const __half *Ah[4], *Al[4], *Wh[4], *Wl[4];
    const float* bias[4];
    float* C[4];
    __half *Ch[4], *Cl[4];
    const float *xl, *xg, *gpre;    // epi==4 operands
    __half *xch;                    // epi==4 split output (hi only)
};

__device__ __forceinline__ uint32_t smem_u32(const void* p) {
    uint32_t a;
    asm("{ .reg .u64 t; cvta.to.shared.u64 t, %1; cvt.u32.u64 %0, t; }" : "=r"(a) : "l"(p));
    return a;
}
__device__ __forceinline__ void mma_f16(float* c, uint32_t a0, uint32_t a1,
                                        uint32_t a2, uint32_t a3,
                                        uint32_t b0, uint32_t b1) {
    asm volatile("mma.sync.aligned.m16n8k16.row.col.f32.f16.f16.f32 "
                 "{%0,%1,%2,%3}, {%4,%5,%6,%7}, {%8,%9}, {%0,%1,%2,%3};"
                 : "+f"(c[0]), "+f"(c[1]), "+f"(c[2]), "+f"(c[3])
                 : "r"(a0), "r"(a1), "r"(a2), "r"(a3), "r"(b0), "r"(b1));
}

// shared epilogue (epi: 0 store, 1 gelu->f16hi, 4 gate-finish)
__device__ __forceinline__ void gemm_epilogue(const B4& b, int epi, int z,
    int bm, int bn, int N, int wm, int wn, int grp, int tg,
    float acc[4][4][4])
{
#pragma unroll
    for (int mi = 0; mi < 4; ++mi) {
#pragma unroll
        for (int ni = 0; ni < 4; ++ni) {
            const int col = bn + wn * 32 + ni * 8 + 2 * tg;
            float bx = 0.f, by = 0.f;
            if (b.bias[z]) { bx = b.bias[z][col]; by = b.bias[z][col + 1]; }
#pragma unroll
            for (int hf = 0; hf < 2; ++hf) {
                const int row = bm + wm * 64 + mi * 16 + grp + hf * 8;
                float v0 = acc[mi][ni][hf * 2 + 0] + bx;
                float v1 = acc[mi][ni][hf * 2 + 1] + by;
                const size_t idx = (size_t)row * N + col;
                if (epi == 0) {
                    *(float2*)(b.C[z] + idx) = make_float2(v0, v1);
                } else if (epi == 1) {
                    float u3;
                    u3 = v0 * v0 * v0;
                    v0 = 0.5f * v0 * (1.f + tanhf(0.7978845608028654f * (v0 + 0.044715f * u3)));
                    u3 = v1 * v1 * v1;
                    v1 = 0.5f * v1 * (1.f + tanhf(0.7978845608028654f * (v1 + 0.044715f * u3)));
                    __half2 hh = __floats2half2_rn(v0, v1);
                    *(__half2*)(b.Ch[z] + idx) = hh;
                } else { // epi == 4
                    float2 gp = *(const float2*)(b.gpre + idx);
                    v0 += gp.x; v1 += gp.y;
                    float s0 = 1.f / (1.f + __expf(-v0));
                    float s1 = 1.f / (1.f + __expf(-v1));
                    float2 xl2 = *(const float2*)(b.xl + idx);
                    float2 xg2 = *(const float2*)(b.xg + idx);
                    v0 = s0 * xl2.x + (1.f - s0) * xg2.x;
                    v1 = s1 * xl2.y + (1.f - s1) * xg2.y;
                    *(float2*)(b.C[z] + idx) = make_float2(v0, v1);
                    __half2 hh = __floats2half2_rn(v0, v1);
                    *(__half2*)(b.xch + idx) = hh;
                }
            }
        }
    }
}

// ===================== multi-pass GEMM (TBK=32): passes in {2,3} ===========
__global__ __launch_bounds__(256, 2) void gemm_tc(
    B4 b, int lda, int ldw, int N, int K, int epi, int passes)
{
    extern __shared__ char smc[];
    const int t   = threadIdx.x;
    const int lid = t & 31;
    const int wid = t >> 5;
    const int wm  = wid & 1;
    const int wn  = wid >> 1;
    const int grp = lid >> 2;
    const int tg  = lid & 3;
    const int bm  = blockIdx.y * TBM;
    const int bn  = blockIdx.x * TBN;
    const int z   = blockIdx.z;

    float acc[4][4][4];
#pragma unroll
    for (int mi = 0; mi < 4; ++mi)
#pragma unroll
        for (int ni = 0; ni < 4; ++ni)
#pragma unroll
            for (int r = 0; r < 4; ++r) acc[mi][ni][r] = 0.f;

    const int nstage = K / TBK;
    const uint32_t sbase = smem_u32(smc);

    const int lr    = lid & 7;
    const int hsel  = (lid >> 3) & 1;
    const int seg2  = (lid >> 4) & 1;

    const __half* pAh = b.Ah[z];
    const __half* pAl = b.Al[z];
    const __half* pWh = b.Wh[z];
    const __half* pWl = b.Wl[z];

    auto ld_stage = [&](int buf, int k0) {
#pragma unroll
        for (int i = 0; i < 8; ++i) {
            const int tile = i >> 1;               // 0:Ahi 1:Alo 2:Whi 3:Wlo
            if (tile == 3 && passes < 3) continue;
            const int rem  = ((i & 1) << 8) + t;   // 0..511
            const int row  = rem >> 2;
            const int chn  = t & 3;
            const __half* src;
            if (tile == 0)      src = pAh + (size_t)(bm + row) * lda + k0 + chn * 8;
            else if (tile == 1) src = pAl + (size_t)(bm + row) * lda + k0 + chn * 8;
            else if (tile == 2) src = pWh + (size_t)(bn + row) * ldw + k0 + chn * 8;
            else                src = pWl + (size_t)(bn + row) * ldw + k0 + chn * 8;
            const uint32_t dst = sbase + buf * STG_BYTES + tile * 8192
                               + row * 64 + ((chn ^ ((row >> 1) & 3)) << 4);
            CP_ASYNC16(dst, src);
        }
    };

    ld_stage(0, 0);   CP_COMMIT();
    ld_stage(1, TBK); CP_COMMIT();

    for (int s = 0; s < nstage; ++s) {
        if (s == nstage - 1) CP_WAIT0(); else CP_WAIT1();
        __syncthreads();
        if (s + 2 < nstage) { ld_stage((s + 2) % 3, (s + 2) * TBK); CP_COMMIT(); }

        const uint32_t stg = sbase + (s % 3) * STG_BYTES;
        const uint32_t a_h = stg, a_l = stg + 8192;
        const uint32_t w_h = stg + 16384, w_l = stg + 24576;

#pragma unroll
        for (int kk = 0; kk < 2; ++kk) {
            uint32_t Bh[4][2], Bl[4][2];
#pragma unroll
            for (int np = 0; np < 2; ++np) {
                const int nr = wn * 32 + np * 16 + seg2 * 8 + lr;
                const int ch = kk * 2 + hsel;
                const uint32_t off = nr * 64 + ((ch ^ ((nr >> 1) & 3)) << 4);
                LDSM_X4(Bh[np*2][0], Bh[np*2][1], Bh[np*2+1][0], Bh[np*2+1][1], w_h + off);
                if (passes == 3)
                    LDSM_X4(Bl[np*2][0], Bl[np*2][1], Bl[np*2+1][0], Bl[np*2+1][1], w_l + off);
            }
            uint32_t Ah[4][4], Al[4][4];
#pragma unroll
            for (int mi = 0; mi < 4; ++mi) {
                const int ar = wm * 64 + mi * 16 + hsel * 8 + lr;
                const int ch = kk * 2 + seg2;
                const uint32_t off = ar * 64 + ((ch ^ ((ar >> 1) & 3)) << 4);
                LDSM_X4(Ah[mi][0], Ah[mi][1], Ah[mi][2], Ah[mi][3], a_h + off);
                LDSM_X4(Al[mi][0], Al[mi][1], Al[mi][2], Al[mi][3], a_l + off);
            }
#pragma unroll
            for (int mi = 0; mi < 4; ++mi)
#pragma unroll
                for (int ni = 0; ni < 4; ++ni)
                    mma_f16(acc[mi][ni], Ah[mi][0], Ah[mi][1], Ah[mi][2], Ah[mi][3],
                            Bh[ni][0], Bh[ni][1]);
#pragma unroll
            for (int mi = 0; mi < 4; ++mi)
#pragma unroll
                for (int ni = 0; ni < 4; ++ni)
                    mma_f16(acc[mi][ni], Al[mi][0], Al[mi][1], Al[mi][2], Al[mi][3],
                            Bh[ni][0], Bh[ni][1]);
            if (passes == 3) {
#pragma unroll
                for (int mi = 0; mi < 4; ++mi)
#pragma unroll
                    for (int ni = 0; ni < 4; ++ni)
                        mma_f16(acc[mi][ni], Ah[mi][0], Ah[mi][1], Ah[mi][2], Ah[mi][3],
                                Bl[ni][0], Bl[ni][1]);
            }
        }
    }

    gemm_epilogue(b, epi, z, bm, bn, N, wm, wn, grp, tg, acc);
}

// ===================== 1-pass GEMM, TBK=64 (hi planes only) ================
// Stage: Ah 128x64 f16 (16KB) + Wh 16KB = 32KB; rows are 128B; swizzle ch^(row&7).
#define TBK1 64
#define STG1_BYTES 32768
#define GEMM1_SMEM (3*STG1_BYTES)

__global__ __launch_bounds__(256, 2) void gemm1(
    B4 b, int lda, int ldw, int N, int K, int epi)
{
    extern __shared__ char smc[];
    const int t   = threadIdx.x;
    const int lid = t & 31;
    const int wid = t >> 5;
    const int wm  = wid & 1;
    const int wn  = wid >> 1;
    const int grp = lid >> 2;
    const int tg  = lid & 3;
    const int bm  = blockIdx.y * TBM;
    const int bn  = blockIdx.x * TBN;
    const int z   = blockIdx.z;

    float acc[4][4][4];
#pragma unroll
    for (int mi = 0; mi < 4; ++mi)
#pragma unroll
        for (int ni = 0; ni < 4; ++ni)
#pragma unroll
            for (int r = 0; r < 4; ++r) acc[mi][ni][r] = 0.f;

    const int nstage = K / TBK1;
    const uint32_t sbase = smem_u32(smc);

    const int lr    = lid & 7;
    const int hsel  = (lid >> 3) & 1;
    const int seg2  = (lid >> 4) & 1;

    const __half* pAh = b.Ah[z];
    const __half* pWh = b.Wh[z];

    auto ld_stage = [&](int buf, int k0) {
#pragma unroll
        for (int i = 0; i < 8; ++i) {
            const int tile = i >> 2;               // 0:A 1:W
            const int f    = (i & 3) * 256 + t;    // 0..1023
            const int row  = f >> 3;
            const int chn  = f & 7;
            const __half* src = tile
                ? pWh + (size_t)(bn + row) * ldw + k0 + chn * 8
                : pAh + (size_t)(bm + row) * lda + k0 + chn * 8;
            const uint32_t dst = sbase + buf * STG1_BYTES + tile * 16384
                               + row * 128 + ((chn ^ (row & 7)) << 4);
            CP_ASYNC16(dst, src);
        }
    };

    ld_stage(0, 0);    CP_COMMIT();
    ld_stage(1, TBK1); CP_COMMIT();

    for (int s = 0; s < nstage; ++s) {
        if (s == nstage - 1) CP_WAIT0(); else CP_WAIT1();
        __syncthreads();
        if (s + 2 < nstage) { ld_stage((s + 2) % 3, (s + 2) * TBK1); CP_COMMIT(); }

        const uint32_t stg = sbase + (s % 3) * STG1_BYTES;
        const uint32_t a_h = stg;
        const uint32_t w_h = stg + 16384;

#pragma unroll
        for (int kk = 0; kk < 4; ++kk) {
            uint32_t Bh[4][2];
#pragma unroll
            for (int np = 0; np < 2; ++np) {
                const int nr = wn * 32 + np * 16 + seg2 * 8 + lr;
                const int ch = kk * 2 + hsel;
                const uint32_t off = nr * 128 + ((ch ^ (nr & 7)) << 4);
                LDSM_X4(Bh[np*2][0], Bh[np*2][1], Bh[np*2+1][0], Bh[np*2+1][1], w_h + off);
            }
            uint32_t Ah[4][4];
#pragma unroll
            for (int mi = 0; mi < 4; ++mi) {
                const int ar = wm * 64 + mi * 16 + hsel * 8 + lr;
                const int ch = kk * 2 + seg2;
                const uint32_t off = ar * 128 + ((ch ^ (ar & 7)) << 4);
                LDSM_X4(Ah[mi][0], Ah[mi][1], Ah[mi][2], Ah[mi][3], a_h + off);
            }
#pragma unroll
            for (int mi = 0; mi < 4; ++mi)
#pragma unroll
                for (int ni = 0; ni < 4; ++ni)
                    mma_f16(acc[mi][ni], Ah[mi][0], Ah[mi][1], Ah[mi][2], Ah[mi][3],
                            Bh[ni][0], Bh[ni][1]);
        }
    }

    gemm_epilogue(b, epi, z, bm, bn, N, wm, wn, grp, tg, acc);
}

// ----------------- fused splitter: f32 -> f16 hi(/lo) ----------------------
struct SplitSeg { const float4* src; uint2* hi; uint2* lo; unsigned n4; };
struct SplitTab { SplitSeg seg[10]; };

__global__ void split_all_kernel(SplitTab tab)
{
    unsigned idx = blockIdx.x * blockDim.x + threadIdx.x;
#pragma unroll
    for (int s = 0; s < 10; ++s) {
        if (idx < tab.seg[s].n4) {
            float4 v = tab.seg[s].src[idx];
            __half2 h0 = __floats2half2_rn(v.x, v.y);
            __half2 h1 = __floats2half2_rn(v.z, v.w);
            tab.seg[s].hi[idx] = make_uint2(*(uint32_t*)&h0, *(uint32_t*)&h1);
            if (tab.seg[s].lo) {
                float2 f0 = __half22float2(h0), f1 = __half22float2(h1);
                __half2 l0 = __floats2half2_rn(v.x - f0.x, v.y - f0.y);
                __half2 l1 = __floats2half2_rn(v.z - f1.x, v.w - f1.y);
                tab.seg[s].lo[idx] = make_uint2(*(uint32_t*)&l0, *(uint32_t*)&l1);
            }
            return;
        }
        idx -= tab.seg[s].n4;
    }
}

// ----------------- sliding-window causal attention (f32x2, hi-only out) ---
__global__ __launch_bounds__(64) void attn_kernel(const float* __restrict__ qkv,
                                                  __half* __restrict__ oh)
{
    const int qt = blockIdx.x;
    const int b  = blockIdx.y;
    const int h  = blockIdx.z;
    const int t  = threadIdx.x;
    const int qi = qt * 64 + t;

    __shared__ __align__(16) float ks[64][64];
    __shared__ __align__(16) float vs[64][64];

    ull q2[32], o2[32];
    {
        const float4* qb = (const float4*)(qkv + ((size_t)(b * SEQ + qi)) * (3 * DIM) + h * HD);
#pragma unroll
        for (int d4 = 0; d4 < 16; ++d4) {
            float4 v = qb[d4];
            q2[2*d4]   = pack2f(v.x * 0.125f, v.y * 0.125f);
            q2[2*d4+1] = pack2f(v.z * 0.125f, v.w * 0.125f);
        }
    }
#pragma unroll
    for (int i = 0; i < 32; ++i) o2[i] = 0ull;
    float m = -1e30f, l = 0.f;

    const int kt0 = (qt >= 8) ? (qt - 8) : 0;
    for (int kt = kt0; kt <= qt; ++kt) {
        const float* kbase = qkv + ((size_t)(b * SEQ + kt * 64)) * (3 * DIM) + DIM + h * HD + t;
        const float* vbase = kbase + DIM;
        for (int r = 0; r < 64; ++r) {
            ks[r][t] = kbase[(size_t)r * (3 * DIM)];
            vs[r][t] = vbase[(size_t)r * (3 * DIM)];
        }
        __syncthreads();

        int jlo = qi - WIN + 1 - kt * 64; if (jlo < 0)  jlo = 0;
        int jhi = qi - kt * 64;           if (jhi > 63) jhi = 63;
        for (int j = jlo; j <= jhi; ++j) {
            const ull* kr2 = (const ull*)ks[j];
            ull a0 = 0ull, a1 = 0ull, a2 = 0ull, a3 = 0ull;
#pragma unroll
            for (int i = 0; i < 32; i += 4) {
                ffma2(a0, q2[i],   kr2[i]);
                ffma2(a1, q2[i+1], kr2[i+1]);
                ffma2(a2, q2[i+2], kr2[i+2]);
                ffma2(a3, q2[i+3], kr2[i+3]);
            }
            float2 f0 = unpack2f(a0), f1 = unpack2f(a1);
            float2 f2 = unpack2f(a2), f3 = unpack2f(a3);
            float s = ((f0.x + f0.y) + (f1.x + f1.y)) + ((f2.x + f2.y) + (f3.x + f3.y));
            const ull* vr2 = (const ull*)vs[j];
            if (s <= m) {
                float p = __expf(s - m);
                l += p;
                ull p2 = pack2f(p, p);
#pragma unroll
                for (int i = 0; i < 32; ++i) ffma2(o2[i], p2, vr2[i]);
            } else {
                float al = __expf(m - s);
                m = s; l = l * al + 1.f;
                ull al2 = pack2f(al, al);
#pragma unroll
                for (int i = 0; i < 32; ++i) ffma2b(o2[i], al2, vr2[i]);
            }
        }
        __syncthreads();
    }

    const float inv = 1.f / l;
    const size_t ob = ((size_t)(b * SEQ + qi)) * DIM + h * HD;
#pragma unroll
    for (int i = 0; i < 32; i += 2) {
        float2 p0 = unpack2f(o2[i]), p1 = unpack2f(o2[i+1]);
        __half2 h0 = __floats2half2_rn(p0.x * inv, p0.y * inv);
        __half2 h1 = __floats2half2_rn(p1.x * inv, p1.y * inv);
        *(uint2*)(oh + ob + 2*i) = make_uint2(*(uint32_t*)&h0, *(uint32_t*)&h1);
    }
}

// ----------------- fused residual-add + LayerNorm (+hi split out) ---------
__global__ __launch_bounds__(256) void add_ln_kernel(const float* __restrict__ x,
    const float* __restrict__ r, const float* __restrict__ gg,
    const float* __restrict__ bb, float* __restrict__ y,
    __half* __restrict__ yh)
{
    const int row = blockIdx.x;
    const int t = threadIdx.x;
    __shared__ float red[8];
    __shared__ float bc0, bc1;

    const float* xr = x + (size_t)row * DIM;
    const float* rr = r + (size_t)row * DIM;
    float v[3]; float s = 0.f;
#pragma unroll
    for (int i = 0; i < 3; ++i) { int c = t + i * 256; v[i] = xr[c] + rr[c]; s += v[i]; }
#pragma unroll
    for (int off = 16; off; off >>= 1) s += __shfl_xor_sync(0xffffffffu, s, off);
    if ((t & 31) == 0) red[t >> 5] = s;
    __syncthreads();
    if (t == 0) { float tot = 0.f;
#pragma unroll
        for (int w = 0; w < 8; ++w) tot += red[w];
        bc0 = tot * (1.f / DIM);
    }
    __syncthreads();
    const float mean = bc0;
    float sq = 0.f;
#pragma unroll
    for (int i = 0; i < 3; ++i) { float d = v[i] - mean; sq += d * d; }
#pragma unroll
    for (int off = 16; off; off >>= 1) sq += __shfl_xor_sync(0xffffffffu, sq, off);
    if ((t & 31) == 0) red[t >> 5] = sq;
    __syncthreads();
    if (t == 0) { float tot = 0.f;
#pragma unroll
        for (int w = 0; w < 8; ++w) tot += red[w];
        bc1 = rsqrtf(tot * (1.f / DIM) + 1e-5f);
    }
    __syncthreads();
    const float rstd = bc1;
#pragma unroll
    for (int i = 0; i < 3; ++i) {
        int c = t + i * 256;
        float val = (v[i] - mean) * rstd * gg[c] + bb[c];
        y[(size_t)row * DIM + c] = val;
        yh[(size_t)row * DIM + c] = __float2half_rn(val);
    }
}

// ----------------- final LN with 4-way CMS mean ----------------------------
__global__ __launch_bounds__(256) void ln_final_kernel(const float* __restrict__ xc,
    const float* __restrict__ c0, const float* __restrict__ c1,
    const float* __restrict__ c2, const float* __restrict__ c3,
    const float* __restrict__ gg, const float* __restrict__ bb,
    float* __restrict__ y)
{
    const int row = blockIdx.x;
    const int t = threadIdx.x;
    __shared__ float red[8];
    __shared__ float bc0, bc1;

    const size_t rb = (size_t)row * DIM;
    float v[3]; float s = 0.f;
#pragma unroll
    for (int i = 0; i < 3; ++i) {
        int c = t + i * 256;
        v[i] = xc[rb + c] + 0.25f * (c0[rb + c] + c1[rb + c] + c2[rb + c] + c3[rb + c]);
        s += v[i];
    }
#pragma unroll
    for (int off = 16; off; off >>= 1) s += __shfl_xor_sync(0xffffffffu, s, off);
    if ((t & 31) == 0) red[t >> 5] = s;
    __syncthreads();
    if (t == 0) { float tot = 0.f;
#pragma unroll
        for (int w = 0; w < 8; ++w) tot += red[w];
        bc0 = tot * (1.f / DIM);
    }
    __syncthreads();
    const float mean = bc0;
    float sq = 0.f;
#pragma unroll
    for (int i = 0; i < 3; ++i) { float d = v[i] - mean; sq += d * d; }
#pragma unroll
    for (int off = 16; off; off >>= 1) sq += __shfl_xor_sync(0xffffffffu, sq, off);
    if ((t & 31) == 0) red[t >> 5] = sq;
    __syncthreads();
    if (t == 0) { float tot = 0.f;
#pragma unroll
        for (int w = 0; w < 8; ++w) tot += red[w];
        bc1 = rsqrtf(tot * (1.f / DIM) + 1e-5f);
    }
    __syncthreads();
    const float rstd = bc1;
#pragma unroll
    for (int i = 0; i < 3; ++i) {
        int c = t + i * 256;
        y[rb + c] = (v[i] - mean) * rstd * gg[c] + bb[c];
    }
}

// ----------------- delta-rule scan: 1 barrier/step + warp shuffles --------
__global__ __launch_bounds__(256) void delta_scan_kernel(const float* __restrict__ tq,
    const float* __restrict__ tk, const float* __restrict__ tv,
    __half* __restrict__ toh, float* __restrict__ Mout)
{
    const int bh = blockIdx.x;
    const int b = bh / NH, h = bh % NH;
    const int t = threadIdx.x;
    const int lane = t & 31;
    const int w = t >> 5;
    const int e = w * 8 + (lane & 7);
    const int g = lane >> 3;

    __shared__ __align__(8) float kb[2][64], vb[2][64], qb[2][64];

    ull M2[8];
#pragma unroll
    for (int i = 0; i < 8; ++i) M2[i] = 0ull;

    const int grp3 = t >> 6;
    const size_t sbase = ((size_t)b * SEQ) * DIM + h * HD + (t & 63);
    float nxt = 0.f;
    if (grp3 == 0) nxt = tk[sbase];
    else if (grp3 == 1) nxt = tv[sbase];
    else if (grp3 == 2) nxt = tq[sbase];

    const size_t obase = ((size_t)b * SEQ) * DIM + h * HD + e;

    for (int s = 0; s < SEQ; ++s) {
        const int p = s & 1;
        if (grp3 == 0) kb[p][t & 63] = nxt;
        else if (grp3 == 1) vb[p][t & 63] = nxt;
        else if (grp3 == 2) qb[p][t & 63] = nxt;
        __syncthreads();
        if (s + 1 < SEQ) {
            const size_t nb = sbase + (size_t)(s + 1) * DIM;
            if (grp3 == 0) nxt = tk[nb];
            else if (grp3 == 1) nxt = tv[nb];
            else if (grp3 == 2) nxt = tq[nb];
        }
        ull k2[8];
        ull pa = 0ull, pb = 0ull;
        const ull* kp = (const ull*)&kb[p][g * 16];
#pragma unroll
        for (int i = 0; i < 8; i += 2) {
            k2[i] = kp[i]; k2[i+1] = kp[i+1];
            ffma2(pa, M2[i], k2[i]);
            ffma2(pb, M2[i+1], k2[i+1]);
        }
        float2 pf = unpack2f(pa), pg2 = unpack2f(pb);
        float pp = (pf.x + pf.y) + (pg2.x + pg2.y);
        float r1 = pp + __shfl_xor_sync(0xffffffffu, pp, 8);
        const float pred = r1 + __shfl_xor_sync(0xffffffffu, r1, 16);
        const float delta = LRATE * (vb[p][e] - pred);
        const ull d2 = pack2f(delta, delta);
        const ull* qp = (const ull*)&qb[p][g * 16];
        ull oa = 0ull, ob2 = 0ull;
#pragma unroll
        for (int i = 0; i < 8; i += 2) {
            ffma2(M2[i], k2[i], d2);     ffma2(oa, M2[i], qp[i]);
            ffma2(M2[i+1], k2[i+1], d2); ffma2(ob2, M2[i+1], qp[i+1]);
        }
        float2 of = unpack2f(oa), og = unpack2f(ob2);
        float oo = (of.x + of.y) + (og.x + og.y);
        float r2 = oo + __shfl_xor_sync(0xffffffffu, oo, 8);
        float ov = r2 + __shfl_xor_sync(0xffffffffu, r2, 16);
        if (g == 0)
            toh[obase + (size_t)s * DIM] = __float2half_rn(ov);
    }
    if (Mout) {
#pragma unroll
        for (int i = 0; i < 8; ++i) {
            float2 mv = unpack2f(M2[i]);
            Mout[(((size_t)b * NH + h) * HD + (g * 16 + 2*i))     * HD + e] = mv.x;
            Mout[(((size_t)b * NH + h) * HD + (g * 16 + 2*i + 1)) * HD + e] = mv.y;
        }
    }
}

// ----------------- launch ---------------------------------------------------
static void* symp(const void* s) {
    void* p = nullptr;
    cudaGetSymbolAddress(&p, s);
    return p;
}

extern "C" void kernel_launch(void* const* d_in, const int* in_sizes, int n_in,
                              void* d_out, int out_size)
{
    const float* x          = (const float*)d_in[0];
    const float* in_proj_w  = (const float*)d_in[1];
    const float* in_proj_b  = (const float*)d_in[2];
    const float* out_proj_w = (const float*)d_in[3];
    const float* out_proj_b = (const float*)d_in[4];
    const float* ln_local_g = (const float*)d_in[5];
    const float* ln_local_b = (const float*)d_in[6];
    const float* t_wq       = (const float*)d_in[7];
    const float* t_wk       = (const float*)d_in[8];
    const float* t_wv       = (const float*)d_in[9];
    const float* t_wo       = (const float*)d_in[10];
    const float* ln_tit_g   = (const float*)d_in[11];
    const float* ln_tit_b   = (const float*)d_in[12];
    const float* gate_w     = (const float*)d_in[13];
    const float* gate_b     = (const float*)d_in[14];
    const float* cms_w1     = (const float*)d_in[15];
    const float* cms_b1     = (const float*)d_in[16];
    const float* cms_w2     = (const float*)d_in[17];
    const float* cms_b2     = (const float*)d_in[18];
    const float* ln_cms_g   = (const float*)d_in[19];
    const float* ln_cms_b   = (const float*)d_in[20];

    float* qkv    = (float*)symp(g_qkv);
    float* proj   = (float*)symp(g_proj);
    float* proj2  = (float*)symp(g_proj2);
    float* xlocal = (float*)symp(g_xlocal);
    float* xglob  = (float*)symp(g_xglobal);
    float* tq     = (float*)symp(g_tq);
    float* tk     = (float*)symp(g_tk);
    float* tv     = (float*)symp(g_tv);
    float* gpre   = (float*)symp(g_gpre);
    float* xc     = (float*)symp(g_xc);
    float* cmsb   = (float*)symp(g_cms);

    __half* x_h   = (__half*)symp(g_x_h);   __half* x_l   = (__half*)symp(g_x_l);
    __half* wi_h  = (__half*)symp(g_wi_h);  __half* wi_l  = (__half*)symp(g_wi_l);
    __half* wo_h  = (__half*)symp(g_wo_h);
    __half* wtq_h = (__half*)symp(g_wtq_h); __half* wtq_l = (__half*)symp(g_wtq_l);
    __half* wtk_h = (__half*)symp(g_wtk_h); __half* wtk_l = (__half*)symp(g_wtk_l);
    __half* wtv_h = (__half*)symp(g_wtv_h); __half* wtv_l = (__half*)symp(g_wtv_l);
    __half* wto_h = (__half*)symp(g_wto_h);
    __half* wg_h  = (__half*)symp(g_wg_h);
    __half* wc1_h = (__half*)symp(g_wc1_h);
    __half* wc2_h = (__half*)symp(g_wc2_h);
    __half* att_h = (__half*)symp(g_att_h);
    __half* to_h  = (__half*)symp(g_to_h);
    __half* xl_h  = (__half*)symp(g_xl_h);
    __half* xg_h  = (__half*)symp(g_xg_h);
    __half* xc_h  = (__half*)symp(g_xc_h);
    __half* hb_h  = (__half*)symp(g_hb_h);

    float* out = (float*)d_out;
    float* mout = (out_size >= ROWS * DIM + BATCH * NH * HD * HD)
                      ? out + (size_t)ROWS * DIM : nullptr;

    static cudaStream_t s2 = nullptr;
    static cudaEvent_t ev_fork = nullptr, ev_join = nullptr;
    if (!s2) {
        cudaFuncSetAttribute(gemm_tc, cudaFuncAttributeMaxDynamicSharedMemorySize, GEMM_SMEM);
        cudaFuncSetAttribute(gemm1, cudaFuncAttributeMaxDynamicSharedMemorySize, GEMM1_SMEM);
        cudaStreamCreateWithFlags(&s2, cudaStreamNonBlocking);
        cudaEventCreateWithFlags(&ev_fork, cudaEventDisableTiming);
        cudaEventCreateWithFlags(&ev_join, cudaEventDisableTiming);
    }

    // [0] single fused split of all f32 operands
    {
        SplitTab tab{};
        unsigned tot4 = 0;
        auto add = [&](int i, const float* s, __half* h, __half* l, size_t n) {
            tab.seg[i] = SplitSeg{ (const float4*)s, (uint2*)h, (uint2*)l, (unsigned)(n / 4) };
            tot4 += (unsigned)(n / 4);
        };
        add(0, x, x_h, x_l, (size_t)ROWS * DIM);
        add(1, t_wq, wtq_h, wtq_l, (size_t)DIM * DIM);
        add(2, t_wk, wtk_h, wtk_l, (size_t)DIM * DIM);
        add(3, t_wv, wtv_h, wtv_l, (size_t)DIM * DIM);
        add(4, t_wo, wto_h, nullptr, (size_t)DIM * DIM);
        add(5, in_proj_w, wi_h, wi_l, (size_t)3 * DIM * DIM);
        add(6, out_proj_w, wo_h, nullptr, (size_t)DIM * DIM);
        add(7, gate_w, wg_h, nullptr, (size_t)2 * DIM * DIM);
        add(8, cms_w1, wc1_h, nullptr, (size_t)16 * DIM * DIM);
        add(9, cms_w2, wc2_h, nullptr, (size_t)16 * DIM * DIM);
        split_all_kernel<<<(tot4 + 255) / 256, 256>>>(tab);
    }

    cudaEventRecord(ev_fork, 0);
    cudaStreamWaitEvent(s2, ev_fork, 0);

    B4 b{};

    // [s2] Titans projections (z-batched x3) — FULL 3-pass (feeds the scan)
    b = B4{};
    b.Ah[0] = x_h; b.Al[0] = x_l; b.Wh[0] = wtq_h; b.Wl[0] = wtq_l; b.C[0] = tq;
    b.Ah[1] = x_h; b.Al[1] = x_l; b.Wh[1] = wtk_h; b.Wl[1] = wtk_l; b.C[1] = tk;
    b.Ah[2] = x_h; b.Al[2] = x_l; b.Wh[2] = wtv_h; b.Wl[2] = wtv_l; b.C[2] = tv;
    gemm_tc<<<dim3(DIM / TBN, ROWS / TBM, 3), 256, GEMM_SMEM, s2>>>(b, DIM, DIM, DIM, DIM, 0, 3);

    // [s2] delta-rule scan (hi-only output + memory_state)
    delta_scan_kernel<<<BATCH * NH, 256, 0, s2>>>(tq, tk, tv, to_h, mout);

    // [s2] titans out proj (1-pass TBK=64) + residual LN -> x_global (+hi split)
    b = B4{};
    b.Ah[0] = to_h; b.Wh[0] = wto_h; b.C[0] = proj2;
    gemm1<<<dim3(DIM / TBN, ROWS / TBM, 1), 256, GEMM1_SMEM, s2>>>(b, DIM, DIM, DIM, DIM, 0);
    add_ln_kernel<<<ROWS, 256, 0, s2>>>(x, proj2, ln_tit_g, ln_tit_b, xglob, xg_h);
    cudaEventRecord(ev_join, s2);

    // [0] packed QKV projection (2-pass)
    b = B4{};
    b.Ah[0] = x_h; b.Al[0] = x_l; b.Wh[0] = wi_h;
    b.bias[0] = in_proj_b; b.C[0] = qkv;
    gemm_tc<<<dim3(3 * DIM / TBN, ROWS / TBM, 1), 256, GEMM_SMEM>>>(b, DIM, DIM, 3 * DIM, DIM, 0, 2);

    // [0] sliding-window attention -> att (hi only)
    attn_kernel<<<dim3(SEQ / 64, BATCH, NH), 64>>>(qkv, att_h);

    // [0] out_proj (1-pass TBK=64) + residual LN -> x_local (+hi split)
    b = B4{};
    b.Ah[0] = att_h; b.Wh[0] = wo_h;
    b.bias[0] = out_proj_b; b.C[0] = proj;
    gemm1<<<dim3(DIM / TBN, ROWS / TBM, 1), 256, GEMM1_SMEM>>>(b, DIM, DIM, DIM, DIM, 0);
    add_ln_kernel<<<ROWS, 256>>>(x, proj, ln_local_g, ln_local_b, xlocal, xl_h);

    // [0] gate pre-pass (1-pass): gpre = xlocal @ Wg1^T + gate_b (overlaps s2 scan)
    b = B4{};
    b.Ah[0] = xl_h; b.Wh[0] = wg_h;
    b.bias[0] = gate_b; b.C[0] = gpre;
    gemm1<<<dim3(DIM / TBN, ROWS / TBM, 1), 256, GEMM1_SMEM>>>(b, DIM, 2 * DIM, DIM, DIM, 0);

    // ---- join ----
    cudaStreamWaitEvent(0, ev_join, 0);

    // [0] gate finish (1-pass): logits = gpre + xglob @ Wg2^T -> sigmoid-combine
    b = B4{};
    b.Ah[0] = xg_h; b.Wh[0] = wg_h + DIM;
    b.C[0] = xc;
    b.xl = xlocal; b.xg = xglob; b.gpre = gpre; b.xch = xc_h;
    gemm1<<<dim3(DIM / TBN, ROWS / TBM, 1), 256, GEMM1_SMEM>>>(b, DIM, 2 * DIM, DIM, DIM, 4);

    // [0] CMS: w1 x4 (gelu, hi-only output, 1-pass), z-batched
    b = B4{};
    for (int l = 0; l < 4; ++l) {
        b.Ah[l] = xc_h;
        b.Wh[l] = wc1_h + (size_t)l * 4 * DIM * DIM;
        b.bias[l] = cms_b1 + (size_t)l * 4 * DIM;
        b.Ch[l] = hb_h + (size_t)l * ROWS * 4 * DIM;
    }
    gemm1<<<dim3(4 * DIM / TBN, ROWS / TBM, 4), 256, GEMM1_SMEM>>>(b, DIM, DIM, 4 * DIM, DIM, 1);

    // [0] CMS: w2 x4 (1-pass), z-batched, per-level f32 outputs
    b = B4{};
    for (int l = 0; l < 4; ++l) {
        b.Ah[l] = hb_h + (size_t)l * ROWS * 4 * DIM;
        b.Wh[l] = wc2_h + (size_t)l * 4 * DIM * DIM;
        b.bias[l] = cms_b2 + (size_t)l * DIM;
        b.C[l] = cmsb + (size_t)l * ROWS * DIM;
    }
    gemm1<<<dim3(DIM / TBN, ROWS / TBM, 4), 256, GEMM1_SMEM>>>(b, 4 * DIM, 4 * DIM, DIM, 4 * DIM, 0);

    // [0] final LN
    ln_final_kernel<<<ROWS, 256>>>(xc, cmsb, cmsb + (size_t)ROWS * DIM,
                                   cmsb + 2 * (size_t)ROWS * DIM, cmsb + 3 * (size_t)ROWS * DIM,
                                   ln_cms_g, ln_cms_b, out);
}

// round 15
// speedup vs baseline: 1.5380x; 1.0365x over previous
#include <cuda_runtime.h>
#include <cuda_fp16.h>
#include <math.h>
#include <stdint.h>

#define SEQ   2048
#define BATCH 2
#define DIM   768
#define NH    12
#define HD    64
#define WIN   512
#define ROWS  (BATCH*SEQ)     // 4096
#define LRATE 0.1f

typedef unsigned long long ull;

// ----------------- device scratch (no cudaMalloc allowed) -----------------
__device__ float g_qkv[ROWS*3*DIM];
__device__ float g_proj[ROWS*DIM];
__device__ float g_proj2[ROWS*DIM];
__device__ float g_xlocal[ROWS*DIM];
__device__ float g_xglobal[ROWS*DIM];
__device__ float g_tq[ROWS*DIM];
__device__ float g_tk[ROWS*DIM];
__device__ float g_tv[ROWS*DIM];
__device__ float g_gpre[ROWS*DIM];
__device__ float g_xc[ROWS*DIM];
__device__ float g_cms[4*(size_t)ROWS*DIM];

// f16 planes for GEMM operands (lo planes only where needed)
__device__ __half g_x_h[ROWS*DIM],     g_x_l[ROWS*DIM];
__device__ __half g_wi_h[3*DIM*DIM],   g_wi_l[3*DIM*DIM];
__device__ __half g_wo_h[DIM*DIM];
__device__ __half g_wtq_h[DIM*DIM],    g_wtq_l[DIM*DIM];
__device__ __half g_wtk_h[DIM*DIM],    g_wtk_l[DIM*DIM];
__device__ __half g_wtv_h[DIM*DIM],    g_wtv_l[DIM*DIM];
__device__ __half g_wto_h[DIM*DIM];
__device__ __half g_wg_h[2*DIM*DIM];
__device__ __half g_wc1_h[4*4*DIM*DIM];
__device__ __half g_wc2_h[4*4*DIM*DIM];
__device__ __half g_att_h[ROWS*DIM];
__device__ __half g_to_h[ROWS*DIM];
__device__ __half g_xl_h[ROWS*DIM];
__device__ __half g_xg_h[ROWS*DIM];
__device__ __half g_xc_h[ROWS*DIM];
__device__ __half g_hb_h[4*(size_t)ROWS*4*DIM];

// ----------------- f32x2 packed helpers ------------------------------------
__device__ __forceinline__ void ffma2(ull& d, ull a, ull b) {      // d += a*b
    asm("fma.rn.f32x2 %0, %1, %2, %0;" : "+l"(d) : "l"(a), "l"(b));
}
__device__ __forceinline__ void ffma2b(ull& d, ull a, ull b) {     // d = d*a + b
    asm("fma.rn.f32x2 %0, %0, %1, %2;" : "+l"(d) : "l"(a), "l"(b));
}
__device__ __forceinline__ ull pack2f(float x, float y) {
    ull r; asm("mov.b64 %0, {%1, %2};" : "=l"(r) : "f"(x), "f"(y)); return r;
}
__device__ __forceinline__ float2 unpack2f(ull v) {
    float x, y; asm("mov.b64 {%0, %1}, %2;" : "=f"(x), "=f"(y) : "l"(v));
    return make_float2(x, y);
}
// fast gelu: 0.5*v*(1+tanh(z)) == v * sigmoid(2z), 2z = 1.5957691*v + 0.0713548*v^3
__device__ __forceinline__ float fast_gelu(float v) {
    float arg = v * fmaf(0.0713548162f, v * v, 1.5957691216f);
    return __fdividef(v, 1.f + __expf(-arg));
}

// ===================== shared GEMM infrastructure ==========================
#define TBM 128
#define TBN 128
#define TBK 32
#define STG_BYTES 32768
#define GEMM_SMEM (3*STG_BYTES)          // 98304 -> 2 blocks/SM

#define CP_ASYNC16(dst, src) \
    asm volatile("cp.async.cg.shared.global [%0], [%1], 16;" :: "r"(dst), "l"(src))
#define CP_COMMIT() asm volatile("cp.async.commit_group;")
#define CP_WAIT1()  asm volatile("cp.async.wait_group 1;" ::: "memory")
#define CP_WAIT0()  asm volatile("cp.async.wait_group 0;" ::: "memory")
#define LDSM_X4(r0,r1,r2,r3,addr) \
    asm volatile("ldmatrix.sync.aligned.m8n8.x4.shared.b16 {%0,%1,%2,%3}, [%4];" \
        : "=r"(r0),"=r"(r1),"=r"(r2),"=r"(r3) : "r"(addr))

struct B4 {
    const __half *Ah[4], *Al[4], *Wh[4], *Wl[4];
    const float* bias[4];
    float* C[4];
    __half *Ch[4], *Cl[4];
    const float *xl, *xg, *gpre;    // epi==4 operands
    __half *xch;                    // epi==4 split output (hi only)
};

__device__ __forceinline__ uint32_t smem_u32(const void* p) {
    uint32_t a;
    asm("{ .reg .u64 t; cvta.to.shared.u64 t, %1; cvt.u32.u64 %0, t; }" : "=r"(a) : "l"(p));
    return a;
}
__device__ __forceinline__ void mma_f16(float* c, uint32_t a0, uint32_t a1,
                                        uint32_t a2, uint32_t a3,
                                        uint32_t b0, uint32_t b1) {
    asm volatile("mma.sync.aligned.m16n8k16.row.col.f32.f16.f16.f32 "
                 "{%0,%1,%2,%3}, {%4,%5,%6,%7}, {%8,%9}, {%0,%1,%2,%3};"
                 : "+f"(c[0]), "+f"(c[1]), "+f"(c[2]), "+f"(c[3])
                 : "r"(a0), "r"(a1), "r"(a2), "r"(a3), "r"(b0), "r"(b1));
}

// shared epilogue (epi: 0 store, 1 fast-gelu->f16hi, 4 gate-finish)
__device__ __forceinline__ void gemm_epilogue(const B4& b, int epi, int z,
    int bm, int bn, int N, int wm, int wn, int grp, int tg,
    float acc[4][4][4])
{
#pragma unroll
    for (int mi = 0; mi < 4; ++mi) {
#pragma unroll
        for (int ni = 0; ni < 4; ++ni) {
            const int col = bn + wn * 32 + ni * 8 + 2 * tg;
            float bx = 0.f, by = 0.f;
            if (b.bias[z]) { bx = b.bias[z][col]; by = b.bias[z][col + 1]; }
#pragma unroll
            for (int hf = 0; hf < 2; ++hf) {
                const int row = bm + wm * 64 + mi * 16 + grp + hf * 8;
                float v0 = acc[mi][ni][hf * 2 + 0] + bx;
                float v1 = acc[mi][ni][hf * 2 + 1] + by;
                const size_t idx = (size_t)row * N + col;
                if (epi == 0) {
                    *(float2*)(b.C[z] + idx) = make_float2(v0, v1);
                } else if (epi == 1) {
                    v0 = fast_gelu(v0);
                    v1 = fast_gelu(v1);
                    __half2 hh = __floats2half2_rn(v0, v1);
                    *(__half2*)(b.Ch[z] + idx) = hh;
                } else { // epi == 4
                    float2 gp = *(const float2*)(b.gpre + idx);
                    v0 += gp.x; v1 += gp.y;
                    float s0 = __fdividef(1.f, 1.f + __expf(-v0));
                    float s1 = __fdividef(1.f, 1.f + __expf(-v1));
                    float2 xl2 = *(const float2*)(b.xl + idx);
                    float2 xg2 = *(const float2*)(b.xg + idx);
                    v0 = s0 * xl2.x + (1.f - s0) * xg2.x;
                    v1 = s1 * xl2.y + (1.f - s1) * xg2.y;
                    *(float2*)(b.C[z] + idx) = make_float2(v0, v1);
                    __half2 hh = __floats2half2_rn(v0, v1);
                    *(__half2*)(b.xch + idx) = hh;
                }
            }
        }
    }
}

// ===================== multi-pass GEMM (TBK=32): passes in {2,3} ===========
__global__ __launch_bounds__(256, 2) void gemm_tc(
    B4 b, int lda, int ldw, int N, int K, int epi, int passes)
{
    extern __shared__ char smc[];
    const int t   = threadIdx.x;
    const int lid = t & 31;
    const int wid = t >> 5;
    const int wm  = wid & 1;
    const int wn  = wid >> 1;
    const int grp = lid >> 2;
    const int tg  = lid & 3;
    const int bm  = blockIdx.y * TBM;
    const int bn  = blockIdx.x * TBN;
    const int z   = blockIdx.z;

    float acc[4][4][4];
#pragma unroll
    for (int mi = 0; mi < 4; ++mi)
#pragma unroll
        for (int ni = 0; ni < 4; ++ni)
#pragma unroll
            for (int r = 0; r < 4; ++r) acc[mi][ni][r] = 0.f;

    const int nstage = K / TBK;
    const uint32_t sbase = smem_u32(smc);

    const int lr    = lid & 7;
    const int hsel  = (lid >> 3) & 1;
    const int seg2  = (lid >> 4) & 1;

    const __half* pAh = b.Ah[z];
    const __half* pAl = b.Al[z];
    const __half* pWh = b.Wh[z];
    const __half* pWl = b.Wl[z];

    auto ld_stage = [&](int buf, int k0) {
#pragma unroll
        for (int i = 0; i < 8; ++i) {
            const int tile = i >> 1;               // 0:Ahi 1:Alo 2:Whi 3:Wlo
            if (tile == 3 && passes < 3) continue;
            const int rem  = ((i & 1) << 8) + t;   // 0..511
            const int row  = rem >> 2;
            const int chn  = t & 3;
            const __half* src;
            if (tile == 0)      src = pAh + (size_t)(bm + row) * lda + k0 + chn * 8;
            else if (tile == 1) src = pAl + (size_t)(bm + row) * lda + k0 + chn * 8;
            else if (tile == 2) src = pWh + (size_t)(bn + row) * ldw + k0 + chn * 8;
            else                src = pWl + (size_t)(bn + row) * ldw + k0 + chn * 8;
            const uint32_t dst = sbase + buf * STG_BYTES + tile * 8192
                               + row * 64 + ((chn ^ ((row >> 1) & 3)) << 4);
            CP_ASYNC16(dst, src);
        }
    };

    ld_stage(0, 0);   CP_COMMIT();
    ld_stage(1, TBK); CP_COMMIT();

    for (int s = 0; s < nstage; ++s) {
        if (s == nstage - 1) CP_WAIT0(); else CP_WAIT1();
        __syncthreads();
        if (s + 2 < nstage) { ld_stage((s + 2) % 3, (s + 2) * TBK); CP_COMMIT(); }

        const uint32_t stg = sbase + (s % 3) * STG_BYTES;
        const uint32_t a_h = stg, a_l = stg + 8192;
        const uint32_t w_h = stg + 16384, w_l = stg + 24576;

#pragma unroll
        for (int kk = 0; kk < 2; ++kk) {
            uint32_t Bh[4][2], Bl[4][2];
#pragma unroll
            for (int np = 0; np < 2; ++np) {
                const int nr = wn * 32 + np * 16 + seg2 * 8 + lr;
                const int ch = kk * 2 + hsel;
                const uint32_t off = nr * 64 + ((ch ^ ((nr >> 1) & 3)) << 4);
                LDSM_X4(Bh[np*2][0], Bh[np*2][1], Bh[np*2+1][0], Bh[np*2+1][1], w_h + off);
                if (passes == 3)
                    LDSM_X4(Bl[np*2][0], Bl[np*2][1], Bl[np*2+1][0], Bl[np*2+1][1], w_l + off);
            }
            uint32_t Ah[4][4], Al[4][4];
#pragma unroll
            for (int mi = 0; mi < 4; ++mi) {
                const int ar = wm * 64 + mi * 16 + hsel * 8 + lr;
                const int ch = kk * 2 + seg2;
                const uint32_t off = ar * 64 + ((ch ^ ((ar >> 1) & 3)) << 4);
                LDSM_X4(Ah[mi][0], Ah[mi][1], Ah[mi][2], Ah[mi][3], a_h + off);
                LDSM_X4(Al[mi][0], Al[mi][1], Al[mi][2], Al[mi][3], a_l + off);
            }
#pragma unroll
            for (int mi = 0; mi < 4; ++mi)
#pragma unroll
                for (int ni = 0; ni < 4; ++ni)
                    mma_f16(acc[mi][ni], Ah[mi][0], Ah[mi][1], Ah[mi][2], Ah[mi][3],
                            Bh[ni][0], Bh[ni][1]);
#pragma unroll
            for (int mi = 0; mi < 4; ++mi)
#pragma unroll
                for (int ni = 0; ni < 4; ++ni)
                    mma_f16(acc[mi][ni], Al[mi][0], Al[mi][1], Al[mi][2], Al[mi][3],
                            Bh[ni][0], Bh[ni][1]);
            if (passes == 3) {
#pragma unroll
                for (int mi = 0; mi < 4; ++mi)
#pragma unroll
                    for (int ni = 0; ni < 4; ++ni)
                        mma_f16(acc[mi][ni], Ah[mi][0], Ah[mi][1], Ah[mi][2], Ah[mi][3],
                                Bl[ni][0], Bl[ni][1]);
            }
        }
    }

    gemm_epilogue(b, epi, z, bm, bn, N, wm, wn, grp, tg, acc);
}

// ===================== 1-pass GEMM, TBK=64 (hi planes only) ================
#define TBK1 64
#define STG1_BYTES 32768
#define GEMM1_SMEM (3*STG1_BYTES)

__global__ __launch_bounds__(256, 2) void gemm1(
    B4 b, int lda, int ldw, int N, int K, int epi)
{
    extern __shared__ char smc[];
    const int t   = threadIdx.x;
    const int lid = t & 31;
    const int wid = t >> 5;
    const int wm  = wid & 1;
    const int wn  = wid >> 1;
    const int grp = lid >> 2;
    const int tg  = lid & 3;
    const int bm  = blockIdx.y * TBM;
    const int bn  = blockIdx.x * TBN;
    const int z   = blockIdx.z;

    float acc[4][4][4];
#pragma unroll
    for (int mi = 0; mi < 4; ++mi)
#pragma unroll
        for (int ni = 0; ni < 4; ++ni)
#pragma unroll
            for (int r = 0; r < 4; ++r) acc[mi][ni][r] = 0.f;

    const int nstage = K / TBK1;
    const uint32_t sbase = smem_u32(smc);

    const int lr    = lid & 7;
    const int hsel  = (lid >> 3) & 1;
    const int seg2  = (lid >> 4) & 1;

    const __half* pAh = b.Ah[z];
    const __half* pWh = b.Wh[z];

    auto ld_stage = [&](int buf, int k0) {
#pragma unroll
        for (int i = 0; i < 8; ++i) {
            const int tile = i >> 2;               // 0:A 1:W
            const int f    = (i & 3) * 256 + t;    // 0..1023
            const int row  = f >> 3;
            const int chn  = f & 7;
            const __half* src = tile
                ? pWh + (size_t)(bn + row) * ldw + k0 + chn * 8
                : pAh + (size_t)(bm + row) * lda + k0 + chn * 8;
            const uint32_t dst = sbase + buf * STG1_BYTES + tile * 16384
                               + row * 128 + ((chn ^ (row & 7)) << 4);
            CP_ASYNC16(dst, src);
        }
    };

    ld_stage(0, 0);    CP_COMMIT();
    ld_stage(1, TBK1); CP_COMMIT();

    for (int s = 0; s < nstage; ++s) {
        if (s == nstage - 1) CP_WAIT0(); else CP_WAIT1();
        __syncthreads();
        if (s + 2 < nstage) { ld_stage((s + 2) % 3, (s + 2) * TBK1); CP_COMMIT(); }

        const uint32_t stg = sbase + (s % 3) * STG1_BYTES;
        const uint32_t a_h = stg;
        const uint32_t w_h = stg + 16384;

#pragma unroll
        for (int kk = 0; kk < 4; ++kk) {
            uint32_t Bh[4][2];
#pragma unroll
            for (int np = 0; np < 2; ++np) {
                const int nr = wn * 32 + np * 16 + seg2 * 8 + lr;
                const int ch = kk * 2 + hsel;
                const uint32_t off = nr * 128 + ((ch ^ (nr & 7)) << 4);
                LDSM_X4(Bh[np*2][0], Bh[np*2][1], Bh[np*2+1][0], Bh[np*2+1][1], w_h + off);
            }
            uint32_t Ah[4][4];
#pragma unroll
            for (int mi = 0; mi < 4; ++mi) {
                const int ar = wm * 64 + mi * 16 + hsel * 8 + lr;
                const int ch = kk * 2 + seg2;
                const uint32_t off = ar * 128 + ((ch ^ (ar & 7)) << 4);
                LDSM_X4(Ah[mi][0], Ah[mi][1], Ah[mi][2], Ah[mi][3], a_h + off);
            }
#pragma unroll
            for (int mi = 0; mi < 4; ++mi)
#pragma unroll
                for (int ni = 0; ni < 4; ++ni)
                    mma_f16(acc[mi][ni], Ah[mi][0], Ah[mi][1], Ah[mi][2], Ah[mi][3],
                            Bh[ni][0], Bh[ni][1]);
        }
    }

    gemm_epilogue(b, epi, z, bm, bn, N, wm, wn, grp, tg, acc);
}

// ----------------- fused splitter: f32 -> f16 hi(/lo) ----------------------
struct SplitSeg { const float4* src; uint2* hi; uint2* lo; unsigned n4; };
struct SplitTab { SplitSeg seg[10]; };

__global__ void split_all_kernel(SplitTab tab)
{
    unsigned idx = blockIdx.x * blockDim.x + threadIdx.x;
#pragma unroll
    for (int s = 0; s < 10; ++s) {
        if (idx < tab.seg[s].n4) {
            float4 v = tab.seg[s].src[idx];
            __half2 h0 = __floats2half2_rn(v.x, v.y);
            __half2 h1 = __floats2half2_rn(v.z, v.w);
            tab.seg[s].hi[idx] = make_uint2(*(uint32_t*)&h0, *(uint32_t*)&h1);
            if (tab.seg[s].lo) {
                float2 f0 = __half22float2(h0), f1 = __half22float2(h1);
                __half2 l0 = __floats2half2_rn(v.x - f0.x, v.y - f0.y);
                __half2 l1 = __floats2half2_rn(v.z - f1.x, v.w - f1.y);
                tab.seg[s].lo[idx] = make_uint2(*(uint32_t*)&l0, *(uint32_t*)&l1);
            }
            return;
        }
        idx -= tab.seg[s].n4;
    }
}

// ----------------- sliding-window causal attention (f32x2, hi-only out) ---
__global__ __launch_bounds__(64) void attn_kernel(const float* __restrict__ qkv,
                                                  __half* __restrict__ oh)
{
    const int qt = blockIdx.x;
    const int b  = blockIdx.y;
    const int h  = blockIdx.z;
    const int t  = threadIdx.x;
    const int qi = qt * 64 + t;

    __shared__ __align__(16) float ks[64][64];
    __shared__ __align__(16) float vs[64][64];

    ull q2[32], o2[32];
    {
        const float4* qb = (const float4*)(qkv + ((size_t)(b * SEQ + qi)) * (3 * DIM) + h * HD);
#pragma unroll
        for (int d4 = 0; d4 < 16; ++d4) {
            float4 v = qb[d4];
            q2[2*d4]   = pack2f(v.x * 0.125f, v.y * 0.125f);
            q2[2*d4+1] = pack2f(v.z * 0.125f, v.w * 0.125f);
        }
    }
#pragma unroll
    for (int i = 0; i < 32; ++i) o2[i] = 0ull;
    float m = -1e30f, l = 0.f;

    const int kt0 = (qt >= 8) ? (qt - 8) : 0;
    for (int kt = kt0; kt <= qt; ++kt) {
        const float* kbase = qkv + ((size_t)(b * SEQ + kt * 64)) * (3 * DIM) + DIM + h * HD + t;
        const float* vbase = kbase + DIM;
        for (int r = 0; r < 64; ++r) {
            ks[r][t] = kbase[(size_t)r * (3 * DIM)];
            vs[r][t] = vbase[(size_t)r * (3 * DIM)];
        }
        __syncthreads();

        int jlo = qi - WIN + 1 - kt * 64; if (jlo < 0)  jlo = 0;
        int jhi = qi - kt * 64;           if (jhi > 63) jhi = 63;
        for (int j = jlo; j <= jhi; ++j) {
            const ull* kr2 = (const ull*)ks[j];
            ull a0 = 0ull, a1 = 0ull, a2 = 0ull, a3 = 0ull;
#pragma unroll
            for (int i = 0; i < 32; i += 4) {
                ffma2(a0, q2[i],   kr2[i]);
                ffma2(a1, q2[i+1], kr2[i+1]);
                ffma2(a2, q2[i+2], kr2[i+2]);
                ffma2(a3, q2[i+3], kr2[i+3]);
            }
            float2 f0 = unpack2f(a0), f1 = unpack2f(a1);
            float2 f2 = unpack2f(a2), f3 = unpack2f(a3);
            float s = ((f0.x + f0.y) + (f1.x + f1.y)) + ((f2.x + f2.y) + (f3.x + f3.y));
            const ull* vr2 = (const ull*)vs[j];
            if (s <= m) {
                float p = __expf(s - m);
                l += p;
                ull p2 = pack2f(p, p);
#pragma unroll
                for (int i = 0; i < 32; ++i) ffma2(o2[i], p2, vr2[i]);
            } else {
                float al = __expf(m - s);
                m = s; l = l * al + 1.f;
                ull al2 = pack2f(al, al);
#pragma unroll
                for (int i = 0; i < 32; ++i) ffma2b(o2[i], al2, vr2[i]);
            }
        }
        __syncthreads();
    }

    const float inv = 1.f / l;
    const size_t ob = ((size_t)(b * SEQ + qi)) * DIM + h * HD;
#pragma unroll
    for (int i = 0; i < 32; i += 2) {
        float2 p0 = unpack2f(o2[i]), p1 = unpack2f(o2[i+1]);
        __half2 h0 = __floats2half2_rn(p0.x * inv, p0.y * inv);
        __half2 h1 = __floats2half2_rn(p1.x * inv, p1.y * inv);
        *(uint2*)(oh + ob + 2*i) = make_uint2(*(uint32_t*)&h0, *(uint32_t*)&h1);
    }
}

// ----------------- fused residual-add + LayerNorm (+hi split out) ---------
__global__ __launch_bounds__(256) void add_ln_kernel(const float* __restrict__ x,
    const float* __restrict__ r, const float* __restrict__ gg,
    const float* __restrict__ bb, float* __restrict__ y,
    __half* __restrict__ yh)
{
    const int row = blockIdx.x;
    const int t = threadIdx.x;
    __shared__ float red[8];
    __shared__ float bc0, bc1;

    const float* xr = x + (size_t)row * DIM;
    const float* rr = r + (size_t)row * DIM;
    float v[3]; float s = 0.f;
#pragma unroll
    for (int i = 0; i < 3; ++i) { int c = t + i * 256; v[i] = xr[c] + rr[c]; s += v[i]; }
#pragma unroll
    for (int off = 16; off; off >>= 1) s += __shfl_xor_sync(0xffffffffu, s, off);
    if ((t & 31) == 0) red[t >> 5] = s;
    __syncthreads();
    if (t == 0) { float tot = 0.f;
#pragma unroll
        for (int w = 0; w < 8; ++w) tot += red[w];
        bc0 = tot * (1.f / DIM);
    }
    __syncthreads();
    const float mean = bc0;
    float sq = 0.f;
#pragma unroll
    for (int i = 0; i < 3; ++i) { float d = v[i] - mean; sq += d * d; }
#pragma unroll
    for (int off = 16; off; off >>= 1) sq += __shfl_xor_sync(0xffffffffu, sq, off);
    if ((t & 31) == 0) red[t >> 5] = sq;
    __syncthreads();
    if (t == 0) { float tot = 0.f;
#pragma unroll
        for (int w = 0; w < 8; ++w) tot += red[w];
        bc1 = rsqrtf(tot * (1.f / DIM) + 1e-5f);
    }
    __syncthreads();
    const float rstd = bc1;
#pragma unroll
    for (int i = 0; i < 3; ++i) {
        int c = t + i * 256;
        float val = (v[i] - mean) * rstd * gg[c] + bb[c];
        y[(size_t)row * DIM + c] = val;
        yh[(size_t)row * DIM + c] = __float2half_rn(val);
    }
}

// ----------------- final LN with 4-way CMS mean ----------------------------
__global__ __launch_bounds__(256) void ln_final_kernel(const float* __restrict__ xc,
    const float* __restrict__ c0, const float* __restrict__ c1,
    const float* __restrict__ c2, const float* __restrict__ c3,
    const float* __restrict__ gg, const float* __restrict__ bb,
    float* __restrict__ y)
{
    const int row = blockIdx.x;
    const int t = threadIdx.x;
    __shared__ float red[8];
    __shared__ float bc0, bc1;

    const size_t rb = (size_t)row * DIM;
    float v[3]; float s = 0.f;
#pragma unroll
    for (int i = 0; i < 3; ++i) {
        int c = t + i * 256;
        v[i] = xc[rb + c] + 0.25f * (c0[rb + c] + c1[rb + c] + c2[rb + c] + c3[rb + c]);
        s += v[i];
    }
#pragma unroll
    for (int off = 16; off; off >>= 1) s += __shfl_xor_sync(0xffffffffu, s, off);
    if ((t & 31) == 0) red[t >> 5] = s;
    __syncthreads();
    if (t == 0) { float tot = 0.f;
#pragma unroll
        for (int w = 0; w < 8; ++w) tot += red[w];
        bc0 = tot * (1.f / DIM);
    }
    __syncthreads();
    const float mean = bc0;
    float sq = 0.f;
#pragma unroll
    for (int i = 0; i < 3; ++i) { float d = v[i] - mean; sq += d * d; }
#pragma unroll
    for (int off = 16; off; off >>= 1) sq += __shfl_xor_sync(0xffffffffu, sq, off);
    if ((t & 31) == 0) red[t >> 5] = sq;
    __syncthreads();
    if (t == 0) { float tot = 0.f;
#pragma unroll
        for (int w = 0; w < 8; ++w) tot += red[w];
        bc1 = rsqrtf(tot * (1.f / DIM) + 1e-5f);
    }
    __syncthreads();
    const float rstd = bc1;
#pragma unroll
    for (int i = 0; i < 3; ++i) {
        int c = t + i * 256;
        y[rb + c] = (v[i] - mean) * rstd * gg[c] + bb[c];
    }
}

// ----------------- delta-rule scan: 1 barrier/step + warp shuffles --------
__global__ __launch_bounds__(256) void delta_scan_kernel(const float* __restrict__ tq,
    const float* __restrict__ tk, const float* __restrict__ tv,
    __half* __restrict__ toh, float* __restrict__ Mout)
{
    const int bh = blockIdx.x;
    const int b = bh / NH, h = bh % NH;
    const int t = threadIdx.x;
    const int lane = t & 31;
    const int w = t >> 5;
    const int e = w * 8 + (lane & 7);
    const int g = lane >> 3;

    __shared__ __align__(8) float kb[2][64], vb[2][64], qb[2][64];

    ull M2[8];
#pragma unroll
    for (int i = 0; i < 8; ++i) M2[i] = 0ull;

    const int grp3 = t >> 6;
    const size_t sbase = ((size_t)b * SEQ) * DIM + h * HD + (t & 63);
    float nxt = 0.f;
    if (grp3 == 0) nxt = tk[sbase];
    else if (grp3 == 1) nxt = tv[sbase];
    else if (grp3 == 2) nxt = tq[sbase];

    const size_t obase = ((size_t)b * SEQ) * DIM + h * HD + e;

    for (int s = 0; s < SEQ; ++s) {
        const int p = s & 1;
        if (grp3 == 0) kb[p][t & 63] = nxt;
        else if (grp3 == 1) vb[p][t & 63] = nxt;
        else if (grp3 == 2) qb[p][t & 63] = nxt;
        __syncthreads();
        if (s + 1 < SEQ) {
            const size_t nb = sbase + (size_t)(s + 1) * DIM;
            if (grp3 == 0) nxt = tk[nb];
            else if (grp3 == 1) nxt = tv[nb];
            else if (grp3 == 2) nxt = tq[nb];
        }
        ull k2[8];
        ull pa = 0ull, pb = 0ull;
        const ull* kp = (const ull*)&kb[p][g * 16];
#pragma unroll
        for (int i = 0; i < 8; i += 2) {
            k2[i] = kp[i]; k2[i+1] = kp[i+1];
            ffma2(pa, M2[i], k2[i]);
            ffma2(pb, M2[i+1], k2[i+1]);
        }
        float2 pf = unpack2f(pa), pg2 = unpack2f(pb);
        float pp = (pf.x + pf.y) + (pg2.x + pg2.y);
        float r1 = pp + __shfl_xor_sync(0xffffffffu, pp, 8);
        const float pred = r1 + __shfl_xor_sync(0xffffffffu, r1, 16);
        const float delta = LRATE * (vb[p][e] - pred);
        const ull d2 = pack2f(delta, delta);
        const ull* qp = (const ull*)&qb[p][g * 16];
        ull oa = 0ull, ob2 = 0ull;
#pragma unroll
        for (int i = 0; i < 8; i += 2) {
            ffma2(M2[i], k2[i], d2);     ffma2(oa, M2[i], qp[i]);
            ffma2(M2[i+1], k2[i+1], d2); ffma2(ob2, M2[i+1], qp[i+1]);
        }
        float2 of = unpack2f(oa), og = unpack2f(ob2);
        float oo = (of.x + of.y) + (og.x + og.y);
        float r2 = oo + __shfl_xor_sync(0xffffffffu, oo, 8);
        float ov = r2 + __shfl_xor_sync(0xffffffffu, r2, 16);
        if (g == 0)
            toh[obase + (size_t)s * DIM] = __float2half_rn(ov);
    }
    if (Mout) {
#pragma unroll
        for (int i = 0; i < 8; ++i) {
            float2 mv = unpack2f(M2[i]);
            Mout[(((size_t)b * NH + h) * HD + (g * 16 + 2*i))     * HD + e] = mv.x;
            Mout[(((size_t)b * NH + h) * HD + (g * 16 + 2*i + 1)) * HD + e] = mv.y;
        }
    }
}

// ----------------- launch ---------------------------------------------------
static void* symp(const void* s) {
    void* p = nullptr;
    cudaGetSymbolAddress(&p, s);
    return p;
}

extern "C" void kernel_launch(void* const* d_in, const int* in_sizes, int n_in,
                              void* d_out, int out_size)
{
    const float* x          = (const float*)d_in[0];
    const float* in_proj_w  = (const float*)d_in[1];
    const float* in_proj_b  = (const float*)d_in[2];
    const float* out_proj_w = (const float*)d_in[3];
    const float* out_proj_b = (const float*)d_in[4];
    const float* ln_local_g = (const float*)d_in[5];
    const float* ln_local_b = (const float*)d_in[6];
    const float* t_wq       = (const float*)d_in[7];
    const float* t_wk       = (const float*)d_in[8];
    const float* t_wv       = (const float*)d_in[9];
    const float* t_wo       = (const float*)d_in[10];
    const float* ln_tit_g   = (const float*)d_in[11];
    const float* ln_tit_b   = (const float*)d_in[12];
    const float* gate_w     = (const float*)d_in[13];
    const float* gate_b     = (const float*)d_in[14];
    const float* cms_w1     = (const float*)d_in[15];
    const float* cms_b1     = (const float*)d_in[16];
    const float* cms_w2     = (const float*)d_in[17];
    const float* cms_b2     = (const float*)d_in[18];
    const float* ln_cms_g   = (const float*)d_in[19];
    const float* ln_cms_b   = (const float*)d_in[20];

    float* qkv    = (float*)symp(g_qkv);
    float* proj   = (float*)symp(g_proj);
    float* proj2  = (float*)symp(g_proj2);
    float* xlocal = (float*)symp(g_xlocal);
    float* xglob  = (float*)symp(g_xglobal);
    float* tq     = (float*)symp(g_tq);
    float* tk     = (float*)symp(g_tk);
    float* tv     = (float*)symp(g_tv);
    float* gpre   = (float*)symp(g_gpre);
    float* xc     = (float*)symp(g_xc);
    float* cmsb   = (float*)symp(g_cms);

    __half* x_h   = (__half*)symp(g_x_h);   __half* x_l   = (__half*)symp(g_x_l);
    __half* wi_h  = (__half*)symp(g_wi_h);  __half* wi_l  = (__half*)symp(g_wi_l);
    __half* wo_h  = (__half*)symp(g_wo_h);
    __half* wtq_h = (__half*)symp(g_wtq_h); __half* wtq_l = (__half*)symp(g_wtq_l);
    __half* wtk_h = (__half*)symp(g_wtk_h); __half* wtk_l = (__half*)symp(g_wtk_l);
    __half* wtv_h = (__half*)symp(g_wtv_h); __half* wtv_l = (__half*)symp(g_wtv_l);
    __half* wto_h = (__half*)symp(g_wto_h);
    __half* wg_h  = (__half*)symp(g_wg_h);
    __half* wc1_h = (__half*)symp(g_wc1_h);
    __half* wc2_h = (__half*)symp(g_wc2_h);
    __half* att_h = (__half*)symp(g_att_h);
    __half* to_h  = (__half*)symp(g_to_h);
    __half* xl_h  = (__half*)symp(g_xl_h);
    __half* xg_h  = (__half*)symp(g_xg_h);
    __half* xc_h  = (__half*)symp(g_xc_h);
    __half* hb_h  = (__half*)symp(g_hb_h);

    float* out = (float*)d_out;
    float* mout = (out_size >= ROWS * DIM + BATCH * NH * HD * HD)
                      ? out + (size_t)ROWS * DIM : nullptr;

    static cudaStream_t s2 = nullptr;
    static cudaEvent_t ev_fork = nullptr, ev_join = nullptr, ev_gate = nullptr, ev_cms = nullptr;
    if (!s2) {
        cudaFuncSetAttribute(gemm_tc, cudaFuncAttributeMaxDynamicSharedMemorySize, GEMM_SMEM);
        cudaFuncSetAttribute(gemm1, cudaFuncAttributeMaxDynamicSharedMemorySize, GEMM1_SMEM);
        cudaStreamCreateWithFlags(&s2, cudaStreamNonBlocking);
        cudaEventCreateWithFlags(&ev_fork, cudaEventDisableTiming);
        cudaEventCreateWithFlags(&ev_join, cudaEventDisableTiming);
        cudaEventCreateWithFlags(&ev_gate, cudaEventDisableTiming);
        cudaEventCreateWithFlags(&ev_cms, cudaEventDisableTiming);
    }

    // [0] single fused split of all f32 operands
    {
        SplitTab tab{};
        unsigned tot4 = 0;
        auto add = [&](int i, const float* s, __half* h, __half* l, size_t n) {
            tab.seg[i] = SplitSeg{ (const float4*)s, (uint2*)h, (uint2*)l, (unsigned)(n / 4) };
            tot4 += (unsigned)(n / 4);
        };
        add(0, x, x_h, x_l, (size_t)ROWS * DIM);
        add(1, t_wq, wtq_h, wtq_l, (size_t)DIM * DIM);
        add(2, t_wk, wtk_h, wtk_l, (size_t)DIM * DIM);
        add(3, t_wv, wtv_h, wtv_l, (size_t)DIM * DIM);
        add(4, t_wo, wto_h, nullptr, (size_t)DIM * DIM);
        add(5, in_proj_w, wi_h, wi_l, (size_t)3 * DIM * DIM);
        add(6, out_proj_w, wo_h, nullptr, (size_t)DIM * DIM);
        add(7, gate_w, wg_h, nullptr, (size_t)2 * DIM * DIM);
        add(8, cms_w1, wc1_h, nullptr, (size_t)16 * DIM * DIM);
        add(9, cms_w2, wc2_h, nullptr, (size_t)16 * DIM * DIM);
        split_all_kernel<<<(tot4 + 255) / 256, 256>>>(tab);
    }

    cudaEventRecord(ev_fork, 0);
    cudaStreamWaitEvent(s2, ev_fork, 0);

    B4 b{};

    // [s2] Titans projections (z-batched x3) — FULL 3-pass (feeds the scan)
    b = B4{};
    b.Ah[0] = x_h; b.Al[0] = x_l; b.Wh[0] = wtq_h; b.Wl[0] = wtq_l; b.C[0] = tq;
    b.Ah[1] = x_h; b.Al[1] = x_l; b.Wh[1] = wtk_h; b.Wl[1] = wtk_l; b.C[1] = tk;
    b.Ah[2] = x_h; b.Al[2] = x_l; b.Wh[2] = wtv_h; b.Wl[2] = wtv_l; b.C[2] = tv;
    gemm_tc<<<dim3(DIM / TBN, ROWS / TBM, 3), 256, GEMM_SMEM, s2>>>(b, DIM, DIM, DIM, DIM, 0, 3);

    // [s2] delta-rule scan (hi-only output + memory_state)
    delta_scan_kernel<<<BATCH * NH, 256, 0, s2>>>(tq, tk, tv, to_h, mout);

    // [s2] titans out proj (1-pass TBK=64) + residual LN -> x_global (+hi split)
    b = B4{};
    b.Ah[0] = to_h; b.Wh[0] = wto_h; b.C[0] = proj2;
    gemm1<<<dim3(DIM / TBN, ROWS / TBM, 1), 256, GEMM1_SMEM, s2>>>(b, DIM, DIM, DIM, DIM, 0);
    add_ln_kernel<<<ROWS, 256, 0, s2>>>(x, proj2, ln_tit_g, ln_tit_b, xglob, xg_h);
    cudaEventRecord(ev_join, s2);

    // [0] packed QKV projection (2-pass)
    b = B4{};
    b.Ah[0] = x_h; b.Al[0] = x_l; b.Wh[0] = wi_h;
    b.bias[0] = in_proj_b; b.C[0] = qkv;
    gemm_tc<<<dim3(3 * DIM / TBN, ROWS / TBM, 1), 256, GEMM_SMEM>>>(b, DIM, DIM, 3 * DIM, DIM, 0, 2);

    // [0] sliding-window attention -> att (hi only)
    attn_kernel<<<dim3(SEQ / 64, BATCH, NH), 64>>>(qkv, att_h);

    // [0] out_proj (1-pass TBK=64) + residual LN -> x_local (+hi split)
    b = B4{};
    b.Ah[0] = att_h; b.Wh[0] = wo_h;
    b.bias[0] = out_proj_b; b.C[0] = proj;
    gemm1<<<dim3(DIM / TBN, ROWS / TBM, 1), 256, GEMM1_SMEM>>>(b, DIM, DIM, DIM, DIM, 0);
    add_ln_kernel<<<ROWS, 256>>>(x, proj, ln_local_g, ln_local_b, xlocal, xl_h);

    // [0] gate pre-pass (1-pass): gpre = xlocal @ Wg1^T + gate_b (overlaps s2 scan)
    b = B4{};
    b.Ah[0] = xl_h; b.Wh[0] = wg_h;
    b.bias[0] = gate_b; b.C[0] = gpre;
    gemm1<<<dim3(DIM / TBN, ROWS / TBM, 1), 256, GEMM1_SMEM>>>(b, DIM, 2 * DIM, DIM, DIM, 0);

    // ---- join ----
    cudaStreamWaitEvent(0, ev_join, 0);

    // [0] gate finish (1-pass): logits = gpre + xglob @ Wg2^T -> sigmoid-combine
    b = B4{};
    b.Ah[0] = xg_h; b.Wh[0] = wg_h + DIM;
    b.C[0] = xc;
    b.xl = xlocal; b.xg = xglob; b.gpre = gpre; b.xch = xc_h;
    gemm1<<<dim3(DIM / TBN, ROWS / TBM, 1), 256, GEMM1_SMEM>>>(b, DIM, 2 * DIM, DIM, DIM, 4);
    cudaEventRecord(ev_gate, 0);
    cudaStreamWaitEvent(s2, ev_gate, 0);

    // [0/s2] CMS per level, pipelined across both streams (w1 -> w2 per level)
    for (int l = 0; l < 4; ++l) {
        cudaStream_t st = (l & 1) ? s2 : 0;
        b = B4{};
        b.Ah[0] = xc_h;
        b.Wh[0] = wc1_h + (size_t)l * 4 * DIM * DIM;
        b.bias[0] = cms_b1 + (size_t)l * 4 * DIM;
        b.Ch[0] = hb_h + (size_t)l * ROWS * 4 * DIM;
        gemm1<<<dim3(4 * DIM / TBN, ROWS / TBM, 1), 256, GEMM1_SMEM, st>>>(
            b, DIM, DIM, 4 * DIM, DIM, 1);

        b = B4{};
        b.Ah[0] = hb_h + (size_t)l * ROWS * 4 * DIM;
        b.Wh[0] = wc2_h + (size_t)l * 4 * DIM * DIM;
        b.bias[0] = cms_b2 + (size_t)l * DIM;
        b.C[0] = cmsb + (size_t)l * ROWS * DIM;
        gemm1<<<dim3(DIM / TBN, ROWS / TBM, 1), 256, GEMM1_SMEM, st>>>(
            b, 4 * DIM, 4 * DIM, DIM, 4 * DIM, 0);
    }
    cudaEventRecord(ev_cms, s2);
    cudaStreamWaitEvent(0, ev_cms, 0);

    // [0] final LN
    ln_final_kernel<<<ROWS, 256>>>(xc, cmsb, cmsb + (size_t)ROWS * DIM,
                                   cmsb + 2 * (size_t)ROWS * DIM, cmsb + 3 * (size_t)ROWS * DIM,
                                   ln_cms_g, ln_cms_b, out);
}